// round 3
// baseline (speedup 1.0000x reference)
#include <cuda_runtime.h>

#define Hh 4
#define Oo 32
#define Mm 128
#define M2 256
#define Dd 16
#define Bb 1024
#define HO 128
#define HOB (HO*Bb)
#define JIT 1e-4f
#define PACKN 32896   /* 256*257/2 */

// ---------------- device scratch ----------------
__device__ float g_sf2[Hh];
__device__ float g_invls[Hh][Dd];
__device__ float g_Xs[Hh][Bb][Dd];
__device__ float g_xn[Hh][Bb];
__device__ float g_Zs[HO][M2][Dd];
__device__ float g_zn[HO][M2];
__device__ float g_kuu2[HO][M2][M2];   // k(z_joint,z_joint), NO jitter
__device__ float g_W[HO][M2][M2];      // Linv (lower tri, upper zero)
__device__ float g_AtXT[HO][Mm][Mm];   // AtXT[k][j] = AtX[j][k]
__device__ float g_vm[HO][M2];         // Linv @ m_joint
__device__ float g_mj[HO][M2];
__device__ float g_kx[HO][M2][Bb];     // k(z_joint, x)
__device__ float g_a[HO][M2][Bb];      // Linv @ kx
__device__ float g_u[HO][M2][Bb];      // Kinv @ kx
__device__ float g_d1[HO][Bb];         // diag1 = ||a||^2 per column

// ---------------- prep ----------------
__global__ void k_prep_theta(const float* __restrict__ theta) {
    int t = threadIdx.x;
    if (t < Hh * (Dd + 1)) {
        int h = t / (Dd + 1), c = t % (Dd + 1);
        float v = theta[t];
        if (c == 0) g_sf2[h] = expf(v);
        else        g_invls[h][c - 1] = expf(-v);
    }
}

__global__ void k_prep_x(const float* __restrict__ x) {
    int g = blockIdx.x * blockDim.x + threadIdx.x;
    if (g >= Hh * Bb) return;
    int h = g / Bb, b = g % Bb;
    float s = 0.0f;
#pragma unroll
    for (int d = 0; d < Dd; d++) {
        float v = x[b * Dd + d] * g_invls[h][d];
        g_Xs[h][b][d] = v;
        s += v * v;
    }
    g_xn[h][b] = s;
}

__global__ void k_prep_z(const float* __restrict__ z, const float* __restrict__ z_old) {
    int p = blockIdx.x;
    int h = p / Oo, o = p % Oo;
    int i = threadIdx.x;  // 0..255
    const float* src = (i < Mm) ? &z_old[(o * Mm + i) * Dd] : &z[(o * Mm + (i - Mm)) * Dd];
    float s = 0.0f;
#pragma unroll
    for (int d = 0; d < Dd; d++) {
        float v = src[d] * g_invls[h][d];
        g_Zs[p][i][d] = v;
        s += v * v;
    }
    g_zn[p][i] = s;
}

// kuu2: grid (16, HO), block 256
__global__ void k_kuu2() {
    __shared__ float zn[M2];
    int p = blockIdx.y, rc = blockIdx.x, t = threadIdx.x;
    float myz[Dd];
#pragma unroll
    for (int d = 0; d < Dd; d++) myz[d] = g_Zs[p][t][d];
    zn[t] = g_zn[p][t];
    __syncthreads();
    float sf2 = g_sf2[p / Oo];
#pragma unroll 2
    for (int e = 0; e < 16; e++) {
        int row = rc * 16 + e;
        float dot = 0.0f;
#pragma unroll
        for (int d = 0; d < Dd; d++) dot += g_Zs[p][row][d] * myz[d];
        float d2 = fmaxf(zn[row] + zn[t] - 2.0f * dot, 0.0f);
        g_kuu2[p][row][t] = sf2 * __expf(-0.5f * d2);
    }
}

// kx = k(z_joint, x): grid (8, HO), block 256
__global__ void k_kx() {
    __shared__ float zs[M2][Dd + 1];
    __shared__ float zn[M2];
    int p = blockIdx.y, b0 = blockIdx.x * 128, t = threadIdx.x;
    int h = p / Oo;
    for (int e = t; e < M2 * Dd; e += 256) {
        int i = e >> 4, d = e & 15;
        zs[i][d] = g_Zs[p][i][d];
    }
    zn[t] = g_zn[p][t];
    __syncthreads();
    int bl = t & 127, half = t >> 7;
    float xr[Dd];
#pragma unroll
    for (int d = 0; d < Dd; d++) xr[d] = g_Xs[h][b0 + bl][d];
    float xnn = g_xn[h][b0 + bl];
    float sf2 = g_sf2[h];
    for (int ii = 0; ii < 128; ii++) {
        int i = half * 128 + ii;
        float dot = 0.0f;
#pragma unroll
        for (int d = 0; d < Dd; d++) dot += zs[i][d] * xr[d];
        float d2 = fmaxf(zn[i] + xnn - 2.0f * dot, 0.0f);
        g_kx[p][i][b0 + bl] = sf2 * __expf(-0.5f * d2);
    }
}

// ---------------- stage A: 128-chol + solves -> m_joint, AtXT ----------------
// dyn smem: Ls[128*129] X1[128*129] X2[128*129] dinv[128] yv[128] = 199168 B
__global__ void k_stageA(const float* __restrict__ m_old, const float* __restrict__ L_old,
                         const float* __restrict__ u_mean) {
    extern __shared__ float sm[];
    const int LD = 129;
    float* Ls   = sm;
    float* X1   = sm + 16512;
    float* X2   = sm + 33024;
    float* dinv = sm + 49536;
    float* yv   = sm + 49664;
    int p = blockIdx.x, o = p % Oo, t = threadIdx.x;

    for (int e = t; e < Mm * Mm; e += 256) {
        int i = e >> 7, j = e & 127;
        float v = g_kuu2[p][i][j];
        if (i == j) v += JIT;
        Ls[i * LD + j] = v;
    }
    __syncthreads();

    // Cholesky (128)
    for (int j = 0; j < Mm; j++) {
        if (t < 32) {
            float s = 0.0f;
            for (int k = t; k < j; k += 32) { float v = Ls[j * LD + k]; s += v * v; }
            for (int w = 16; w; w >>= 1) s += __shfl_down_sync(0xffffffffu, s, w);
            if (t == 0) {
                float d = sqrtf(Ls[j * LD + j] - s);
                Ls[j * LD + j] = d;
                dinv[j] = 1.0f / d;
            }
        }
        __syncthreads();
        int i = j + 1 + t;
        if (i < Mm) {
            float s0 = 0, s1 = 0, s2 = 0, s3 = 0;
            int k = 0;
            for (; k + 3 < j; k += 4) {
                s0 += Ls[i * LD + k]     * Ls[j * LD + k];
                s1 += Ls[i * LD + k + 1] * Ls[j * LD + k + 1];
                s2 += Ls[i * LD + k + 2] * Ls[j * LD + k + 2];
                s3 += Ls[i * LD + k + 3] * Ls[j * LD + k + 3];
            }
            for (; k < j; k++) s0 += Ls[i * LD + k] * Ls[j * LD + k];
            Ls[i * LD + j] = (Ls[i * LD + j] - ((s0 + s1) + (s2 + s3))) * dinv[j];
        }
        __syncthreads();
    }

    // yv = Linv * m_old
    {
        float acc = 0.0f;
        for (int i = 0; i < Mm; i++) {
            if (t == i) yv[i] = (m_old[o * Mm + i] - acc) * dinv[i];
            __syncthreads();
            if (t > i && t < Mm) acc += Ls[t * LD + i] * yv[i];
        }
    }
    __syncthreads();

    // X1 = Linv*kuf (t<128), X2 = Linv*L_old (t>=128)
    {
        int c = t & 127;
        bool isX1 = (t < 128);
        float* X = isX1 ? X1 : X2;
        for (int i = 0; i < Mm; i++) {
            float r = isX1 ? g_kuu2[p][i][Mm + c] : L_old[(o * Mm + i) * Mm + c];
            float s0 = 0, s1 = 0, s2 = 0, s3 = 0;
            int k = 0;
            for (; k + 3 < i; k += 4) {
                s0 += Ls[i * LD + k]     * X[(k) * LD + c];
                s1 += Ls[i * LD + k + 1] * X[(k + 1) * LD + c];
                s2 += Ls[i * LD + k + 2] * X[(k + 2) * LD + c];
                s3 += Ls[i * LD + k + 3] * X[(k + 3) * LD + c];
            }
            for (; k < i; k++) s0 += Ls[i * LD + k] * X[k * LD + c];
            X[i * LD + c] = (r - ((s0 + s1) + (s2 + s3))) * dinv[i];
        }
    }
    __syncthreads();

    // m_joint
    if (t < Mm) {
        float s = 0.0f;
        for (int i = 0; i < Mm; i++) s += X1[i * LD + t] * yv[i];
        g_mj[p][t] = m_old[o * Mm + t];
        g_mj[p][Mm + t] = s + u_mean[o * Mm + t];
    }
    __syncthreads();

    // AtXT[k][j] = AtX[j][k] = sum_i X2[i][j]*X1[i][k]
    for (int e = t; e < Mm * Mm; e += 256) {
        int kq = e >> 7, jq = e & 127;
        float s0 = 0, s1 = 0;
        for (int i = 0; i < Mm; i += 2) {
            s0 += X2[i * LD + jq] * X1[i * LD + kq];
            s1 += X2[(i + 1) * LD + jq] * X1[(i + 1) * LD + kq];
        }
        g_AtXT[p][kq][jq] = s0 + s1;
    }
}

// ---------------- stage B1: packed 256-chol + trtri -> W, vm ----------------
// dyn smem: Lp[32896] dinv[256] = 132608 B
__global__ void k_stageB1() {
    extern __shared__ float sm[];
    float* Lp   = sm;
    float* dinv = sm + PACKN;
    int p = blockIdx.x, t = threadIdx.x;

    for (int e = t; e < PACKN; e += 256) {
        int r = (int)((sqrtf(8.0f * (float)e + 1.0f) - 1.0f) * 0.5f);
        while ((r + 1) * (r + 2) / 2 <= e) r++;
        while (r * (r + 1) / 2 > e) r--;
        int c = e - r * (r + 1) / 2;
        float v = g_kuu2[p][r][c];
        if (r == c) v += JIT;
        Lp[e] = v;
    }
    __syncthreads();

    // packed Cholesky (256)
    for (int j = 0; j < M2; j++) {
        int oj = j * (j + 1) / 2;
        if (t < 32) {
            float s = 0.0f;
            for (int k = t; k < j; k += 32) { float v = Lp[oj + k]; s += v * v; }
            for (int w = 16; w; w >>= 1) s += __shfl_down_sync(0xffffffffu, s, w);
            if (t == 0) {
                float d = sqrtf(Lp[oj + j] - s);
                Lp[oj + j] = d;
                dinv[j] = 1.0f / d;
            }
        }
        __syncthreads();
        int i = j + 1 + t;
        if (i < M2) {
            int oi = i * (i + 1) / 2;
            float s0 = 0, s1 = 0, s2 = 0, s3 = 0;
            int k = 0;
            for (; k + 3 < j; k += 4) {
                s0 += Lp[oi + k]     * Lp[oj + k];
                s1 += Lp[oi + k + 1] * Lp[oj + k + 1];
                s2 += Lp[oi + k + 2] * Lp[oj + k + 2];
                s3 += Lp[oi + k + 3] * Lp[oj + k + 3];
            }
            for (; k < j; k++) s0 += Lp[oi + k] * Lp[oj + k];
            Lp[oi + j] = (Lp[oi + j] - ((s0 + s1) + (s2 + s3))) * dinv[j];
        }
        __syncthreads();
    }

    // in-place trtri
    if (t == 0) Lp[0] = dinv[0];
    __syncthreads();
    for (int i = 1; i < M2; i++) {
        int oi = i * (i + 1) / 2;
        float v = 0.0f;
        bool act = (t < i);
        if (act) {
            float s = 0.0f;
            int ok = t * (t + 1) / 2;
            for (int k = t; k < i; k++) { s += Lp[oi + k] * Lp[ok + t]; ok += k + 1; }
            v = -dinv[i] * s;
        }
        __syncthreads();
        if (act) Lp[oi + t] = v;
        if (t == 0) Lp[oi + i] = dinv[i];
        __syncthreads();
    }

    // vm = Linv @ m_joint
    {
        int ot = t * (t + 1) / 2;
        float s = 0.0f;
        for (int k = 0; k <= t; k++) s += Lp[ot + k] * g_mj[p][k];
        g_vm[p][t] = s;
    }

    // W dense (upper zeros)
    for (int e = t; e < M2 * M2; e += 256) {
        int r = e >> 8, c = e & 255;
        g_W[p][r][c] = (c <= r) ? Lp[r * (r + 1) / 2 + c] : 0.0f;
    }
}

// ---------------- GEMM1: a = W @ kx (lower-tri) ----------------
// grid (16, 4, HO), block 256, 64x64 tile, 4x4 microtile
__global__ void k_gemm1() {
    __shared__ float Ast[16][64];
    __shared__ float Bs[16][64];
    int p = blockIdx.z;
    int i0 = blockIdx.y * 64, b0 = blockIdx.x * 64;
    int t = threadIdx.x, tx = t % 16, ty = t / 16;
    int kmax = i0 + 64;
    float acc[4][4];
#pragma unroll
    for (int m = 0; m < 4; m++)
#pragma unroll
        for (int n = 0; n < 4; n++) acc[m][n] = 0.0f;

    for (int kc = 0; kc < kmax; kc += 16) {
        for (int idx = t; idx < 1024; idx += 256) {
            int kk = idx & 15, i = idx >> 4;
            Ast[kk][i] = g_W[p][i0 + i][kc + kk];
        }
        for (int idx = t; idx < 1024; idx += 256) {
            int b = idx & 63, kk = idx >> 6;
            Bs[kk][b] = g_kx[p][kc + kk][b0 + b];
        }
        __syncthreads();
#pragma unroll
        for (int kk = 0; kk < 16; kk++) {
            float4 a4 = *(const float4*)&Ast[kk][ty * 4];
            float4 b4 = *(const float4*)&Bs[kk][tx * 4];
            float av[4] = {a4.x, a4.y, a4.z, a4.w};
            float bv[4] = {b4.x, b4.y, b4.z, b4.w};
#pragma unroll
            for (int m = 0; m < 4; m++)
#pragma unroll
                for (int n = 0; n < 4; n++) acc[m][n] += av[m] * bv[n];
        }
        __syncthreads();
    }
#pragma unroll
    for (int m = 0; m < 4; m++) {
        float4 v = make_float4(acc[m][0], acc[m][1], acc[m][2], acc[m][3]);
        *(float4*)&g_a[p][i0 + ty * 4 + m][b0 + tx * 4] = v;
    }
}

// ---------------- GEMM2: u = W^T @ a (upper-tri) + epilogue diag1/mu ----------------
__global__ void k_gemm2(float* __restrict__ out) {
    __shared__ float Ast[16][64];
    __shared__ float Bs[16][64];
    __shared__ float vs[M2];
    __shared__ float red1[16][64];
    __shared__ float red2[16][64];
    int p = blockIdx.z;
    int i0 = blockIdx.y * 64, b0 = blockIdx.x * 64;
    int t = threadIdx.x, tx = t % 16, ty = t / 16;
    bool epi = (blockIdx.y == 0);
    if (epi) vs[t] = g_vm[p][t];
    float acc[4][4];
#pragma unroll
    for (int m = 0; m < 4; m++)
#pragma unroll
        for (int n = 0; n < 4; n++) acc[m][n] = 0.0f;
    float d1[4] = {0, 0, 0, 0}, mp[4] = {0, 0, 0, 0};
    __syncthreads();

    for (int kc = i0; kc < M2; kc += 16) {
        for (int idx = t; idx < 1024; idx += 256) {
            int i = idx & 63, kk = idx >> 6;
            Ast[kk][i] = g_W[p][kc + kk][i0 + i];   // W^T[i][k] = W[k][i]
        }
        for (int idx = t; idx < 1024; idx += 256) {
            int b = idx & 63, kk = idx >> 6;
            Bs[kk][b] = g_a[p][kc + kk][b0 + b];
        }
        __syncthreads();
#pragma unroll
        for (int kk = 0; kk < 16; kk++) {
            float4 a4 = *(const float4*)&Ast[kk][ty * 4];
            float4 b4 = *(const float4*)&Bs[kk][tx * 4];
            float av[4] = {a4.x, a4.y, a4.z, a4.w};
            float bv[4] = {b4.x, b4.y, b4.z, b4.w};
#pragma unroll
            for (int m = 0; m < 4; m++)
#pragma unroll
                for (int n = 0; n < 4; n++) acc[m][n] += av[m] * bv[n];
        }
        if (epi) {
            float vv = vs[kc + ty];
#pragma unroll
            for (int n = 0; n < 4; n++) {
                float bv = Bs[ty][tx * 4 + n];
                d1[n] += bv * bv;
                mp[n] += vv * bv;
            }
        }
        __syncthreads();
    }
#pragma unroll
    for (int m = 0; m < 4; m++) {
        float4 v = make_float4(acc[m][0], acc[m][1], acc[m][2], acc[m][3]);
        *(float4*)&g_u[p][i0 + ty * 4 + m][b0 + tx * 4] = v;
    }
    if (epi) {
#pragma unroll
        for (int n = 0; n < 4; n++) { red1[ty][tx * 4 + n] = d1[n]; red2[ty][tx * 4 + n] = mp[n]; }
        __syncthreads();
        if (t < 64) {
            float s1 = 0, s2 = 0;
#pragma unroll
            for (int y = 0; y < 16; y++) { s1 += red1[y][t]; s2 += red2[y][t]; }
            g_d1[p][b0 + t] = s1;
            out[p * Bb + b0 + t] = s2;
        }
    }
}

// ---------------- stage D: diag2 + var ----------------
// grid (16, HO), block 256; tx = b (64), ty = j-group (4 x 32 rows)
__global__ void k_stageD(const float* __restrict__ L_old, const float* __restrict__ u_tril_vec,
                         float* __restrict__ out) {
    __shared__ float Ms[16][128];
    __shared__ float Us[16][128];
    __shared__ float Uu[16][64];
    __shared__ float sred[4][64];
    int p = blockIdx.y, o = p % Oo, b0 = blockIdx.x * 64;
    int t = threadIdx.x, tx = t & 63, ty = t >> 6;
    int jb = ty * 32;
    float qa[32], ra[32];
#pragma unroll
    for (int j = 0; j < 32; j++) { qa[j] = 0.0f; ra[j] = 0.0f; }
    float u2s = 0.0f;

    for (int kc = 0; kc < M2; kc += 16) {
        for (int idx = t; idx < 1024; idx += 256) {
            int b = idx & 63, kk = idx >> 6;
            Uu[kk][b] = g_u[p][kc + kk][b0 + b];
        }
        for (int idx = t; idx < 2048; idx += 256) {
            int j = idx & 127, kk = idx >> 7;
            int i = kc + kk;
            Ms[kk][j] = (i < Mm) ? L_old[(o * Mm + i) * Mm + j] : g_AtXT[p][i - Mm][j];
        }
        if (kc >= Mm) {
            for (int idx = t; idx < 2048; idx += 256) {
                int j = idx & 127, kk = idx >> 7;
                int i2 = kc + kk - Mm;
                Us[kk][j] = (j <= i2) ? u_tril_vec[o * (Mm * (Mm + 1) / 2) + i2 * (i2 + 1) / 2 + j] : 0.0f;
            }
        }
        __syncthreads();
#pragma unroll
        for (int g = 0; g < 4; g++) {
            float v = Uu[ty + 4 * g][tx];
            u2s += v * v;
        }
        if (kc < Mm) {
#pragma unroll
            for (int kk = 0; kk < 16; kk++) {
                float uv = Uu[kk][tx];
#pragma unroll
                for (int j = 0; j < 32; j++) qa[j] += Ms[kk][jb + j] * uv;
            }
        } else {
#pragma unroll
            for (int kk = 0; kk < 16; kk++) {
                float uv = Uu[kk][tx];
#pragma unroll
                for (int j = 0; j < 32; j++) {
                    qa[j] += Ms[kk][jb + j] * uv;
                    ra[j] += Us[kk][jb + j] * uv;
                }
            }
        }
        __syncthreads();
    }

    float dloc = JIT * u2s;
#pragma unroll
    for (int j = 0; j < 32; j++) dloc += qa[j] * qa[j] + ra[j] * ra[j];
    sred[ty][tx] = dloc;
    __syncthreads();
    if (t < 64) {
        float diag2 = sred[0][t] + sred[1][t] + sred[2][t] + sred[3][t];
        float var = g_sf2[p / Oo] - g_d1[p][b0 + t] + diag2;
        out[HOB + p * Bb + b0 + t] = var;
    }
}

extern "C" void kernel_launch(void* const* d_in, const int* in_sizes, int n_in,
                              void* d_out, int out_size) {
    const float* x          = (const float*)d_in[0];
    const float* z          = (const float*)d_in[1];
    const float* u_mean     = (const float*)d_in[2];
    const float* u_tril_vec = (const float*)d_in[3];
    const float* m_old      = (const float*)d_in[4];
    const float* L_old      = (const float*)d_in[5];
    const float* z_old      = (const float*)d_in[6];
    const float* theta      = (const float*)d_in[7];
    float* out = (float*)d_out;

    static bool attrs_set = false;
    if (!attrs_set) {
        cudaFuncSetAttribute(k_stageA, cudaFuncAttributeMaxDynamicSharedMemorySize, 199168);
        cudaFuncSetAttribute(k_stageB1, cudaFuncAttributeMaxDynamicSharedMemorySize, 132608);
        attrs_set = true;
    }

    k_prep_theta<<<1, 128>>>(theta);
    k_prep_x<<<16, 256>>>(x);
    k_prep_z<<<HO, 256>>>(z, z_old);
    k_kuu2<<<dim3(16, HO), 256>>>();
    k_kx<<<dim3(8, HO), 256>>>();
    k_stageA<<<HO, 256, 199168>>>(m_old, L_old, u_mean);
    k_stageB1<<<HO, 256, 132608>>>();
    k_gemm1<<<dim3(16, 4, HO), 256>>>();
    k_gemm2<<<dim3(16, 4, HO), 256>>>(out);
    k_stageD<<<dim3(16, HO), 256>>>(L_old, u_tril_vec, out);
}

// round 4
// speedup vs baseline: 1.2656x; 1.2656x over previous
#include <cuda_runtime.h>

#define Hh 4
#define Oo 32
#define Mm 128
#define M2 256
#define Dd 16
#define Bb 1024
#define HO 128
#define HOB (HO*Bb)
#define JIT 1e-4f
#define PACKN 32896   /* 256*257/2 */

// ---------------- device scratch ----------------
__device__ float g_sf2[Hh];
__device__ float g_invls[Hh][Dd];
__device__ float g_Xs[Hh][Bb][Dd];
__device__ float g_xn[Hh][Bb];
__device__ float g_Zs[HO][M2][Dd];
__device__ float g_zn[HO][M2];
__device__ float g_kuu2[HO][M2][M2];   // k(z_joint,z_joint), NO jitter
__device__ float g_cov[HO][M2][M2];    // cov_joint, NO jitter
__device__ float g_Wt[HO][M2][M2];     // Wt[k][i] = Linv[i][k]  (zero where i<k)
__device__ float g_Lj[HO][M2][M2];     // L_joint = chol(cov+jit I), zeros upper
__device__ float g_R[HO][M2][M2];      // R = Linv @ L_joint (lower tri)
__device__ float g_vm[HO][M2];         // Linv @ m_joint
__device__ float g_mj[HO][M2];
__device__ float g_kx[HO][M2][Bb];     // k(z_joint, x)
__device__ float g_a[HO][M2][Bb];      // Linv @ kx
__device__ float g_d1p[4][HO][Bb];
__device__ float g_d2p[4][HO][Bb];
__device__ float g_mup[4][HO][Bb];

// ---------------- prep ----------------
__global__ void k_prep_theta(const float* __restrict__ theta) {
    int t = threadIdx.x;
    if (t < Hh * (Dd + 1)) {
        int h = t / (Dd + 1), c = t % (Dd + 1);
        float v = theta[t];
        if (c == 0) g_sf2[h] = expf(v);
        else        g_invls[h][c - 1] = expf(-v);
    }
}

__global__ void k_prep_x(const float* __restrict__ x) {
    int g = blockIdx.x * blockDim.x + threadIdx.x;
    if (g >= Hh * Bb) return;
    int h = g / Bb, b = g % Bb;
    float s = 0.0f;
#pragma unroll
    for (int d = 0; d < Dd; d++) {
        float v = x[b * Dd + d] * g_invls[h][d];
        g_Xs[h][b][d] = v;
        s += v * v;
    }
    g_xn[h][b] = s;
}

__global__ void k_prep_z(const float* __restrict__ z, const float* __restrict__ z_old) {
    int p = blockIdx.x;
    int h = p / Oo, o = p % Oo;
    int i = threadIdx.x;  // 0..255
    const float* src = (i < Mm) ? &z_old[(o * Mm + i) * Dd] : &z[(o * Mm + (i - Mm)) * Dd];
    float s = 0.0f;
#pragma unroll
    for (int d = 0; d < Dd; d++) {
        float v = src[d] * g_invls[h][d];
        g_Zs[p][i][d] = v;
        s += v * v;
    }
    g_zn[p][i] = s;
}

// kuu2: grid (16, HO), block 256
__global__ void k_kuu2() {
    __shared__ float zn[M2];
    int p = blockIdx.y, rc = blockIdx.x, t = threadIdx.x;
    float myz[Dd];
#pragma unroll
    for (int d = 0; d < Dd; d++) myz[d] = g_Zs[p][t][d];
    zn[t] = g_zn[p][t];
    __syncthreads();
    float sf2 = g_sf2[p / Oo];
#pragma unroll 2
    for (int e = 0; e < 16; e++) {
        int row = rc * 16 + e;
        float dot = 0.0f;
#pragma unroll
        for (int d = 0; d < Dd; d++) dot += g_Zs[p][row][d] * myz[d];
        float d2 = fmaxf(zn[row] + zn[t] - 2.0f * dot, 0.0f);
        g_kuu2[p][row][t] = sf2 * __expf(-0.5f * d2);
    }
}

// kx = k(z_joint, x): grid (8, HO), block 256
__global__ void k_kx() {
    __shared__ float zs[M2][Dd + 1];
    __shared__ float zn[M2];
    int p = blockIdx.y, b0 = blockIdx.x * 128, t = threadIdx.x;
    int h = p / Oo;
    for (int e = t; e < M2 * Dd; e += 256) {
        int i = e >> 4, d = e & 15;
        zs[i][d] = g_Zs[p][i][d];
    }
    zn[t] = g_zn[p][t];
    __syncthreads();
    int bl = t & 127, half = t >> 7;
    float xr[Dd];
#pragma unroll
    for (int d = 0; d < Dd; d++) xr[d] = g_Xs[h][b0 + bl][d];
    float xnn = g_xn[h][b0 + bl];
    float sf2 = g_sf2[h];
    for (int ii = 0; ii < 128; ii++) {
        int i = half * 128 + ii;
        float dot = 0.0f;
#pragma unroll
        for (int d = 0; d < Dd; d++) dot += zs[i][d] * xr[d];
        float d2 = fmaxf(zn[i] + xnn - 2.0f * dot, 0.0f);
        g_kx[p][i][b0 + bl] = sf2 * __expf(-0.5f * d2);
    }
}

// ---------------- stage A: 128-chol + solves -> m_joint, cov_joint ----------------
// dyn smem: Ls[128*129] X1[128*129] X2[128*129] dinv[128] yv[128] = 199168 B
__global__ void k_stageA(const float* __restrict__ m_old, const float* __restrict__ L_old,
                         const float* __restrict__ u_mean, const float* __restrict__ u_tril_vec) {
    extern __shared__ float sm[];
    const int LD = 129;
    float* Ls   = sm;
    float* X1   = sm + 16512;
    float* X2   = sm + 33024;
    float* dinv = sm + 49536;
    float* yv   = sm + 49664;
    int p = blockIdx.x, o = p % Oo, t = threadIdx.x;

    for (int e = t; e < Mm * Mm; e += 256) {
        int i = e >> 7, j = e & 127;
        float v = g_kuu2[p][i][j];
        if (i == j) v += JIT;
        Ls[i * LD + j] = v;
    }
    __syncthreads();

    // Cholesky (128)
    for (int j = 0; j < Mm; j++) {
        if (t < 32) {
            float s = 0.0f;
            for (int k = t; k < j; k += 32) { float v = Ls[j * LD + k]; s += v * v; }
            for (int w = 16; w; w >>= 1) s += __shfl_down_sync(0xffffffffu, s, w);
            if (t == 0) {
                float d = sqrtf(Ls[j * LD + j] - s);
                Ls[j * LD + j] = d;
                dinv[j] = 1.0f / d;
            }
        }
        __syncthreads();
        int i = j + 1 + t;
        if (i < Mm) {
            float s0 = 0, s1 = 0, s2 = 0, s3 = 0;
            int k = 0;
            for (; k + 3 < j; k += 4) {
                s0 += Ls[i * LD + k]     * Ls[j * LD + k];
                s1 += Ls[i * LD + k + 1] * Ls[j * LD + k + 1];
                s2 += Ls[i * LD + k + 2] * Ls[j * LD + k + 2];
                s3 += Ls[i * LD + k + 3] * Ls[j * LD + k + 3];
            }
            for (; k < j; k++) s0 += Ls[i * LD + k] * Ls[j * LD + k];
            Ls[i * LD + j] = (Ls[i * LD + j] - ((s0 + s1) + (s2 + s3))) * dinv[j];
        }
        __syncthreads();
    }

    // yv = Linv * m_old
    {
        float acc = 0.0f;
        for (int i = 0; i < Mm; i++) {
            if (t == i) yv[i] = (m_old[o * Mm + i] - acc) * dinv[i];
            __syncthreads();
            if (t > i && t < Mm) acc += Ls[t * LD + i] * yv[i];
        }
    }
    __syncthreads();

    // X1 = Linv*kuf (t<128), X2 = Linv*L_old (t>=128)
    {
        int c = t & 127;
        bool isX1 = (t < 128);
        float* X = isX1 ? X1 : X2;
        for (int i = 0; i < Mm; i++) {
            float r = isX1 ? g_kuu2[p][i][Mm + c] : L_old[(o * Mm + i) * Mm + c];
            float s0 = 0, s1 = 0, s2 = 0, s3 = 0;
            int k = 0;
            for (; k + 3 < i; k += 4) {
                s0 += Ls[i * LD + k]     * X[(k) * LD + c];
                s1 += Ls[i * LD + k + 1] * X[(k + 1) * LD + c];
                s2 += Ls[i * LD + k + 2] * X[(k + 2) * LD + c];
                s3 += Ls[i * LD + k + 3] * X[(k + 3) * LD + c];
            }
            for (; k < i; k++) s0 += Ls[i * LD + k] * X[k * LD + c];
            X[i * LD + c] = (r - ((s0 + s1) + (s2 + s3))) * dinv[i];
        }
    }
    __syncthreads();

    // m_joint
    if (t < Mm) {
        float s = 0.0f;
        for (int i = 0; i < Mm; i++) s += X1[i * LD + t] * yv[i];
        g_mj[p][t] = m_old[o * Mm + t];
        g_mj[p][Mm + t] = s + u_mean[o * Mm + t];
    }
    __syncthreads();

    // AtX = X2^T X1 -> overwrite Ls  (AtX[j][k])
    for (int e = t; e < Mm * Mm; e += 256) {
        int j = e >> 7, k = e & 127;
        float s0 = 0, s1 = 0;
        for (int i = 0; i < Mm; i += 2) {
            s0 += X2[i * LD + j] * X1[i * LD + k];
            s1 += X2[(i + 1) * LD + j] * X1[(i + 1) * LD + k];
        }
        Ls[j * LD + k] = s0 + s1;
    }
    __syncthreads();

    // reload: X1 <- L_old, X2 <- dense(u_tril)
    for (int e = t; e < Mm * Mm; e += 256) {
        int i = e >> 7, j = e & 127;
        X1[i * LD + j] = L_old[(o * Mm + i) * Mm + j];
        X2[i * LD + j] = (j <= i) ? u_tril_vec[o * 8256 + (i * (i + 1)) / 2 + j] : 0.0f;
    }
    __syncthreads();

    // cov_joint (NO jitter): TL = L_old L_old^T, TR = L_old@AtX, BR = AtX^T AtX + U U^T
    for (int e = t; e < Mm * Mm; e += 256) {
        int i = e >> 7, j = e & 127;
        float s = 0.0f;
        int kk = min(i, j);
        for (int k = 0; k <= kk; k++) s += X1[i * LD + k] * X1[j * LD + k];
        g_cov[p][i][j] = s;
    }
    for (int e = t; e < Mm * Mm; e += 256) {
        int i = e >> 7, j = e & 127;
        float s = 0.0f;
        for (int k = 0; k <= i; k++) s += X1[i * LD + k] * Ls[k * LD + j];
        g_cov[p][i][Mm + j] = s;
        g_cov[p][Mm + j][i] = s;
    }
    for (int e = t; e < Mm * Mm; e += 256) {
        int i = e >> 7, j = e & 127;
        float s = 0.0f;
        int kk = min(i, j);
        for (int k = 0; k <= kk; k++) s += X2[i * LD + k] * X2[j * LD + k];
        for (int k = 0; k < Mm; k++) s += Ls[k * LD + i] * Ls[k * LD + j];
        g_cov[p][Mm + i][Mm + j] = s;
    }
}

// ---------------- stage B1: packed 256-chol(kuu2) + trtri -> Wt, vm ----------------
// dyn smem: Lp[32896] dinv[256] = 132608 B
__global__ void k_stageB1() {
    extern __shared__ float sm[];
    float* Lp   = sm;
    float* dinv = sm + PACKN;
    int p = blockIdx.x, t = threadIdx.x;

    for (int e = t; e < PACKN; e += 256) {
        int r = (int)((sqrtf(8.0f * (float)e + 1.0f) - 1.0f) * 0.5f);
        while ((r + 1) * (r + 2) / 2 <= e) r++;
        while (r * (r + 1) / 2 > e) r--;
        int c = e - r * (r + 1) / 2;
        float v = g_kuu2[p][r][c];
        if (r == c) v += JIT;
        Lp[e] = v;
    }
    __syncthreads();

    // packed Cholesky (256)
    for (int j = 0; j < M2; j++) {
        int oj = j * (j + 1) / 2;
        if (t < 32) {
            float s = 0.0f;
            for (int k = t; k < j; k += 32) { float v = Lp[oj + k]; s += v * v; }
            for (int w = 16; w; w >>= 1) s += __shfl_down_sync(0xffffffffu, s, w);
            if (t == 0) {
                float d = sqrtf(Lp[oj + j] - s);
                Lp[oj + j] = d;
                dinv[j] = 1.0f / d;
            }
        }
        __syncthreads();
        int i = j + 1 + t;
        if (i < M2) {
            int oi = i * (i + 1) / 2;
            float s0 = 0, s1 = 0, s2 = 0, s3 = 0;
            int k = 0;
            for (; k + 3 < j; k += 4) {
                s0 += Lp[oi + k]     * Lp[oj + k];
                s1 += Lp[oi + k + 1] * Lp[oj + k + 1];
                s2 += Lp[oi + k + 2] * Lp[oj + k + 2];
                s3 += Lp[oi + k + 3] * Lp[oj + k + 3];
            }
            for (; k < j; k++) s0 += Lp[oi + k] * Lp[oj + k];
            Lp[oi + j] = (Lp[oi + j] - ((s0 + s1) + (s2 + s3))) * dinv[j];
        }
        __syncthreads();
    }

    // in-place trtri (4-way unrolled chains)
    if (t == 0) Lp[0] = dinv[0];
    __syncthreads();
    for (int i = 1; i < M2; i++) {
        int oi = i * (i + 1) / 2;
        float v = 0.0f;
        if (t < i) {
            float s0 = 0, s1 = 0, s2 = 0, s3 = 0;
            int k = t, ok = t * (t + 1) / 2;
            for (; k + 3 < i; ) {
                int ok1 = ok + k + 1, ok2 = ok1 + k + 2, ok3 = ok2 + k + 3;
                s0 += Lp[oi + k]     * Lp[ok + t];
                s1 += Lp[oi + k + 1] * Lp[ok1 + t];
                s2 += Lp[oi + k + 2] * Lp[ok2 + t];
                s3 += Lp[oi + k + 3] * Lp[ok3 + t];
                ok = ok3 + k + 4; k += 4;
            }
            for (; k < i; k++) { s0 += Lp[oi + k] * Lp[ok + t]; ok += k + 1; }
            v = -dinv[i] * ((s0 + s1) + (s2 + s3));
        }
        __syncthreads();
        if (t < i) Lp[oi + t] = v;
        if (t == 0) Lp[oi + i] = dinv[i];
        __syncthreads();
    }

    // vm = Linv @ m_joint
    {
        int ot = t * (t + 1) / 2;
        float s = 0.0f;
        for (int k = 0; k <= t; k++) s += Lp[ot + k] * g_mj[p][k];
        g_vm[p][t] = s;
    }

    // Wt[k][i] = Linv[i][k] (zeros where i<k)
    for (int e = t; e < M2 * M2; e += 256) {
        int k = e >> 8, i = e & 255;
        g_Wt[p][k][i] = (i >= k) ? Lp[i * (i + 1) / 2 + k] : 0.0f;
    }
}

// ---------------- stage B2: packed 256-chol(cov+jit) -> L_joint dense ----------------
__global__ void k_stageB2() {
    extern __shared__ float sm[];
    float* Lp   = sm;
    float* dinv = sm + PACKN;
    int p = blockIdx.x, t = threadIdx.x;

    for (int e = t; e < PACKN; e += 256) {
        int r = (int)((sqrtf(8.0f * (float)e + 1.0f) - 1.0f) * 0.5f);
        while ((r + 1) * (r + 2) / 2 <= e) r++;
        while (r * (r + 1) / 2 > e) r--;
        int c = e - r * (r + 1) / 2;
        float v = g_cov[p][r][c];
        if (r == c) v += JIT;
        Lp[e] = v;
    }
    __syncthreads();

    for (int j = 0; j < M2; j++) {
        int oj = j * (j + 1) / 2;
        if (t < 32) {
            float s = 0.0f;
            for (int k = t; k < j; k += 32) { float v = Lp[oj + k]; s += v * v; }
            for (int w = 16; w; w >>= 1) s += __shfl_down_sync(0xffffffffu, s, w);
            if (t == 0) {
                float d = sqrtf(Lp[oj + j] - s);
                Lp[oj + j] = d;
                dinv[j] = 1.0f / d;
            }
        }
        __syncthreads();
        int i = j + 1 + t;
        if (i < M2) {
            int oi = i * (i + 1) / 2;
            float s0 = 0, s1 = 0, s2 = 0, s3 = 0;
            int k = 0;
            for (; k + 3 < j; k += 4) {
                s0 += Lp[oi + k]     * Lp[oj + k];
                s1 += Lp[oi + k + 1] * Lp[oj + k + 1];
                s2 += Lp[oi + k + 2] * Lp[oj + k + 2];
                s3 += Lp[oi + k + 3] * Lp[oj + k + 3];
            }
            for (; k < j; k++) s0 += Lp[oi + k] * Lp[oj + k];
            Lp[oi + j] = (Lp[oi + j] - ((s0 + s1) + (s2 + s3))) * dinv[j];
        }
        __syncthreads();
    }

    // L_joint dense (zeros upper)
    for (int e = t; e < M2 * M2; e += 256) {
        int r = e >> 8, c = e & 255;
        g_Lj[p][r][c] = (c <= r) ? Lp[r * (r + 1) / 2 + c] : 0.0f;
    }
}

// ---------------- gemmR: R = Linv @ L_joint  (grid (2,4,HO), 256 thr) ----------------
__global__ __launch_bounds__(256) void k_gemmR() {
    __shared__ float As[16][64];
    __shared__ float Bs[16][128];
    int p = blockIdx.z;
    int i0 = blockIdx.y * 64, j0 = blockIdx.x * 128;
    int t = threadIdx.x, tx = t % 16, ty = t / 16;
    float acc[4][8];
#pragma unroll
    for (int m = 0; m < 4; m++)
#pragma unroll
        for (int n = 0; n < 8; n++) acc[m][n] = 0.0f;

    int kmin = j0, kmax = i0 + 64;
    for (int kc = kmin; kc < kmax; kc += 16) {
        {   // A: As[kk][i] = Wt[kc+kk][i0+i]
            int kk = t >> 4, i4 = t & 15;
            *(float4*)&As[kk][i4 * 4] = *(const float4*)&g_Wt[p][kc + kk][i0 + i4 * 4];
        }
        {   // B: Bs[kk][j] = Lj[kc+kk][j0+j]
#pragma unroll
            for (int e = 0; e < 2; e++) {
                int q = t + e * 256;
                int kk = q >> 5, b4 = q & 31;
                *(float4*)&Bs[kk][b4 * 4] = *(const float4*)&g_Lj[p][kc + kk][j0 + b4 * 4];
            }
        }
        __syncthreads();
#pragma unroll
        for (int kk = 0; kk < 16; kk++) {
            float av[4], bv[8];
#pragma unroll
            for (int m = 0; m < 4; m++) av[m] = As[kk][ty * 4 + m];
            float4 b0v = *(const float4*)&Bs[kk][tx * 8];
            float4 b1v = *(const float4*)&Bs[kk][tx * 8 + 4];
            bv[0] = b0v.x; bv[1] = b0v.y; bv[2] = b0v.z; bv[3] = b0v.w;
            bv[4] = b1v.x; bv[5] = b1v.y; bv[6] = b1v.z; bv[7] = b1v.w;
#pragma unroll
            for (int m = 0; m < 4; m++)
#pragma unroll
                for (int n = 0; n < 8; n++) acc[m][n] += av[m] * bv[n];
        }
        __syncthreads();
    }
#pragma unroll
    for (int m = 0; m < 4; m++) {
        *(float4*)&g_R[p][i0 + ty * 4 + m][j0 + tx * 8]     = make_float4(acc[m][0], acc[m][1], acc[m][2], acc[m][3]);
        *(float4*)&g_R[p][i0 + ty * 4 + m][j0 + tx * 8 + 4] = make_float4(acc[m][4], acc[m][5], acc[m][6], acc[m][7]);
    }
}

// ---------------- gemmA: a = Linv @ kx  + d1/mu partials (grid (8,4,HO)) ----------------
__global__ __launch_bounds__(256) void k_gemmA() {
    __shared__ float As[16][64];
    __shared__ float Bs[16][128];
    __shared__ float vs[64];
    __shared__ float red[16][128];
    int p = blockIdx.z;
    int i0 = blockIdx.y * 64, b0 = blockIdx.x * 128;
    int t = threadIdx.x, tx = t % 16, ty = t / 16;
    if (t < 64) vs[t] = g_vm[p][i0 + t];
    float acc[4][8];
#pragma unroll
    for (int m = 0; m < 4; m++)
#pragma unroll
        for (int n = 0; n < 8; n++) acc[m][n] = 0.0f;

    int kmax = i0 + 64;
    for (int kc = 0; kc < kmax; kc += 16) {
        {
            int kk = t >> 4, i4 = t & 15;
            *(float4*)&As[kk][i4 * 4] = *(const float4*)&g_Wt[p][kc + kk][i0 + i4 * 4];
        }
#pragma unroll
        for (int e = 0; e < 2; e++) {
            int q = t + e * 256;
            int kk = q >> 5, b4 = q & 31;
            *(float4*)&Bs[kk][b4 * 4] = *(const float4*)&g_kx[p][kc + kk][b0 + b4 * 4];
        }
        __syncthreads();
#pragma unroll
        for (int kk = 0; kk < 16; kk++) {
            float av[4], bv[8];
#pragma unroll
            for (int m = 0; m < 4; m++) av[m] = As[kk][ty * 4 + m];
            float4 b0v = *(const float4*)&Bs[kk][tx * 8];
            float4 b1v = *(const float4*)&Bs[kk][tx * 8 + 4];
            bv[0] = b0v.x; bv[1] = b0v.y; bv[2] = b0v.z; bv[3] = b0v.w;
            bv[4] = b1v.x; bv[5] = b1v.y; bv[6] = b1v.z; bv[7] = b1v.w;
#pragma unroll
            for (int m = 0; m < 4; m++)
#pragma unroll
                for (int n = 0; n < 8; n++) acc[m][n] += av[m] * bv[n];
        }
        __syncthreads();
    }
    // write a
#pragma unroll
    for (int m = 0; m < 4; m++) {
        *(float4*)&g_a[p][i0 + ty * 4 + m][b0 + tx * 8]     = make_float4(acc[m][0], acc[m][1], acc[m][2], acc[m][3]);
        *(float4*)&g_a[p][i0 + ty * 4 + m][b0 + tx * 8 + 4] = make_float4(acc[m][4], acc[m][5], acc[m][6], acc[m][7]);
    }
    // d1 partials
#pragma unroll
    for (int n = 0; n < 8; n++) {
        float s = 0.0f;
#pragma unroll
        for (int m = 0; m < 4; m++) s += acc[m][n] * acc[m][n];
        red[ty][tx * 8 + n] = s;
    }
    __syncthreads();
    if (t < 128) {
        float s = 0.0f;
#pragma unroll
        for (int y = 0; y < 16; y++) s += red[y][t];
        g_d1p[blockIdx.y][p][b0 + t] = s;
    }
    __syncthreads();
    // mu partials
#pragma unroll
    for (int n = 0; n < 8; n++) {
        float s = 0.0f;
#pragma unroll
        for (int m = 0; m < 4; m++) s += vs[ty * 4 + m] * acc[m][n];
        red[ty][tx * 8 + n] = s;
    }
    __syncthreads();
    if (t < 128) {
        float s = 0.0f;
#pragma unroll
        for (int y = 0; y < 16; y++) s += red[y][t];
        g_mup[blockIdx.y][p][b0 + t] = s;
    }
}

// ---------------- gemmH: h = R^T @ a, d2 = ||h||^2 partials (grid (8,4,HO)) ----------------
__global__ __launch_bounds__(256) void k_gemmH() {
    __shared__ float As[16][64];
    __shared__ float Bs[16][128];
    __shared__ float red[16][128];
    int p = blockIdx.z;
    int j0 = blockIdx.y * 64, b0 = blockIdx.x * 128;
    int t = threadIdx.x, tx = t % 16, ty = t / 16;
    float acc[4][8];
#pragma unroll
    for (int m = 0; m < 4; m++)
#pragma unroll
        for (int n = 0; n < 8; n++) acc[m][n] = 0.0f;

    for (int kc = j0; kc < M2; kc += 16) {
        {   // A: As[kk][j] = R[kc+kk][j0+j]  (R^T staging, coalesced)
            int kk = t >> 4, i4 = t & 15;
            *(float4*)&As[kk][i4 * 4] = *(const float4*)&g_R[p][kc + kk][j0 + i4 * 4];
        }
#pragma unroll
        for (int e = 0; e < 2; e++) {
            int q = t + e * 256;
            int kk = q >> 5, b4 = q & 31;
            *(float4*)&Bs[kk][b4 * 4] = *(const float4*)&g_a[p][kc + kk][b0 + b4 * 4];
        }
        __syncthreads();
#pragma unroll
        for (int kk = 0; kk < 16; kk++) {
            float av[4], bv[8];
#pragma unroll
            for (int m = 0; m < 4; m++) av[m] = As[kk][ty * 4 + m];
            float4 b0v = *(const float4*)&Bs[kk][tx * 8];
            float4 b1v = *(const float4*)&Bs[kk][tx * 8 + 4];
            bv[0] = b0v.x; bv[1] = b0v.y; bv[2] = b0v.z; bv[3] = b0v.w;
            bv[4] = b1v.x; bv[5] = b1v.y; bv[6] = b1v.z; bv[7] = b1v.w;
#pragma unroll
            for (int m = 0; m < 4; m++)
#pragma unroll
                for (int n = 0; n < 8; n++) acc[m][n] += av[m] * bv[n];
        }
        __syncthreads();
    }
    // d2 partials (h never written to global)
#pragma unroll
    for (int n = 0; n < 8; n++) {
        float s = 0.0f;
#pragma unroll
        for (int m = 0; m < 4; m++) s += acc[m][n] * acc[m][n];
        red[ty][tx * 8 + n] = s;
    }
    __syncthreads();
    if (t < 128) {
        float s = 0.0f;
#pragma unroll
        for (int y = 0; y < 16; y++) s += red[y][t];
        g_d2p[blockIdx.y][p][b0 + t] = s;
    }
}

// ---------------- final combine ----------------
__global__ void k_final(float* __restrict__ out) {
    int idx = blockIdx.x * 256 + threadIdx.x;
    if (idx >= HOB) return;
    int p = idx / Bb, b = idx % Bb;
    float mu = g_mup[0][p][b] + g_mup[1][p][b] + g_mup[2][p][b] + g_mup[3][p][b];
    float d1 = g_d1p[0][p][b] + g_d1p[1][p][b] + g_d1p[2][p][b] + g_d1p[3][p][b];
    float d2 = g_d2p[0][p][b] + g_d2p[1][p][b] + g_d2p[2][p][b] + g_d2p[3][p][b];
    out[idx] = mu;
    out[HOB + idx] = g_sf2[p / Oo] - d1 + d2;
}

extern "C" void kernel_launch(void* const* d_in, const int* in_sizes, int n_in,
                              void* d_out, int out_size) {
    const float* x          = (const float*)d_in[0];
    const float* z          = (const float*)d_in[1];
    const float* u_mean     = (const float*)d_in[2];
    const float* u_tril_vec = (const float*)d_in[3];
    const float* m_old      = (const float*)d_in[4];
    const float* L_old      = (const float*)d_in[5];
    const float* z_old      = (const float*)d_in[6];
    const float* theta      = (const float*)d_in[7];
    float* out = (float*)d_out;

    cudaFuncSetAttribute(k_stageA, cudaFuncAttributeMaxDynamicSharedMemorySize, 199168);
    cudaFuncSetAttribute(k_stageB1, cudaFuncAttributeMaxDynamicSharedMemorySize, 132608);
    cudaFuncSetAttribute(k_stageB2, cudaFuncAttributeMaxDynamicSharedMemorySize, 132608);

    k_prep_theta<<<1, 128>>>(theta);
    k_prep_x<<<16, 256>>>(x);
    k_prep_z<<<HO, 256>>>(z, z_old);
    k_kuu2<<<dim3(16, HO), 256>>>();
    k_kx<<<dim3(8, HO), 256>>>();
    k_stageA<<<HO, 256, 199168>>>(m_old, L_old, u_mean, u_tril_vec);
    k_stageB1<<<HO, 256, 132608>>>();
    k_stageB2<<<HO, 256, 132608>>>();
    k_gemmR<<<dim3(2, 4, HO), 256>>>();
    k_gemmA<<<dim3(8, 4, HO), 256>>>();
    k_gemmH<<<dim3(8, 4, HO), 256>>>();
    k_final<<<512, 256>>>(out);
}

// round 5
// speedup vs baseline: 1.4224x; 1.1239x over previous
#include <cuda_runtime.h>

#define Hh 4
#define Oo 32
#define Mm 128
#define M2 256
#define Dd 16
#define Bb 1024
#define HO 128
#define HOB (HO*Bb)
#define JIT 1e-4f
#define PACKN 32896   /* 256*257/2 */

// ---------------- f32x2 helpers ----------------
__device__ __forceinline__ unsigned long long pk2(float lo, float hi) {
    unsigned long long r;
    asm("mov.b64 %0, {%1, %2};" : "=l"(r) : "f"(lo), "f"(hi));
    return r;
}
__device__ __forceinline__ float2 upk2(unsigned long long v) {
    float2 r;
    asm("mov.b64 {%0, %1}, %2;" : "=f"(r.x), "=f"(r.y) : "l"(v));
    return r;
}
__device__ __forceinline__ unsigned long long ffma2(unsigned long long a, unsigned long long b, unsigned long long c) {
    unsigned long long d;
    asm("fma.rn.f32x2 %0, %1, %2, %3;" : "=l"(d) : "l"(a), "l"(b), "l"(c));
    return d;
}

// ---------------- device scratch ----------------
__device__ float g_sf2[Hh];
__device__ float g_invls[Hh][Dd];
__device__ float g_Xs[Hh][Bb][Dd];
__device__ float g_xn[Hh][Bb];
__device__ float g_Zs[HO][M2][Dd];
__device__ float g_zn[HO][M2];
__device__ float g_kuu2[HO][M2][M2];   // k(z_joint,z_joint), NO jitter
__device__ float g_cov[HO][M2][M2];    // cov_joint (lower triangle valid), NO jitter
__device__ float g_Wt[HO][M2][M2];     // Wt[k][i] = Linv[i][k]  (zero where i<k)
__device__ float g_Lj[HO][M2][M2];     // L_joint = chol(cov+jit I), zeros upper
__device__ float g_R[HO][M2][M2];      // R = Linv @ L_joint (lower tri)
__device__ float g_vm[HO][M2];         // Linv @ m_joint
__device__ float g_mj[HO][M2];
__device__ float g_kx[HO][M2][Bb];     // k(z_joint, x)
__device__ float g_a[HO][M2][Bb];      // Linv @ kx
__device__ float g_d1p[2][HO][Bb];
__device__ float g_d2p[2][HO][Bb];
__device__ float g_mup[2][HO][Bb];

// ---------------- prep ----------------
__global__ void k_prep_theta(const float* __restrict__ theta) {
    int t = threadIdx.x;
    if (t < Hh * (Dd + 1)) {
        int h = t / (Dd + 1), c = t % (Dd + 1);
        float v = theta[t];
        if (c == 0) g_sf2[h] = expf(v);
        else        g_invls[h][c - 1] = expf(-v);
    }
}

__global__ void k_prep_x(const float* __restrict__ x) {
    int g = blockIdx.x * blockDim.x + threadIdx.x;
    if (g >= Hh * Bb) return;
    int h = g / Bb, b = g % Bb;
    float s = 0.0f;
#pragma unroll
    for (int d = 0; d < Dd; d++) {
        float v = x[b * Dd + d] * g_invls[h][d];
        g_Xs[h][b][d] = v;
        s += v * v;
    }
    g_xn[h][b] = s;
}

__global__ void k_prep_z(const float* __restrict__ z, const float* __restrict__ z_old) {
    int p = blockIdx.x;
    int h = p / Oo, o = p % Oo;
    int i = threadIdx.x;  // 0..255
    const float* src = (i < Mm) ? &z_old[(o * Mm + i) * Dd] : &z[(o * Mm + (i - Mm)) * Dd];
    float s = 0.0f;
#pragma unroll
    for (int d = 0; d < Dd; d++) {
        float v = src[d] * g_invls[h][d];
        g_Zs[p][i][d] = v;
        s += v * v;
    }
    g_zn[p][i] = s;
}

// kuu2: grid (16, HO), block 256
__global__ void k_kuu2() {
    __shared__ float zn[M2];
    int p = blockIdx.y, rc = blockIdx.x, t = threadIdx.x;
    float myz[Dd];
#pragma unroll
    for (int d = 0; d < Dd; d++) myz[d] = g_Zs[p][t][d];
    zn[t] = g_zn[p][t];
    __syncthreads();
    float sf2 = g_sf2[p / Oo];
#pragma unroll 2
    for (int e = 0; e < 16; e++) {
        int row = rc * 16 + e;
        float dot = 0.0f;
#pragma unroll
        for (int d = 0; d < Dd; d++) dot += g_Zs[p][row][d] * myz[d];
        float d2 = fmaxf(zn[row] + zn[t] - 2.0f * dot, 0.0f);
        g_kuu2[p][row][t] = sf2 * __expf(-0.5f * d2);
    }
}

// kx = k(z_joint, x): grid (8, HO), block 256
__global__ void k_kx() {
    __shared__ float zs[M2][Dd + 1];
    __shared__ float zn[M2];
    int p = blockIdx.y, b0 = blockIdx.x * 128, t = threadIdx.x;
    int h = p / Oo;
    for (int e = t; e < M2 * Dd; e += 256) {
        int i = e >> 4, d = e & 15;
        zs[i][d] = g_Zs[p][i][d];
    }
    zn[t] = g_zn[p][t];
    __syncthreads();
    int bl = t & 127, half = t >> 7;
    float xr[Dd];
#pragma unroll
    for (int d = 0; d < Dd; d++) xr[d] = g_Xs[h][b0 + bl][d];
    float xnn = g_xn[h][b0 + bl];
    float sf2 = g_sf2[h];
    for (int ii = 0; ii < 128; ii++) {
        int i = half * 128 + ii;
        float dot = 0.0f;
#pragma unroll
        for (int d = 0; d < Dd; d++) dot += zs[i][d] * xr[d];
        float d2 = fmaxf(zn[i] + xnn - 2.0f * dot, 0.0f);
        g_kx[p][i][b0 + bl] = sf2 * __expf(-0.5f * d2);
    }
}

// ---------------- stage A: 128-chol + solves -> m_joint, cov_joint (lower) ----------------
// dyn smem: Ls[128*129] X1[128*129] X2[128*129] dinv[128] yv[128] = 199168 B
__global__ void k_stageA(const float* __restrict__ m_old, const float* __restrict__ L_old,
                         const float* __restrict__ u_mean, const float* __restrict__ u_tril_vec) {
    extern __shared__ float sm[];
    const int LD = 129;
    float* Ls   = sm;
    float* X1   = sm + 16512;
    float* X2   = sm + 33024;
    float* dinv = sm + 49536;
    float* yv   = sm + 49664;
    int p = blockIdx.x, o = p % Oo, t = threadIdx.x;
    int tx = t & 15, ty = t >> 4;   // 16x16 thread grid for microtiled sections

    for (int e = t; e < Mm * Mm; e += 256) {
        int i = e >> 7, j = e & 127;
        float v = g_kuu2[p][i][j];
        if (i == j) v += JIT;
        Ls[i * LD + j] = v;
    }
    __syncthreads();

    // Cholesky (128)
    for (int j = 0; j < Mm; j++) {
        if (t < 32) {
            float s = 0.0f;
            for (int k = t; k < j; k += 32) { float v = Ls[j * LD + k]; s += v * v; }
            for (int w = 16; w; w >>= 1) s += __shfl_down_sync(0xffffffffu, s, w);
            if (t == 0) {
                float d = sqrtf(Ls[j * LD + j] - s);
                Ls[j * LD + j] = d;
                dinv[j] = 1.0f / d;
            }
        }
        __syncthreads();
        int i = j + 1 + t;
        if (i < Mm) {
            float s0 = 0, s1 = 0, s2 = 0, s3 = 0;
            int k = 0;
            for (; k + 3 < j; k += 4) {
                s0 += Ls[i * LD + k]     * Ls[j * LD + k];
                s1 += Ls[i * LD + k + 1] * Ls[j * LD + k + 1];
                s2 += Ls[i * LD + k + 2] * Ls[j * LD + k + 2];
                s3 += Ls[i * LD + k + 3] * Ls[j * LD + k + 3];
            }
            for (; k < j; k++) s0 += Ls[i * LD + k] * Ls[j * LD + k];
            Ls[i * LD + j] = (Ls[i * LD + j] - ((s0 + s1) + (s2 + s3))) * dinv[j];
        }
        __syncthreads();
    }

    // yv = Linv * m_old
    {
        float acc = 0.0f;
        for (int i = 0; i < Mm; i++) {
            if (t == i) yv[i] = (m_old[o * Mm + i] - acc) * dinv[i];
            __syncthreads();
            if (t > i && t < Mm) acc += Ls[t * LD + i] * yv[i];
        }
    }
    __syncthreads();

    // X1 = Linv*kuf (t<128), X2 = Linv*L_old (t>=128)
    {
        int c = t & 127;
        bool isX1 = (t < 128);
        float* X = isX1 ? X1 : X2;
        for (int i = 0; i < Mm; i++) {
            float r = isX1 ? g_kuu2[p][i][Mm + c] : L_old[(o * Mm + i) * Mm + c];
            float s0 = 0, s1 = 0, s2 = 0, s3 = 0;
            int k = 0;
            for (; k + 3 < i; k += 4) {
                s0 += Ls[i * LD + k]     * X[(k) * LD + c];
                s1 += Ls[i * LD + k + 1] * X[(k + 1) * LD + c];
                s2 += Ls[i * LD + k + 2] * X[(k + 2) * LD + c];
                s3 += Ls[i * LD + k + 3] * X[(k + 3) * LD + c];
            }
            for (; k < i; k++) s0 += Ls[i * LD + k] * X[k * LD + c];
            X[i * LD + c] = (r - ((s0 + s1) + (s2 + s3))) * dinv[i];
        }
    }
    __syncthreads();

    // m_joint
    if (t < Mm) {
        float s = 0.0f;
        for (int i = 0; i < Mm; i++) s += X1[i * LD + t] * yv[i];
        g_mj[p][t] = m_old[o * Mm + t];
        g_mj[p][Mm + t] = s + u_mean[o * Mm + t];
    }
    __syncthreads();

    // AtX[j][k] = sum_i X2[i][j]*X1[i][k]  (8x8 microtile, rows j = ty+16m, cols k = tx+16n)
    {
        float c[8][8];
#pragma unroll
        for (int m = 0; m < 8; m++)
#pragma unroll
            for (int n = 0; n < 8; n++) c[m][n] = 0.0f;
        for (int i = 0; i < Mm; i++) {
            float a[8], b[8];
#pragma unroll
            for (int m = 0; m < 8; m++) a[m] = X2[i * LD + ty + 16 * m];
#pragma unroll
            for (int n = 0; n < 8; n++) b[n] = X1[i * LD + tx + 16 * n];
#pragma unroll
            for (int m = 0; m < 8; m++)
#pragma unroll
                for (int n = 0; n < 8; n++) c[m][n] += a[m] * b[n];
        }
        __syncthreads();   // Ls (chol) no longer needed after this point? it IS: writes go to Ls
#pragma unroll
        for (int m = 0; m < 8; m++)
#pragma unroll
            for (int n = 0; n < 8; n++) Ls[(ty + 16 * m) * LD + tx + 16 * n] = c[m][n];
    }
    __syncthreads();

    // reload: X1 <- L_old (true zeros upper), X2 <- dense(u_tril)
    for (int e = t; e < Mm * Mm; e += 256) {
        int i = e >> 7, j = e & 127;
        X1[i * LD + j] = L_old[(o * Mm + i) * Mm + j];
        X2[i * LD + j] = (j <= i) ? u_tril_vec[o * 8256 + (i * (i + 1)) / 2 + j] : 0.0f;
    }
    __syncthreads();

    // cov_joint lower triangle blocks (8x8 microtiles):
    // TL[i][j] = sum_k X1[i,k] X1[j,k]
    {
        float c[8][8];
#pragma unroll
        for (int m = 0; m < 8; m++)
#pragma unroll
            for (int n = 0; n < 8; n++) c[m][n] = 0.0f;
        for (int k = 0; k < Mm; k++) {
            float a[8], b[8];
#pragma unroll
            for (int m = 0; m < 8; m++) a[m] = X1[(ty + 16 * m) * LD + k];
#pragma unroll
            for (int n = 0; n < 8; n++) b[n] = X1[(tx + 16 * n) * LD + k];
#pragma unroll
            for (int m = 0; m < 8; m++)
#pragma unroll
                for (int n = 0; n < 8; n++) c[m][n] += a[m] * b[n];
        }
#pragma unroll
        for (int m = 0; m < 8; m++)
#pragma unroll
            for (int n = 0; n < 8; n++) g_cov[p][ty + 16 * m][tx + 16 * n] = c[m][n];
    }

    // BL[Mm+j][i] = sum_k X1[i,k] * AtX[k,j]   (rows j = ty+16m, cols i = tx+16n)
    {
        float c[8][8];
#pragma unroll
        for (int m = 0; m < 8; m++)
#pragma unroll
            for (int n = 0; n < 8; n++) c[m][n] = 0.0f;
        for (int k = 0; k < Mm; k++) {
            float a[8], b[8];
#pragma unroll
            for (int m = 0; m < 8; m++) a[m] = Ls[k * LD + ty + 16 * m];
#pragma unroll
            for (int n = 0; n < 8; n++) b[n] = X1[(tx + 16 * n) * LD + k];
#pragma unroll
            for (int m = 0; m < 8; m++)
#pragma unroll
                for (int n = 0; n < 8; n++) c[m][n] += a[m] * b[n];
        }
#pragma unroll
        for (int m = 0; m < 8; m++)
#pragma unroll
            for (int n = 0; n < 8; n++) g_cov[p][Mm + ty + 16 * m][tx + 16 * n] = c[m][n];
    }

    // BR[Mm+i][Mm+j] = sum_k X2[i,k]X2[j,k] + sum_k AtX[k,i]AtX[k,j]
    {
        float c[8][8];
#pragma unroll
        for (int m = 0; m < 8; m++)
#pragma unroll
            for (int n = 0; n < 8; n++) c[m][n] = 0.0f;
        for (int k = 0; k < Mm; k++) {
            float a[8], b[8];
#pragma unroll
            for (int m = 0; m < 8; m++) a[m] = X2[(ty + 16 * m) * LD + k];
#pragma unroll
            for (int n = 0; n < 8; n++) b[n] = X2[(tx + 16 * n) * LD + k];
#pragma unroll
            for (int m = 0; m < 8; m++)
#pragma unroll
                for (int n = 0; n < 8; n++) c[m][n] += a[m] * b[n];
        }
        for (int k = 0; k < Mm; k++) {
            float a[8], b[8];
#pragma unroll
            for (int m = 0; m < 8; m++) a[m] = Ls[k * LD + ty + 16 * m];
#pragma unroll
            for (int n = 0; n < 8; n++) b[n] = Ls[k * LD + tx + 16 * n];
#pragma unroll
            for (int m = 0; m < 8; m++)
#pragma unroll
                for (int n = 0; n < 8; n++) c[m][n] += a[m] * b[n];
        }
#pragma unroll
        for (int m = 0; m < 8; m++)
#pragma unroll
            for (int n = 0; n < 8; n++) g_cov[p][Mm + ty + 16 * m][Mm + tx + 16 * n] = c[m][n];
    }
}

// ---------------- stage B1: packed 256-chol(kuu2) + trtri -> Wt, vm ----------------
// dyn smem: Lp[32896] dinv[256] = 132608 B
__global__ void k_stageB1() {
    extern __shared__ float sm[];
    float* Lp   = sm;
    float* dinv = sm + PACKN;
    int p = blockIdx.x, t = threadIdx.x;

    for (int e = t; e < PACKN; e += 256) {
        int r = (int)((sqrtf(8.0f * (float)e + 1.0f) - 1.0f) * 0.5f);
        while ((r + 1) * (r + 2) / 2 <= e) r++;
        while (r * (r + 1) / 2 > e) r--;
        int c = e - r * (r + 1) / 2;
        float v = g_kuu2[p][r][c];
        if (r == c) v += JIT;
        Lp[e] = v;
    }
    __syncthreads();

    // packed Cholesky (256)
    for (int j = 0; j < M2; j++) {
        int oj = j * (j + 1) / 2;
        if (t < 32) {
            float s = 0.0f;
            for (int k = t; k < j; k += 32) { float v = Lp[oj + k]; s += v * v; }
            for (int w = 16; w; w >>= 1) s += __shfl_down_sync(0xffffffffu, s, w);
            if (t == 0) {
                float d = sqrtf(Lp[oj + j] - s);
                Lp[oj + j] = d;
                dinv[j] = 1.0f / d;
            }
        }
        __syncthreads();
        int i = j + 1 + t;
        if (i < M2) {
            int oi = i * (i + 1) / 2;
            float s0 = 0, s1 = 0, s2 = 0, s3 = 0;
            int k = 0;
            for (; k + 3 < j; k += 4) {
                s0 += Lp[oi + k]     * Lp[oj + k];
                s1 += Lp[oi + k + 1] * Lp[oj + k + 1];
                s2 += Lp[oi + k + 2] * Lp[oj + k + 2];
                s3 += Lp[oi + k + 3] * Lp[oj + k + 3];
            }
            for (; k < j; k++) s0 += Lp[oi + k] * Lp[oj + k];
            Lp[oi + j] = (Lp[oi + j] - ((s0 + s1) + (s2 + s3))) * dinv[j];
        }
        __syncthreads();
    }

    // in-place trtri
    if (t == 0) Lp[0] = dinv[0];
    __syncthreads();
    for (int i = 1; i < M2; i++) {
        int oi = i * (i + 1) / 2;
        float v = 0.0f;
        if (t < i) {
            float s0 = 0, s1 = 0, s2 = 0, s3 = 0;
            int k = t, ok = t * (t + 1) / 2;
            for (; k + 3 < i; ) {
                int ok1 = ok + k + 1, ok2 = ok1 + k + 2, ok3 = ok2 + k + 3;
                s0 += Lp[oi + k]     * Lp[ok + t];
                s1 += Lp[oi + k + 1] * Lp[ok1 + t];
                s2 += Lp[oi + k + 2] * Lp[ok2 + t];
                s3 += Lp[oi + k + 3] * Lp[ok3 + t];
                ok = ok3 + k + 4; k += 4;
            }
            for (; k < i; k++) { s0 += Lp[oi + k] * Lp[ok + t]; ok += k + 1; }
            v = -dinv[i] * ((s0 + s1) + (s2 + s3));
        }
        __syncthreads();
        if (t < i) Lp[oi + t] = v;
        if (t == 0) Lp[oi + i] = dinv[i];
        __syncthreads();
    }

    // vm = Linv @ m_joint
    {
        int ot = t * (t + 1) / 2;
        float s = 0.0f;
        for (int k = 0; k <= t; k++) s += Lp[ot + k] * g_mj[p][k];
        g_vm[p][t] = s;
    }

    // Wt[k][i] = Linv[i][k] (zeros where i<k)
    for (int e = t; e < M2 * M2; e += 256) {
        int k = e >> 8, i = e & 255;
        g_Wt[p][k][i] = (i >= k) ? Lp[i * (i + 1) / 2 + k] : 0.0f;
    }
}

// ---------------- stage B2: packed 256-chol(cov+jit) -> L_joint dense ----------------
__global__ void k_stageB2() {
    extern __shared__ float sm[];
    float* Lp   = sm;
    float* dinv = sm + PACKN;
    int p = blockIdx.x, t = threadIdx.x;

    for (int e = t; e < PACKN; e += 256) {
        int r = (int)((sqrtf(8.0f * (float)e + 1.0f) - 1.0f) * 0.5f);
        while ((r + 1) * (r + 2) / 2 <= e) r++;
        while (r * (r + 1) / 2 > e) r--;
        int c = e - r * (r + 1) / 2;
        float v = g_cov[p][r][c];
        if (r == c) v += JIT;
        Lp[e] = v;
    }
    __syncthreads();

    for (int j = 0; j < M2; j++) {
        int oj = j * (j + 1) / 2;
        if (t < 32) {
            float s = 0.0f;
            for (int k = t; k < j; k += 32) { float v = Lp[oj + k]; s += v * v; }
            for (int w = 16; w; w >>= 1) s += __shfl_down_sync(0xffffffffu, s, w);
            if (t == 0) {
                float d = sqrtf(Lp[oj + j] - s);
                Lp[oj + j] = d;
                dinv[j] = 1.0f / d;
            }
        }
        __syncthreads();
        int i = j + 1 + t;
        if (i < M2) {
            int oi = i * (i + 1) / 2;
            float s0 = 0, s1 = 0, s2 = 0, s3 = 0;
            int k = 0;
            for (; k + 3 < j; k += 4) {
                s0 += Lp[oi + k]     * Lp[oj + k];
                s1 += Lp[oi + k + 1] * Lp[oj + k + 1];
                s2 += Lp[oi + k + 2] * Lp[oj + k + 2];
                s3 += Lp[oi + k + 3] * Lp[oj + k + 3];
            }
            for (; k < j; k++) s0 += Lp[oi + k] * Lp[oj + k];
            Lp[oi + j] = (Lp[oi + j] - ((s0 + s1) + (s2 + s3))) * dinv[j];
        }
        __syncthreads();
    }

    // L_joint dense (zeros upper)
    for (int e = t; e < M2 * M2; e += 256) {
        int r = e >> 8, c = e & 255;
        g_Lj[p][r][c] = (c <= r) ? Lp[r * (r + 1) / 2 + c] : 0.0f;
    }
}

// ---------------- gemmR: R = Linv @ L_joint  (grid (2,4,HO), 256 thr) ----------------
__global__ __launch_bounds__(256) void k_gemmR() {
    __shared__ float As[16][64];
    __shared__ float Bs[16][128];
    int p = blockIdx.z;
    int i0 = blockIdx.y * 64, j0 = blockIdx.x * 128;
    int t = threadIdx.x, tx = t % 16, ty = t / 16;
    float acc[4][8];
#pragma unroll
    for (int m = 0; m < 4; m++)
#pragma unroll
        for (int n = 0; n < 8; n++) acc[m][n] = 0.0f;

    int kmin = j0, kmax = i0 + 64;
    for (int kc = kmin; kc < kmax; kc += 16) {
        {
            int kk = t >> 4, i4 = t & 15;
            *(float4*)&As[kk][i4 * 4] = *(const float4*)&g_Wt[p][kc + kk][i0 + i4 * 4];
        }
#pragma unroll
        for (int e = 0; e < 2; e++) {
            int q = t + e * 256;
            int kk = q >> 5, b4 = q & 31;
            *(float4*)&Bs[kk][b4 * 4] = *(const float4*)&g_Lj[p][kc + kk][j0 + b4 * 4];
        }
        __syncthreads();
#pragma unroll
        for (int kk = 0; kk < 16; kk++) {
            float av[4], bv[8];
#pragma unroll
            for (int m = 0; m < 4; m++) av[m] = As[kk][ty * 4 + m];
            float4 b0v = *(const float4*)&Bs[kk][tx * 8];
            float4 b1v = *(const float4*)&Bs[kk][tx * 8 + 4];
            bv[0] = b0v.x; bv[1] = b0v.y; bv[2] = b0v.z; bv[3] = b0v.w;
            bv[4] = b1v.x; bv[5] = b1v.y; bv[6] = b1v.z; bv[7] = b1v.w;
#pragma unroll
            for (int m = 0; m < 4; m++)
#pragma unroll
                for (int n = 0; n < 8; n++) acc[m][n] += av[m] * bv[n];
        }
        __syncthreads();
    }
#pragma unroll
    for (int m = 0; m < 4; m++) {
        *(float4*)&g_R[p][i0 + ty * 4 + m][j0 + tx * 8]     = make_float4(acc[m][0], acc[m][1], acc[m][2], acc[m][3]);
        *(float4*)&g_R[p][i0 + ty * 4 + m][j0 + tx * 8 + 4] = make_float4(acc[m][4], acc[m][5], acc[m][6], acc[m][7]);
    }
}

// ---------------- gemmA: a = Linv @ kx  (FFMA2, 128x128 tile) + d1/mu partials ----------------
// grid (8, 2, HO), 256 threads
__global__ __launch_bounds__(256) void k_gemmA() {
    __shared__ float As[16][128];
    __shared__ float Bs[16][128];
    __shared__ float vs[128];
    __shared__ float red[16][128];
    int p = blockIdx.z;
    int i0 = blockIdx.y * 128, b0 = blockIdx.x * 128;
    int t = threadIdx.x, tx = t % 16, ty = t / 16;
    if (t < 128) vs[t] = g_vm[p][i0 + t];
    unsigned long long acc[8][4];
#pragma unroll
    for (int m = 0; m < 8; m++)
#pragma unroll
        for (int n = 0; n < 4; n++) acc[m][n] = 0ULL;

    int kmax = i0 + 128;
    for (int kc = 0; kc < kmax; kc += 16) {
#pragma unroll
        for (int e = 0; e < 2; e++) {
            int q = t + e * 256;
            int kk = q >> 5, c4 = q & 31;
            *(float4*)&As[kk][c4 * 4] = *(const float4*)&g_Wt[p][kc + kk][i0 + c4 * 4];
            *(float4*)&Bs[kk][c4 * 4] = *(const float4*)&g_kx[p][kc + kk][b0 + c4 * 4];
        }
        __syncthreads();
#pragma unroll
        for (int kk = 0; kk < 16; kk++) {
            float4 a0 = *(const float4*)&As[kk][ty * 8];
            float4 a1 = *(const float4*)&As[kk][ty * 8 + 4];
            float4 q0 = *(const float4*)&Bs[kk][tx * 8];
            float4 q1 = *(const float4*)&Bs[kk][tx * 8 + 4];
            unsigned long long bp[4] = { pk2(q0.x, q0.y), pk2(q0.z, q0.w), pk2(q1.x, q1.y), pk2(q1.z, q1.w) };
            float am[8] = { a0.x, a0.y, a0.z, a0.w, a1.x, a1.y, a1.z, a1.w };
#pragma unroll
            for (int m = 0; m < 8; m++) {
                unsigned long long ad = pk2(am[m], am[m]);
#pragma unroll
                for (int n = 0; n < 4; n++) acc[m][n] = ffma2(ad, bp[n], acc[m][n]);
            }
        }
        __syncthreads();
    }
    // unpack + write a
    float av[8][8];
#pragma unroll
    for (int m = 0; m < 8; m++) {
#pragma unroll
        for (int n = 0; n < 4; n++) {
            float2 v = upk2(acc[m][n]);
            av[m][n * 2] = v.x; av[m][n * 2 + 1] = v.y;
        }
        *(float4*)&g_a[p][i0 + ty * 8 + m][b0 + tx * 8]     = make_float4(av[m][0], av[m][1], av[m][2], av[m][3]);
        *(float4*)&g_a[p][i0 + ty * 8 + m][b0 + tx * 8 + 4] = make_float4(av[m][4], av[m][5], av[m][6], av[m][7]);
    }
    // d1 partials
#pragma unroll
    for (int n = 0; n < 8; n++) {
        float s = 0.0f;
#pragma unroll
        for (int m = 0; m < 8; m++) s += av[m][n] * av[m][n];
        red[ty][tx * 8 + n] = s;
    }
    __syncthreads();
    if (t < 128) {
        float s = 0.0f;
#pragma unroll
        for (int y = 0; y < 16; y++) s += red[y][t];
        g_d1p[blockIdx.y][p][b0 + t] = s;
    }
    __syncthreads();
    // mu partials
#pragma unroll
    for (int n = 0; n < 8; n++) {
        float s = 0.0f;
#pragma unroll
        for (int m = 0; m < 8; m++) s += vs[ty * 8 + m] * av[m][n];
        red[ty][tx * 8 + n] = s;
    }
    __syncthreads();
    if (t < 128) {
        float s = 0.0f;
#pragma unroll
        for (int y = 0; y < 16; y++) s += red[y][t];
        g_mup[blockIdx.y][p][b0 + t] = s;
    }
}

// ---------------- gemmH: h = R^T @ a, d2 partials (FFMA2, 128x128 tile) ----------------
// grid (8, 2, HO), 256 threads
__global__ __launch_bounds__(256) void k_gemmH() {
    __shared__ float As[16][128];
    __shared__ float Bs[16][128];
    __shared__ float red[16][128];
    int p = blockIdx.z;
    int j0 = blockIdx.y * 128, b0 = blockIdx.x * 128;
    int t = threadIdx.x, tx = t % 16, ty = t / 16;
    unsigned long long acc[8][4];
#pragma unroll
    for (int m = 0; m < 8; m++)
#pragma unroll
        for (int n = 0; n < 4; n++) acc[m][n] = 0ULL;

    for (int kc = j0; kc < M2; kc += 16) {
#pragma unroll
        for (int e = 0; e < 2; e++) {
            int q = t + e * 256;
            int kk = q >> 5, c4 = q & 31;
            *(float4*)&As[kk][c4 * 4] = *(const float4*)&g_R[p][kc + kk][j0 + c4 * 4];
            *(float4*)&Bs[kk][c4 * 4] = *(const float4*)&g_a[p][kc + kk][b0 + c4 * 4];
        }
        __syncthreads();
#pragma unroll
        for (int kk = 0; kk < 16; kk++) {
            float4 a0 = *(const float4*)&As[kk][ty * 8];
            float4 a1 = *(const float4*)&As[kk][ty * 8 + 4];
            float4 q0 = *(const float4*)&Bs[kk][tx * 8];
            float4 q1 = *(const float4*)&Bs[kk][tx * 8 + 4];
            unsigned long long bp[4] = { pk2(q0.x, q0.y), pk2(q0.z, q0.w), pk2(q1.x, q1.y), pk2(q1.z, q1.w) };
            float am[8] = { a0.x, a0.y, a0.z, a0.w, a1.x, a1.y, a1.z, a1.w };
#pragma unroll
            for (int m = 0; m < 8; m++) {
                unsigned long long ad = pk2(am[m], am[m]);
#pragma unroll
                for (int n = 0; n < 4; n++) acc[m][n] = ffma2(ad, bp[n], acc[m][n]);
            }
        }
        __syncthreads();
    }
    // d2 partials (h stays in registers)
#pragma unroll
    for (int n = 0; n < 8; n++) {
        float s = 0.0f;
#pragma unroll
        for (int m = 0; m < 8; m++) {
            float2 v = upk2(acc[m][n / 2]);
            float h = (n & 1) ? v.y : v.x;
            s += h * h;
        }
        red[ty][tx * 8 + n] = s;
    }
    __syncthreads();
    if (t < 128) {
        float s = 0.0f;
#pragma unroll
        for (int y = 0; y < 16; y++) s += red[y][t];
        g_d2p[blockIdx.y][p][b0 + t] = s;
    }
}

// ---------------- final combine ----------------
__global__ void k_final(float* __restrict__ out) {
    int idx = blockIdx.x * 256 + threadIdx.x;
    if (idx >= HOB) return;
    int p = idx / Bb, b = idx % Bb;
    float mu = g_mup[0][p][b] + g_mup[1][p][b];
    float d1 = g_d1p[0][p][b] + g_d1p[1][p][b];
    float d2 = g_d2p[0][p][b] + g_d2p[1][p][b];
    out[idx] = mu;
    out[HOB + idx] = g_sf2[p / Oo] - d1 + d2;
}

extern "C" void kernel_launch(void* const* d_in, const int* in_sizes, int n_in,
                              void* d_out, int out_size) {
    const float* x          = (const float*)d_in[0];
    const float* z          = (const float*)d_in[1];
    const float* u_mean     = (const float*)d_in[2];
    const float* u_tril_vec = (const float*)d_in[3];
    const float* m_old      = (const float*)d_in[4];
    const float* L_old      = (const float*)d_in[5];
    const float* z_old      = (const float*)d_in[6];
    const float* theta      = (const float*)d_in[7];
    float* out = (float*)d_out;

    cudaFuncSetAttribute(k_stageA, cudaFuncAttributeMaxDynamicSharedMemorySize, 199168);
    cudaFuncSetAttribute(k_stageB1, cudaFuncAttributeMaxDynamicSharedMemorySize, 132608);
    cudaFuncSetAttribute(k_stageB2, cudaFuncAttributeMaxDynamicSharedMemorySize, 132608);

    // order chosen so the ncu capture slot (index 3) lands on k_stageA
    k_prep_theta<<<1, 128>>>(theta);
    k_prep_z<<<HO, 256>>>(z, z_old);
    k_kuu2<<<dim3(16, HO), 256>>>();
    k_stageA<<<HO, 256, 199168>>>(m_old, L_old, u_mean, u_tril_vec);
    k_prep_x<<<16, 256>>>(x);
    k_kx<<<dim3(8, HO), 256>>>();
    k_stageB1<<<HO, 256, 132608>>>();
    k_stageB2<<<HO, 256, 132608>>>();
    k_gemmR<<<dim3(2, 4, HO), 256>>>();
    k_gemmA<<<dim3(8, 2, HO), 256>>>();
    k_gemmH<<<dim3(8, 2, HO), 256>>>();
    k_final<<<512, 256>>>(out);
}

// round 6
// speedup vs baseline: 1.8679x; 1.3132x over previous
#include <cuda_runtime.h>

#define Hh 4
#define Oo 32
#define Mm 128
#define M2 256
#define Dd 16
#define Bb 1024
#define HO 128
#define HOB (HO*Bb)
#define JIT 1e-4f
#define LDA 129

// ---------------- f32x2 helpers ----------------
__device__ __forceinline__ unsigned long long pk2(float lo, float hi) {
    unsigned long long r;
    asm("mov.b64 %0, {%1, %2};" : "=l"(r) : "f"(lo), "f"(hi));
    return r;
}
__device__ __forceinline__ float2 upk2(unsigned long long v) {
    float2 r;
    asm("mov.b64 {%0, %1}, %2;" : "=f"(r.x), "=f"(r.y) : "l"(v));
    return r;
}
__device__ __forceinline__ unsigned long long ffma2(unsigned long long a, unsigned long long b, unsigned long long c) {
    unsigned long long d;
    asm("fma.rn.f32x2 %0, %1, %2, %3;" : "=l"(d) : "l"(a), "l"(b), "l"(c));
    return d;
}

// ---------------- device scratch ----------------
__device__ float g_sf2[Hh];
__device__ float g_invls[Hh][Dd];
__device__ float g_Xs[Hh][Bb][Dd];
__device__ float g_xn[Hh][Bb];
__device__ float g_Zs[HO][M2][Dd];
__device__ float g_zn[HO][M2];
__device__ float g_kuu2[HO][M2][M2];   // k(z_joint,z_joint), NO jitter
__device__ float g_cov[HO][M2][M2];    // cov_joint, NO jitter (TL/BL/BR valid)
__device__ float g_Wt[HO][M2][M2];     // Wt[k][i] = Linv256[i][k]
__device__ float g_R[HO][M2][M2];      // R = Linv @ L_joint (blocks; R12 unused)
__device__ float g_vm[HO][M2];         // Linv @ m_joint
__device__ float g_mj[HO][M2];
__device__ float g_kx[HO][M2][Bb];
__device__ float g_a[HO][M2][Bb];
__device__ float g_X1[HO][Mm][Mm];     // Linv11 @ kuf  (= L21^T)
__device__ float g_W11[HO][Mm][Mm];    // trtri(L11) row-major
__device__ float g_W21[HO][Mm][Mm];
__device__ float g_W22[HO][Mm][Mm];    // row-major
__device__ float g_schur[HO][Mm][Mm];  // kuu_new + jit - X1^T X1
__device__ float g_L11p[HO][Mm][Mm];   // chol(cov_TL+jit)
__device__ float g_L21p[HO][Mm][Mm];
__device__ float g_L22p[HO][Mm][Mm];
__device__ float g_d1p[2][HO][Bb];
__device__ float g_d2p[2][HO][Bb];
__device__ float g_mup[2][HO][Bb];

// ---------------- shared serial building blocks (dense 128, LD=129) ----------------
__device__ void chol128(float* Ls, float* dinv, int t) {
    for (int j = 0; j < Mm; j++) {
        if (t < 32) {
            float s = 0.0f;
            for (int k = t; k < j; k += 32) { float v = Ls[j * LDA + k]; s += v * v; }
            for (int w = 16; w; w >>= 1) s += __shfl_down_sync(0xffffffffu, s, w);
            if (t == 0) {
                float d = sqrtf(Ls[j * LDA + j] - s);
                Ls[j * LDA + j] = d;
                dinv[j] = 1.0f / d;
            }
        }
        __syncthreads();
        int i = j + 1 + t;
        if (i < Mm) {
            float s0 = 0, s1 = 0, s2 = 0, s3 = 0;
            int k = 0;
            for (; k + 3 < j; k += 4) {
                s0 += Ls[i * LDA + k]     * Ls[j * LDA + k];
                s1 += Ls[i * LDA + k + 1] * Ls[j * LDA + k + 1];
                s2 += Ls[i * LDA + k + 2] * Ls[j * LDA + k + 2];
                s3 += Ls[i * LDA + k + 3] * Ls[j * LDA + k + 3];
            }
            for (; k < j; k++) s0 += Ls[i * LDA + k] * Ls[j * LDA + k];
            Ls[i * LDA + j] = (Ls[i * LDA + j] - ((s0 + s1) + (s2 + s3))) * dinv[j];
        }
        __syncthreads();
    }
}

__device__ void trtri128(float* Ls, float* dinv, int t) {
    if (t == 0) Ls[0] = dinv[0];
    __syncthreads();
    for (int i = 1; i < Mm; i++) {
        float v = 0.0f;
        if (t < i) {
            float s0 = 0, s1 = 0, s2 = 0, s3 = 0;
            int k = t;
            for (; k + 3 < i; k += 4) {
                s0 += Ls[i * LDA + k]     * Ls[(k)     * LDA + t];
                s1 += Ls[i * LDA + k + 1] * Ls[(k + 1) * LDA + t];
                s2 += Ls[i * LDA + k + 2] * Ls[(k + 2) * LDA + t];
                s3 += Ls[i * LDA + k + 3] * Ls[(k + 3) * LDA + t];
            }
            for (; k < i; k++) s0 += Ls[i * LDA + k] * Ls[k * LDA + t];
            v = -dinv[i] * ((s0 + s1) + (s2 + s3));
        }
        __syncthreads();
        if (t < i) Ls[i * LDA + t] = v;
        if (t == 0) Ls[i * LDA + i] = dinv[i];
        __syncthreads();
    }
}

// ---------------- prep ----------------
__global__ void k_prep_theta(const float* __restrict__ theta) {
    int t = threadIdx.x;
    if (t < Hh * (Dd + 1)) {
        int h = t / (Dd + 1), c = t % (Dd + 1);
        float v = theta[t];
        if (c == 0) g_sf2[h] = expf(v);
        else        g_invls[h][c - 1] = expf(-v);
    }
}

__global__ void k_prep_x(const float* __restrict__ x) {
    int g = blockIdx.x * blockDim.x + threadIdx.x;
    if (g >= Hh * Bb) return;
    int h = g / Bb, b = g % Bb;
    float s = 0.0f;
#pragma unroll
    for (int d = 0; d < Dd; d++) {
        float v = x[b * Dd + d] * g_invls[h][d];
        g_Xs[h][b][d] = v;
        s += v * v;
    }
    g_xn[h][b] = s;
}

__global__ void k_prep_z(const float* __restrict__ z, const float* __restrict__ z_old) {
    int p = blockIdx.x;
    int h = p / Oo, o = p % Oo;
    int i = threadIdx.x;
    const float* src = (i < Mm) ? &z_old[(o * Mm + i) * Dd] : &z[(o * Mm + (i - Mm)) * Dd];
    float s = 0.0f;
#pragma unroll
    for (int d = 0; d < Dd; d++) {
        float v = src[d] * g_invls[h][d];
        g_Zs[p][i][d] = v;
        s += v * v;
    }
    g_zn[p][i] = s;
}

__global__ void k_kuu2() {
    __shared__ float zn[M2];
    int p = blockIdx.y, rc = blockIdx.x, t = threadIdx.x;
    float myz[Dd];
#pragma unroll
    for (int d = 0; d < Dd; d++) myz[d] = g_Zs[p][t][d];
    zn[t] = g_zn[p][t];
    __syncthreads();
    float sf2 = g_sf2[p / Oo];
#pragma unroll 2
    for (int e = 0; e < 16; e++) {
        int row = rc * 16 + e;
        float dot = 0.0f;
#pragma unroll
        for (int d = 0; d < Dd; d++) dot += g_Zs[p][row][d] * myz[d];
        float d2 = fmaxf(zn[row] + zn[t] - 2.0f * dot, 0.0f);
        g_kuu2[p][row][t] = sf2 * __expf(-0.5f * d2);
    }
}

__global__ void k_kx() {
    __shared__ float zs[M2][Dd + 1];
    __shared__ float zn[M2];
    int p = blockIdx.y, b0 = blockIdx.x * 128, t = threadIdx.x;
    int h = p / Oo;
    for (int e = t; e < M2 * Dd; e += 256) {
        int i = e >> 4, d = e & 15;
        zs[i][d] = g_Zs[p][i][d];
    }
    zn[t] = g_zn[p][t];
    __syncthreads();
    int bl = t & 127, half = t >> 7;
    float xr[Dd];
#pragma unroll
    for (int d = 0; d < Dd; d++) xr[d] = g_Xs[h][b0 + bl][d];
    float xnn = g_xn[h][b0 + bl];
    float sf2 = g_sf2[h];
    for (int ii = 0; ii < 128; ii++) {
        int i = half * 128 + ii;
        float dot = 0.0f;
#pragma unroll
        for (int d = 0; d < Dd; d++) dot += zs[i][d] * xr[d];
        float d2 = fmaxf(zn[i] + xnn - 2.0f * dot, 0.0f);
        g_kx[p][i][b0 + bl] = sf2 * __expf(-0.5f * d2);
    }
}

// ---------------- stage A ----------------
// dyn smem: Ls X1 X2 (3*16512) + dinv + yv + mbuf (3*128) = 49920 floats = 199680 B
__global__ void k_stageA(const float* __restrict__ m_old, const float* __restrict__ L_old,
                         const float* __restrict__ u_mean, const float* __restrict__ u_tril_vec) {
    extern __shared__ float sm[];
    float* Ls   = sm;
    float* X1   = sm + 16512;
    float* X2   = sm + 33024;
    float* dinv = sm + 49536;
    float* yv   = sm + 49664;
    float* mbuf = sm + 49792;
    int p = blockIdx.x, o = p % Oo, t = threadIdx.x;
    int tx = t & 15, ty = t >> 4;

    for (int e = t; e < Mm * Mm; e += 256) {
        int i = e >> 7, j = e & 127;
        float v = g_kuu2[p][i][j];
        if (i == j) v += JIT;
        Ls[i * LDA + j] = v;
    }
    __syncthreads();

    chol128(Ls, dinv, t);

    // X1 = Linv*kuf (t<128), X2 = Linv*L_old (t>=128) — per-column serial solve
    {
        int c = t & 127;
        bool isX1 = (t < 128);
        float* X = isX1 ? X1 : X2;
        for (int i = 0; i < Mm; i++) {
            float r = isX1 ? g_kuu2[p][i][Mm + c] : L_old[(o * Mm + i) * Mm + c];
            float s0 = 0, s1 = 0, s2 = 0, s3 = 0;
            int k = 0;
            for (; k + 3 < i; k += 4) {
                s0 += Ls[i * LDA + k]     * X[(k) * LDA + c];
                s1 += Ls[i * LDA + k + 1] * X[(k + 1) * LDA + c];
                s2 += Ls[i * LDA + k + 2] * X[(k + 2) * LDA + c];
                s3 += Ls[i * LDA + k + 3] * X[(k + 3) * LDA + c];
            }
            for (; k < i; k++) s0 += Ls[i * LDA + k] * X[k * LDA + c];
            X[i * LDA + c] = (r - ((s0 + s1) + (s2 + s3))) * dinv[i];
        }
    }
    __syncthreads();

    // persist X1
    for (int e = t; e < Mm * Mm; e += 256) {
        int i = e >> 7, c = e & 127;
        g_X1[p][i][c] = X1[i * LDA + c];
    }

    // trtri in place: Ls -> W11
    trtri128(Ls, dinv, t);

    // persist W11 (row-major) and Wt TL (transposed)
    for (int e = t; e < Mm * Mm; e += 256) {
        int i = e >> 7, k = e & 127;
        g_W11[p][i][k] = (k <= i) ? Ls[i * LDA + k] : 0.0f;
    }
    for (int e = t; e < Mm * Mm; e += 256) {
        int k = e >> 7, i = e & 127;
        g_Wt[p][k][i] = (i >= k) ? Ls[i * LDA + k] : 0.0f;
    }

    // yv = W11 @ m_old (sync-free)
    if (t < 128) mbuf[t] = m_old[o * Mm + t];
    __syncthreads();
    if (t < 128) {
        float s = 0.0f;
        for (int k = 0; k <= t; k++) s += Ls[t * LDA + k] * mbuf[k];
        yv[t] = s;
        g_vm[p][t] = s;
    }
    __syncthreads();

    // m_joint
    if (t < 128) {
        float s = 0.0f;
        for (int i = 0; i < Mm; i++) s += X1[i * LDA + t] * yv[i];
        g_mj[p][t] = mbuf[t];
        g_mj[p][Mm + t] = s + u_mean[o * Mm + t];
    }
    __syncthreads();

    // AtX[j][k] = sum_i X2[i][j]*X1[i][k] -> overwrite Ls
    {
        float c[8][8];
#pragma unroll
        for (int m = 0; m < 8; m++)
#pragma unroll
            for (int n = 0; n < 8; n++) c[m][n] = 0.0f;
        for (int i = 0; i < Mm; i++) {
            float a[8], b[8];
#pragma unroll
            for (int m = 0; m < 8; m++) a[m] = X2[i * LDA + ty + 16 * m];
#pragma unroll
            for (int n = 0; n < 8; n++) b[n] = X1[i * LDA + tx + 16 * n];
#pragma unroll
            for (int m = 0; m < 8; m++)
#pragma unroll
                for (int n = 0; n < 8; n++) c[m][n] += a[m] * b[n];
        }
        __syncthreads();
#pragma unroll
        for (int m = 0; m < 8; m++)
#pragma unroll
            for (int n = 0; n < 8; n++) Ls[(ty + 16 * m) * LDA + tx + 16 * n] = c[m][n];
    }

    // schur = kuu_new + jit I - X1^T X1
    {
        float c[8][8];
#pragma unroll
        for (int m = 0; m < 8; m++)
#pragma unroll
            for (int n = 0; n < 8; n++) c[m][n] = 0.0f;
        for (int k = 0; k < Mm; k++) {
            float a[8], b[8];
#pragma unroll
            for (int m = 0; m < 8; m++) a[m] = X1[k * LDA + ty + 16 * m];
#pragma unroll
            for (int n = 0; n < 8; n++) b[n] = X1[k * LDA + tx + 16 * n];
#pragma unroll
            for (int m = 0; m < 8; m++)
#pragma unroll
                for (int n = 0; n < 8; n++) c[m][n] += a[m] * b[n];
        }
#pragma unroll
        for (int m = 0; m < 8; m++)
#pragma unroll
            for (int n = 0; n < 8; n++) {
                int i = ty + 16 * m, j = tx + 16 * n;
                float v = g_kuu2[p][Mm + i][Mm + j] - c[m][n];
                if (i == j) v += JIT;
                g_schur[p][i][j] = v;
            }
    }
    __syncthreads();

    // reload: X1 <- L_old, X2 <- dense(u_tril)
    for (int e = t; e < Mm * Mm; e += 256) {
        int i = e >> 7, j = e & 127;
        X1[i * LDA + j] = L_old[(o * Mm + i) * Mm + j];
        X2[i * LDA + j] = (j <= i) ? u_tril_vec[o * 8256 + (i * (i + 1)) / 2 + j] : 0.0f;
    }
    __syncthreads();

    // cov TL
    {
        float c[8][8];
#pragma unroll
        for (int m = 0; m < 8; m++)
#pragma unroll
            for (int n = 0; n < 8; n++) c[m][n] = 0.0f;
        for (int k = 0; k < Mm; k++) {
            float a[8], b[8];
#pragma unroll
            for (int m = 0; m < 8; m++) a[m] = X1[(ty + 16 * m) * LDA + k];
#pragma unroll
            for (int n = 0; n < 8; n++) b[n] = X1[(tx + 16 * n) * LDA + k];
#pragma unroll
            for (int m = 0; m < 8; m++)
#pragma unroll
                for (int n = 0; n < 8; n++) c[m][n] += a[m] * b[n];
        }
#pragma unroll
        for (int m = 0; m < 8; m++)
#pragma unroll
            for (int n = 0; n < 8; n++) g_cov[p][ty + 16 * m][tx + 16 * n] = c[m][n];
    }
    // cov BL[Mm+j][i] = sum_k L_old[i][k] AtX[k][j]
    {
        float c[8][8];
#pragma unroll
        for (int m = 0; m < 8; m++)
#pragma unroll
            for (int n = 0; n < 8; n++) c[m][n] = 0.0f;
        for (int k = 0; k < Mm; k++) {
            float a[8], b[8];
#pragma unroll
            for (int m = 0; m < 8; m++) a[m] = Ls[k * LDA + ty + 16 * m];
#pragma unroll
            for (int n = 0; n < 8; n++) b[n] = X1[(tx + 16 * n) * LDA + k];
#pragma unroll
            for (int m = 0; m < 8; m++)
#pragma unroll
                for (int n = 0; n < 8; n++) c[m][n] += a[m] * b[n];
        }
#pragma unroll
        for (int m = 0; m < 8; m++)
#pragma unroll
            for (int n = 0; n < 8; n++) g_cov[p][Mm + ty + 16 * m][tx + 16 * n] = c[m][n];
    }
    // cov BR
    {
        float c[8][8];
#pragma unroll
        for (int m = 0; m < 8; m++)
#pragma unroll
            for (int n = 0; n < 8; n++) c[m][n] = 0.0f;
        for (int k = 0; k < Mm; k++) {
            float a[8], b[8];
#pragma unroll
            for (int m = 0; m < 8; m++) a[m] = X2[(ty + 16 * m) * LDA + k];
#pragma unroll
            for (int n = 0; n < 8; n++) b[n] = X2[(tx + 16 * n) * LDA + k];
#pragma unroll
            for (int m = 0; m < 8; m++)
#pragma unroll
                for (int n = 0; n < 8; n++) c[m][n] += a[m] * b[n];
        }
        for (int k = 0; k < Mm; k++) {
            float a[8], b[8];
#pragma unroll
            for (int m = 0; m < 8; m++) a[m] = Ls[k * LDA + ty + 16 * m];
#pragma unroll
            for (int n = 0; n < 8; n++) b[n] = Ls[k * LDA + tx + 16 * n];
#pragma unroll
            for (int m = 0; m < 8; m++)
#pragma unroll
                for (int n = 0; n < 8; n++) c[m][n] += a[m] * b[n];
        }
#pragma unroll
        for (int m = 0; m < 8; m++)
#pragma unroll
            for (int n = 0; n < 8; n++) g_cov[p][Mm + ty + 16 * m][Mm + tx + 16 * n] = c[m][n];
    }
}

// ---------------- B1n: chol(schur) + trtri -> W22 (+Wt BR) ----------------
// dyn smem: 16512 + 128 = 16640 floats = 66560 B
__global__ void k_stageB1n() {
    extern __shared__ float sm[];
    float* S = sm;
    float* dinv = sm + 16512;
    int p = blockIdx.x, t = threadIdx.x;

    for (int e = t; e < Mm * Mm; e += 256) {
        int i = e >> 7, j = e & 127;
        S[i * LDA + j] = g_schur[p][i][j];
    }
    __syncthreads();
    chol128(S, dinv, t);
    trtri128(S, dinv, t);
    // Wt BR: Wt[Mm+k][Mm+i] = W22[i][k]
    for (int e = t; e < Mm * Mm; e += 256) {
        int k = e >> 7, i = e & 127;
        g_Wt[p][Mm + k][Mm + i] = (i >= k) ? S[i * LDA + k] : 0.0f;
    }
    // row-major W22
    for (int e = t; e < Mm * Mm; e += 256) {
        int i = e >> 7, k = e & 127;
        g_W22[p][i][k] = (k <= i) ? S[i * LDA + k] : 0.0f;
    }
}

// ---------------- w21: W21 = -W22 @ (X1^T @ W11) ----------------
// dyn smem: T1 16512 + At 2048 + Bt 2048 = 20608 floats = 82432 B
__global__ __launch_bounds__(256) void k_w21() {
    extern __shared__ float sm[];
    float* T1 = sm;                    // [128][129]
    float (*At)[128] = (float (*)[128])(sm + 16512);
    float (*Bt)[128] = (float (*)[128])(sm + 18560);
    int p = blockIdx.x, t = threadIdx.x;
    int tx = t & 15, ty = t >> 4;

    // phase 1: T1[c][j] = sum_i X1[i][c] * W11[i][j]
    {
        float acc[8][8];
#pragma unroll
        for (int m = 0; m < 8; m++)
#pragma unroll
            for (int n = 0; n < 8; n++) acc[m][n] = 0.0f;
        for (int kc = 0; kc < Mm; kc += 16) {
            for (int e = t; e < 2048; e += 256) {
                int kk = e >> 7, q = e & 127;
                At[kk][q] = g_X1[p][kc + kk][q];
                Bt[kk][q] = g_W11[p][kc + kk][q];
            }
            __syncthreads();
#pragma unroll
            for (int kk = 0; kk < 16; kk++) {
                float a[8], b[8];
#pragma unroll
                for (int m = 0; m < 8; m++) a[m] = At[kk][ty + 16 * m];
#pragma unroll
                for (int n = 0; n < 8; n++) b[n] = Bt[kk][tx + 16 * n];
#pragma unroll
                for (int m = 0; m < 8; m++)
#pragma unroll
                    for (int n = 0; n < 8; n++) acc[m][n] += a[m] * b[n];
            }
            __syncthreads();
        }
#pragma unroll
        for (int m = 0; m < 8; m++)
#pragma unroll
            for (int n = 0; n < 8; n++) T1[(ty + 16 * m) * LDA + tx + 16 * n] = acc[m][n];
    }
    __syncthreads();

    // phase 2: W21[r][j] = -sum_c W22[r][c] T1[c][j];  A staged from Wt BR (coalesced)
    {
        float acc[8][8];
#pragma unroll
        for (int m = 0; m < 8; m++)
#pragma unroll
            for (int n = 0; n < 8; n++) acc[m][n] = 0.0f;
        for (int kc = 0; kc < Mm; kc += 16) {
            for (int e = t; e < 2048; e += 256) {
                int kk = e >> 7, q = e & 127;
                At[kk][q] = g_Wt[p][Mm + kc + kk][Mm + q];
            }
            __syncthreads();
#pragma unroll
            for (int kk = 0; kk < 16; kk++) {
                float a[8], b[8];
#pragma unroll
                for (int m = 0; m < 8; m++) a[m] = At[kk][ty + 16 * m];
#pragma unroll
                for (int n = 0; n < 8; n++) b[n] = T1[(kc + kk) * LDA + tx + 16 * n];
#pragma unroll
                for (int m = 0; m < 8; m++)
#pragma unroll
                    for (int n = 0; n < 8; n++) acc[m][n] -= a[m] * b[n];
            }
            __syncthreads();
        }
#pragma unroll
        for (int m = 0; m < 8; m++)
#pragma unroll
            for (int n = 0; n < 8; n++) g_W21[p][ty + 16 * m][tx + 16 * n] = acc[m][n];
    }
}

// ---------------- post: Wt TR transpose + vm2 ----------------
__global__ void k_post() {
    __shared__ float smT[32][33];
    int p = blockIdx.x, t = threadIdx.x;
    int lr = t >> 5, lc = t & 31;
    for (int tile = 0; tile < 16; tile++) {
        int r0 = (tile >> 2) * 32, j0 = (tile & 3) * 32;
        for (int rr = lr; rr < 32; rr += 8) smT[rr][lc] = g_W21[p][r0 + rr][j0 + lc];
        __syncthreads();
        for (int jj = lr; jj < 32; jj += 8) g_Wt[p][j0 + jj][Mm + r0 + lc] = smT[lc][jj];
        __syncthreads();
    }
    if (t < 128) {
        int r = t;
        float s = 0.0f;
        for (int j = 0; j < Mm; j++) s += g_W21[p][r][j] * g_mj[p][j];
        for (int j = 0; j < Mm; j++) s += g_W22[p][r][j] * g_mj[p][Mm + j];
        g_vm[p][Mm + r] = s;
    }
}

// ---------------- B2n: block chol of cov+jit -> L11p, L21p, L22p ----------------
// dyn smem: C 16512 + X 16512 + dinv 128 = 33152 floats = 132608 B
__global__ void k_stageB2n() {
    extern __shared__ float sm[];
    float* C = sm;
    float* X = sm + 16512;
    float* dinv = sm + 33024;
    int p = blockIdx.x, t = threadIdx.x;
    int tx = t & 15, ty = t >> 4;

    for (int e = t; e < Mm * Mm; e += 256) {
        int i = e >> 7, j = e & 127;
        float v = g_cov[p][i][j];
        if (i == j) v += JIT;
        C[i * LDA + j] = v;
    }
    __syncthreads();
    chol128(C, dinv, t);
    for (int e = t; e < Mm * Mm; e += 256) {
        int i = e >> 7, k = e & 127;
        g_L11p[p][i][k] = (k <= i) ? C[i * LDA + k] : 0.0f;
    }
    // load BL into X
    for (int e = t; e < Mm * Mm; e += 256) {
        int r = e >> 7, j = e & 127;
        X[r * LDA + j] = g_cov[p][Mm + r][j];
    }
    __syncthreads();
    // trsm rows: X[r][:] <- L21'[r][:]
    if (t < 128) {
        int r = t;
        for (int j = 0; j < Mm; j++) {
            float s0 = 0, s1 = 0, s2 = 0, s3 = 0;
            int k = 0;
            for (; k + 3 < j; k += 4) {
                s0 += X[r * LDA + k]     * C[j * LDA + k];
                s1 += X[r * LDA + k + 1] * C[j * LDA + k + 1];
                s2 += X[r * LDA + k + 2] * C[j * LDA + k + 2];
                s3 += X[r * LDA + k + 3] * C[j * LDA + k + 3];
            }
            for (; k < j; k++) s0 += X[r * LDA + k] * C[j * LDA + k];
            X[r * LDA + j] = (X[r * LDA + j] - ((s0 + s1) + (s2 + s3))) * dinv[j];
        }
    }
    __syncthreads();
    for (int e = t; e < Mm * Mm; e += 256) {
        int r = e >> 7, j = e & 127;
        g_L21p[p][r][j] = X[r * LDA + j];
    }
    // schur2 into C
    {
        float c[8][8];
#pragma unroll
        for (int m = 0; m < 8; m++)
#pragma unroll
            for (int n = 0; n < 8; n++) c[m][n] = 0.0f;
        for (int k = 0; k < Mm; k++) {
            float a[8], b[8];
#pragma unroll
            for (int m = 0; m < 8; m++) a[m] = X[(ty + 16 * m) * LDA + k];
#pragma unroll
            for (int n = 0; n < 8; n++) b[n] = X[(tx + 16 * n) * LDA + k];
#pragma unroll
            for (int m = 0; m < 8; m++)
#pragma unroll
                for (int n = 0; n < 8; n++) c[m][n] += a[m] * b[n];
        }
        __syncthreads();
#pragma unroll
        for (int m = 0; m < 8; m++)
#pragma unroll
            for (int n = 0; n < 8; n++) {
                int i = ty + 16 * m, j = tx + 16 * n;
                float v = g_cov[p][Mm + i][Mm + j] - c[m][n];
                if (i == j) v += JIT;
                C[i * LDA + j] = v;
            }
    }
    __syncthreads();
    chol128(C, dinv, t);
    for (int e = t; e < Mm * Mm; e += 256) {
        int i = e >> 7, k = e & 127;
        g_L22p[p][i][k] = (k <= i) ? C[i * LDA + k] : 0.0f;
    }
}

// ---------------- k_R: R blocks. grid (3, HO) ----------------
__global__ __launch_bounds__(256) void k_R() {
    __shared__ float As[16][128];
    __shared__ float Bs[16][128];
    int v = blockIdx.x, p = blockIdx.y;
    int t = threadIdx.x, tx = t & 15, ty = t >> 4;
    float acc[8][8];
#pragma unroll
    for (int m = 0; m < 8; m++)
#pragma unroll
        for (int n = 0; n < 8; n++) acc[m][n] = 0.0f;

    int kTot = (v == 1) ? M2 : Mm;
    for (int kc = 0; kc < kTot; kc += 16) {
        for (int e = t; e < 2048; e += 256) {
            int kk = e >> 7, q = e & 127;
            int kg = kc + kk;
            float av, bv;
            if (v == 0) { av = g_Wt[p][kg][q];            bv = g_L11p[p][kg][q]; }
            else if (v == 1) {
                av = g_Wt[p][kg][Mm + q];
                bv = (kg < Mm) ? g_L11p[p][kg][q] : g_L21p[p][kg - Mm][q];
            }
            else { av = g_Wt[p][Mm + kg][Mm + q];         bv = g_L22p[p][kg][q]; }
            As[kk][q] = av;
            Bs[kk][q] = bv;
        }
        __syncthreads();
#pragma unroll
        for (int kk = 0; kk < 16; kk++) {
            float4 a0 = *(const float4*)&As[kk][ty * 8];
            float4 a1 = *(const float4*)&As[kk][ty * 8 + 4];
            float4 b0 = *(const float4*)&Bs[kk][tx * 8];
            float4 b1 = *(const float4*)&Bs[kk][tx * 8 + 4];
            float am[8] = { a0.x, a0.y, a0.z, a0.w, a1.x, a1.y, a1.z, a1.w };
            float bn[8] = { b0.x, b0.y, b0.z, b0.w, b1.x, b1.y, b1.z, b1.w };
#pragma unroll
            for (int m = 0; m < 8; m++)
#pragma unroll
                for (int n = 0; n < 8; n++) acc[m][n] += am[m] * bn[n];
        }
        __syncthreads();
    }
    int r0 = (v == 0) ? 0 : Mm;
    int c0 = (v == 2) ? Mm : 0;
#pragma unroll
    for (int m = 0; m < 8; m++) {
        *(float4*)&g_R[p][r0 + ty * 8 + m][c0 + tx * 8]     = make_float4(acc[m][0], acc[m][1], acc[m][2], acc[m][3]);
        *(float4*)&g_R[p][r0 + ty * 8 + m][c0 + tx * 8 + 4] = make_float4(acc[m][4], acc[m][5], acc[m][6], acc[m][7]);
    }
}

// ---------------- gemmA: a = Linv @ kx (FFMA2) + d1/mu partials ----------------
__global__ __launch_bounds__(256) void k_gemmA() {
    __shared__ float As[16][128];
    __shared__ float Bs[16][128];
    __shared__ float vs[128];
    __shared__ float red[16][128];
    int p = blockIdx.z;
    int i0 = blockIdx.y * 128, b0 = blockIdx.x * 128;
    int t = threadIdx.x, tx = t % 16, ty = t / 16;
    if (t < 128) vs[t] = g_vm[p][i0 + t];
    unsigned long long acc[8][4];
#pragma unroll
    for (int m = 0; m < 8; m++)
#pragma unroll
        for (int n = 0; n < 4; n++) acc[m][n] = 0ULL;

    int kmax = i0 + 128;
    for (int kc = 0; kc < kmax; kc += 16) {
#pragma unroll
        for (int e = 0; e < 2; e++) {
            int q = t + e * 256;
            int kk = q >> 5, c4 = q & 31;
            *(float4*)&As[kk][c4 * 4] = *(const float4*)&g_Wt[p][kc + kk][i0 + c4 * 4];
            *(float4*)&Bs[kk][c4 * 4] = *(const float4*)&g_kx[p][kc + kk][b0 + c4 * 4];
        }
        __syncthreads();
#pragma unroll
        for (int kk = 0; kk < 16; kk++) {
            float4 a0 = *(const float4*)&As[kk][ty * 8];
            float4 a1 = *(const float4*)&As[kk][ty * 8 + 4];
            float4 q0 = *(const float4*)&Bs[kk][tx * 8];
            float4 q1 = *(const float4*)&Bs[kk][tx * 8 + 4];
            unsigned long long bp[4] = { pk2(q0.x, q0.y), pk2(q0.z, q0.w), pk2(q1.x, q1.y), pk2(q1.z, q1.w) };
            float am[8] = { a0.x, a0.y, a0.z, a0.w, a1.x, a1.y, a1.z, a1.w };
#pragma unroll
            for (int m = 0; m < 8; m++) {
                unsigned long long ad = pk2(am[m], am[m]);
#pragma unroll
                for (int n = 0; n < 4; n++) acc[m][n] = ffma2(ad, bp[n], acc[m][n]);
            }
        }
        __syncthreads();
    }
    float av[8][8];
#pragma unroll
    for (int m = 0; m < 8; m++) {
#pragma unroll
        for (int n = 0; n < 4; n++) {
            float2 v = upk2(acc[m][n]);
            av[m][n * 2] = v.x; av[m][n * 2 + 1] = v.y;
        }
        *(float4*)&g_a[p][i0 + ty * 8 + m][b0 + tx * 8]     = make_float4(av[m][0], av[m][1], av[m][2], av[m][3]);
        *(float4*)&g_a[p][i0 + ty * 8 + m][b0 + tx * 8 + 4] = make_float4(av[m][4], av[m][5], av[m][6], av[m][7]);
    }
#pragma unroll
    for (int n = 0; n < 8; n++) {
        float s = 0.0f;
#pragma unroll
        for (int m = 0; m < 8; m++) s += av[m][n] * av[m][n];
        red[ty][tx * 8 + n] = s;
    }
    __syncthreads();
    if (t < 128) {
        float s = 0.0f;
#pragma unroll
        for (int y = 0; y < 16; y++) s += red[y][t];
        g_d1p[blockIdx.y][p][b0 + t] = s;
    }
    __syncthreads();
#pragma unroll
    for (int n = 0; n < 8; n++) {
        float s = 0.0f;
#pragma unroll
        for (int m = 0; m < 8; m++) s += vs[ty * 8 + m] * av[m][n];
        red[ty][tx * 8 + n] = s;
    }
    __syncthreads();
    if (t < 128) {
        float s = 0.0f;
#pragma unroll
        for (int y = 0; y < 16; y++) s += red[y][t];
        g_mup[blockIdx.y][p][b0 + t] = s;
    }
}

// ---------------- gemmH: h = R^T @ a, d2 partials (FFMA2) ----------------
__global__ __launch_bounds__(256) void k_gemmH() {
    __shared__ float As[16][128];
    __shared__ float Bs[16][128];
    __shared__ float red[16][128];
    int p = blockIdx.z;
    int j0 = blockIdx.y * 128, b0 = blockIdx.x * 128;
    int t = threadIdx.x, tx = t % 16, ty = t / 16;
    unsigned long long acc[8][4];
#pragma unroll
    for (int m = 0; m < 8; m++)
#pragma unroll
        for (int n = 0; n < 4; n++) acc[m][n] = 0ULL;

    for (int kc = j0; kc < M2; kc += 16) {
#pragma unroll
        for (int e = 0; e < 2; e++) {
            int q = t + e * 256;
            int kk = q >> 5, c4 = q & 31;
            *(float4*)&As[kk][c4 * 4] = *(const float4*)&g_R[p][kc + kk][j0 + c4 * 4];
            *(float4*)&Bs[kk][c4 * 4] = *(const float4*)&g_a[p][kc + kk][b0 + c4 * 4];
        }
        __syncthreads();
#pragma unroll
        for (int kk = 0; kk < 16; kk++) {
            float4 a0 = *(const float4*)&As[kk][ty * 8];
            float4 a1 = *(const float4*)&As[kk][ty * 8 + 4];
            float4 q0 = *(const float4*)&Bs[kk][tx * 8];
            float4 q1 = *(const float4*)&Bs[kk][tx * 8 + 4];
            unsigned long long bp[4] = { pk2(q0.x, q0.y), pk2(q0.z, q0.w), pk2(q1.x, q1.y), pk2(q1.z, q1.w) };
            float am[8] = { a0.x, a0.y, a0.z, a0.w, a1.x, a1.y, a1.z, a1.w };
#pragma unroll
            for (int m = 0; m < 8; m++) {
                unsigned long long ad = pk2(am[m], am[m]);
#pragma unroll
                for (int n = 0; n < 4; n++) acc[m][n] = ffma2(ad, bp[n], acc[m][n]);
            }
        }
        __syncthreads();
    }
#pragma unroll
    for (int n = 0; n < 8; n++) {
        float s = 0.0f;
#pragma unroll
        for (int m = 0; m < 8; m++) {
            float2 v = upk2(acc[m][n / 2]);
            float h = (n & 1) ? v.y : v.x;
            s += h * h;
        }
        red[ty][tx * 8 + n] = s;
    }
    __syncthreads();
    if (t < 128) {
        float s = 0.0f;
#pragma unroll
        for (int y = 0; y < 16; y++) s += red[y][t];
        g_d2p[blockIdx.y][p][b0 + t] = s;
    }
}

// ---------------- final ----------------
__global__ void k_final(float* __restrict__ out) {
    int idx = blockIdx.x * 256 + threadIdx.x;
    if (idx >= HOB) return;
    int p = idx / Bb, b = idx % Bb;
    out[idx] = g_mup[0][p][b] + g_mup[1][p][b];
    out[HOB + idx] = g_sf2[p / Oo] - (g_d1p[0][p][b] + g_d1p[1][p][b]) + (g_d2p[0][p][b] + g_d2p[1][p][b]);
}

extern "C" void kernel_launch(void* const* d_in, const int* in_sizes, int n_in,
                              void* d_out, int out_size) {
    const float* x          = (const float*)d_in[0];
    const float* z          = (const float*)d_in[1];
    const float* u_mean     = (const float*)d_in[2];
    const float* u_tril_vec = (const float*)d_in[3];
    const float* m_old      = (const float*)d_in[4];
    const float* L_old      = (const float*)d_in[5];
    const float* z_old      = (const float*)d_in[6];
    const float* theta      = (const float*)d_in[7];
    float* out = (float*)d_out;

    cudaFuncSetAttribute(k_stageA,   cudaFuncAttributeMaxDynamicSharedMemorySize, 199680);
    cudaFuncSetAttribute(k_stageB1n, cudaFuncAttributeMaxDynamicSharedMemorySize, 66560);
    cudaFuncSetAttribute(k_w21,      cudaFuncAttributeMaxDynamicSharedMemorySize, 82432);
    cudaFuncSetAttribute(k_stageB2n, cudaFuncAttributeMaxDynamicSharedMemorySize, 132608);

    k_prep_theta<<<1, 128>>>(theta);            // 0
    k_prep_z<<<HO, 256>>>(z, z_old);            // 1
    k_kuu2<<<dim3(16, HO), 256>>>();            // 2
    k_stageA<<<HO, 256, 199680>>>(m_old, L_old, u_mean, u_tril_vec);  // 3 (profiled)
    k_stageB1n<<<HO, 256, 66560>>>();           // 4
    k_w21<<<HO, 256, 82432>>>();                // 5
    k_post<<<HO, 256>>>();                      // 6
    k_stageB2n<<<HO, 256, 132608>>>();          // 7
    k_R<<<dim3(3, HO), 256>>>();                // 8
    k_prep_x<<<16, 256>>>(x);                   // 9
    k_kx<<<dim3(8, HO), 256>>>();               // 10
    k_gemmA<<<dim3(8, 2, HO), 256>>>();         // 11
    k_gemmH<<<dim3(8, 2, HO), 256>>>();         // 12
    k_final<<<512, 256>>>(out);                 // 13
}

// round 7
// speedup vs baseline: 2.1012x; 1.1249x over previous
#include <cuda_runtime.h>

#define Hh 4
#define Oo 32
#define Mm 128
#define M2 256
#define Dd 16
#define Bb 1024
#define HO 128
#define HOB (HO*Bb)
#define JIT 1e-4f
#define LDA 129

// ---------------- f32x2 helpers ----------------
__device__ __forceinline__ unsigned long long pk2(float lo, float hi) {
    unsigned long long r;
    asm("mov.b64 %0, {%1, %2};" : "=l"(r) : "f"(lo), "f"(hi));
    return r;
}
__device__ __forceinline__ float2 upk2(unsigned long long v) {
    float2 r;
    asm("mov.b64 {%0, %1}, %2;" : "=f"(r.x), "=f"(r.y) : "l"(v));
    return r;
}
__device__ __forceinline__ unsigned long long ffma2(unsigned long long a, unsigned long long b, unsigned long long c) {
    unsigned long long d;
    asm("fma.rn.f32x2 %0, %1, %2, %3;" : "=l"(d) : "l"(a), "l"(b), "l"(c));
    return d;
}

// ---------------- device scratch ----------------
__device__ float g_sf2[Hh];
__device__ float g_invls[Hh][Dd];
__device__ float g_Xs[Hh][Bb][Dd];
__device__ float g_xn[Hh][Bb];
__device__ float g_Zs[HO][M2][Dd];
__device__ float g_zn[HO][M2];
__device__ float g_kuu2[HO][M2][M2];
__device__ float g_cov[HO][M2][M2];
__device__ float g_Wt[HO][M2][M2];     // Wt[k][i] = Linv256[i][k] (TL/TR/BR used)
__device__ float g_R[HO][M2][M2];
__device__ float g_vm[HO][M2];
__device__ float g_mj[HO][M2];
__device__ float g_kx[HO][M2][Bb];
__device__ float g_a[HO][M2][Bb];
__device__ float g_X1[HO][Mm][Mm];
__device__ float g_W11[HO][Mm][Mm];
__device__ float g_schur[HO][Mm][Mm];
__device__ float g_L11p[HO][Mm][Mm];
__device__ float g_L21p[HO][Mm][Mm];
__device__ float g_L22p[HO][Mm][Mm];
__device__ float g_d1p[2][HO][Bb];
__device__ float g_d2p[2][HO][Bb];
__device__ float g_mup[2][HO][Bb];

// ---------------- serial building blocks (dense 128, LD=129) ----------------
__device__ void chol128(float* Ls, float* dinv, int t) {
    for (int j = 0; j < Mm; j++) {
        if (t < 32) {
            float s = 0.0f;
            for (int k = t; k < j; k += 32) { float v = Ls[j * LDA + k]; s += v * v; }
            for (int w = 16; w; w >>= 1) s += __shfl_down_sync(0xffffffffu, s, w);
            if (t == 0) {
                float d = sqrtf(Ls[j * LDA + j] - s);
                Ls[j * LDA + j] = d;
                dinv[j] = 1.0f / d;
            }
        }
        __syncthreads();
        int i = j + 1 + t;
        if (i < Mm) {
            float s0 = 0, s1 = 0, s2 = 0, s3 = 0;
            int k = 0;
            for (; k + 3 < j; k += 4) {
                s0 += Ls[i * LDA + k]     * Ls[j * LDA + k];
                s1 += Ls[i * LDA + k + 1] * Ls[j * LDA + k + 1];
                s2 += Ls[i * LDA + k + 2] * Ls[j * LDA + k + 2];
                s3 += Ls[i * LDA + k + 3] * Ls[j * LDA + k + 3];
            }
            for (; k < j; k++) s0 += Ls[i * LDA + k] * Ls[j * LDA + k];
            Ls[i * LDA + j] = (Ls[i * LDA + j] - ((s0 + s1) + (s2 + s3))) * dinv[j];
        }
        __syncthreads();
    }
}

// blocked in-place trtri of 128 lower-tri: two 64-blocks in parallel + GEMM corner.
// On exit: full lower = Linv, full upper (incl. in-block uppers and TR) = 0.
__device__ void trtri128_blocked(float* Ls, float* dinv, int t) {
    // simultaneous in-place trtri of A (0,0) and C (64,64)
    if (t == 0) Ls[0] = dinv[0];
    if (t == 1) Ls[64 * LDA + 64] = dinv[64];
    __syncthreads();
    for (int i = 1; i < 64; i++) {
        float v = 0.0f;
        bool actA = (t < i);
        int u = t - 128;
        bool actB = (u >= 0 && u < i);
        if (actA) {
            float s0 = 0, s1 = 0, s2 = 0, s3 = 0;
            int k = t;
            for (; k + 3 < i; k += 4) {
                s0 += Ls[i * LDA + k]     * Ls[(k)     * LDA + t];
                s1 += Ls[i * LDA + k + 1] * Ls[(k + 1) * LDA + t];
                s2 += Ls[i * LDA + k + 2] * Ls[(k + 2) * LDA + t];
                s3 += Ls[i * LDA + k + 3] * Ls[(k + 3) * LDA + t];
            }
            for (; k < i; k++) s0 += Ls[i * LDA + k] * Ls[k * LDA + t];
            v = -dinv[i] * ((s0 + s1) + (s2 + s3));
        } else if (actB) {
            const int O = 64 * LDA + 64;
            float s0 = 0, s1 = 0, s2 = 0, s3 = 0;
            int k = u;
            for (; k + 3 < i; k += 4) {
                s0 += Ls[O + i * LDA + k]     * Ls[O + (k)     * LDA + u];
                s1 += Ls[O + i * LDA + k + 1] * Ls[O + (k + 1) * LDA + u];
                s2 += Ls[O + i * LDA + k + 2] * Ls[O + (k + 2) * LDA + u];
                s3 += Ls[O + i * LDA + k + 3] * Ls[O + (k + 3) * LDA + u];
            }
            for (; k < i; k++) s0 += Ls[O + i * LDA + k] * Ls[O + k * LDA + u];
            v = -dinv[64 + i] * ((s0 + s1) + (s2 + s3));
        }
        __syncthreads();
        if (actA) Ls[i * LDA + t] = v;
        if (actB) Ls[(64 + i) * LDA + 64 + u] = v;
        if (t == 0) Ls[i * LDA + i] = dinv[i];
        if (t == 1) Ls[(64 + i) * LDA + 64 + i] = dinv[64 + i];
        __syncthreads();
    }
    // zero in-block uppers + the big TR block
    for (int e = t; e < 64 * 64; e += 256) {
        int r = e >> 6, c = e & 63;
        if (c > r) { Ls[r * LDA + c] = 0.0f; Ls[(64 + r) * LDA + 64 + c] = 0.0f; }
        Ls[r * LDA + 64 + c] = 0.0f;
    }
    __syncthreads();
    // corner: B <- -Cinv @ (Borig @ Ainv)
    int tx = t & 15, ty = t >> 4;
    float T[4][4];
#pragma unroll
    for (int m = 0; m < 4; m++)
#pragma unroll
        for (int n = 0; n < 4; n++) T[m][n] = 0.0f;
    for (int k = 0; k < 64; k++) {
        float a[4], b[4];
#pragma unroll
        for (int m = 0; m < 4; m++) a[m] = Ls[(64 + ty + 16 * m) * LDA + k];
#pragma unroll
        for (int n = 0; n < 4; n++) b[n] = Ls[k * LDA + tx + 16 * n];
#pragma unroll
        for (int m = 0; m < 4; m++)
#pragma unroll
            for (int n = 0; n < 4; n++) T[m][n] += a[m] * b[n];
    }
    __syncthreads();
#pragma unroll
    for (int m = 0; m < 4; m++)
#pragma unroll
        for (int n = 0; n < 4; n++) Ls[(64 + ty + 16 * m) * LDA + tx + 16 * n] = T[m][n];
    __syncthreads();
#pragma unroll
    for (int m = 0; m < 4; m++)
#pragma unroll
        for (int n = 0; n < 4; n++) T[m][n] = 0.0f;
    for (int k = 0; k < 64; k++) {
        float a[4], b[4];
#pragma unroll
        for (int m = 0; m < 4; m++) a[m] = Ls[(64 + ty + 16 * m) * LDA + 64 + k];
#pragma unroll
        for (int n = 0; n < 4; n++) b[n] = Ls[(64 + k) * LDA + tx + 16 * n];
#pragma unroll
        for (int m = 0; m < 4; m++)
#pragma unroll
            for (int n = 0; n < 4; n++) T[m][n] -= a[m] * b[n];
    }
    __syncthreads();
#pragma unroll
    for (int m = 0; m < 4; m++)
#pragma unroll
        for (int n = 0; n < 4; n++) Ls[(64 + ty + 16 * m) * LDA + tx + 16 * n] = T[m][n];
    __syncthreads();
}

// ---------------- prep ----------------
__global__ void k_prep_theta(const float* __restrict__ theta) {
    int t = threadIdx.x;
    if (t < Hh * (Dd + 1)) {
        int h = t / (Dd + 1), c = t % (Dd + 1);
        float v = theta[t];
        if (c == 0) g_sf2[h] = expf(v);
        else        g_invls[h][c - 1] = expf(-v);
    }
}

__global__ void k_prep_x(const float* __restrict__ x) {
    int g = blockIdx.x * blockDim.x + threadIdx.x;
    if (g >= Hh * Bb) return;
    int h = g / Bb, b = g % Bb;
    float s = 0.0f;
#pragma unroll
    for (int d = 0; d < Dd; d++) {
        float v = x[b * Dd + d] * g_invls[h][d];
        g_Xs[h][b][d] = v;
        s += v * v;
    }
    g_xn[h][b] = s;
}

__global__ void k_prep_z(const float* __restrict__ z, const float* __restrict__ z_old) {
    int p = blockIdx.x;
    int h = p / Oo, o = p % Oo;
    int i = threadIdx.x;
    const float* src = (i < Mm) ? &z_old[(o * Mm + i) * Dd] : &z[(o * Mm + (i - Mm)) * Dd];
    float s = 0.0f;
#pragma unroll
    for (int d = 0; d < Dd; d++) {
        float v = src[d] * g_invls[h][d];
        g_Zs[p][i][d] = v;
        s += v * v;
    }
    g_zn[p][i] = s;
}

__global__ void k_kuu2() {
    __shared__ float zn[M2];
    int p = blockIdx.y, rc = blockIdx.x, t = threadIdx.x;
    float myz[Dd];
#pragma unroll
    for (int d = 0; d < Dd; d++) myz[d] = g_Zs[p][t][d];
    zn[t] = g_zn[p][t];
    __syncthreads();
    float sf2 = g_sf2[p / Oo];
#pragma unroll 2
    for (int e = 0; e < 16; e++) {
        int row = rc * 16 + e;
        float dot = 0.0f;
#pragma unroll
        for (int d = 0; d < Dd; d++) dot += g_Zs[p][row][d] * myz[d];
        float d2 = fmaxf(zn[row] + zn[t] - 2.0f * dot, 0.0f);
        g_kuu2[p][row][t] = sf2 * __expf(-0.5f * d2);
    }
}

__global__ void k_kx() {
    __shared__ float zs[M2][Dd + 1];
    __shared__ float zn[M2];
    int p = blockIdx.y, b0 = blockIdx.x * 128, t = threadIdx.x;
    int h = p / Oo;
    for (int e = t; e < M2 * Dd; e += 256) {
        int i = e >> 4, d = e & 15;
        zs[i][d] = g_Zs[p][i][d];
    }
    zn[t] = g_zn[p][t];
    __syncthreads();
    int bl = t & 127, half = t >> 7;
    float xr[Dd];
#pragma unroll
    for (int d = 0; d < Dd; d++) xr[d] = g_Xs[h][b0 + bl][d];
    float xnn = g_xn[h][b0 + bl];
    float sf2 = g_sf2[h];
    for (int ii = 0; ii < 128; ii++) {
        int i = half * 128 + ii;
        float dot = 0.0f;
#pragma unroll
        for (int d = 0; d < Dd; d++) dot += zs[i][d] * xr[d];
        float d2 = fmaxf(zn[i] + xnn - 2.0f * dot, 0.0f);
        g_kx[p][i][b0 + bl] = sf2 * __expf(-0.5f * d2);
    }
}

// ---------------- stage A ----------------
// dyn smem: Ls 16512 | X1 16512 | X2 16512 | stg 2048 | dinv 128 | yv 128 | mbuf 128 = 51968 fl = 207872 B
__global__ __launch_bounds__(256, 1) void k_stageA(
        const float* __restrict__ m_old, const float* __restrict__ L_old,
        const float* __restrict__ u_mean, const float* __restrict__ u_tril_vec) {
    extern __shared__ float sm[];
    float* Ls   = sm;
    float* X1   = sm + 16512;
    float* X2   = sm + 33024;
    float* stg  = sm + 49536;
    float* dinv = sm + 51584;
    float* yv   = sm + 51712;
    float* mbuf = sm + 51840;
    int p = blockIdx.x, o = p % Oo, t = threadIdx.x;
    int tx = t & 15, ty = t >> 4;

    for (int e = t; e < Mm * Mm; e += 256) {
        int i = e >> 7, j = e & 127;
        float v = g_kuu2[p][i][j];
        if (i == j) v += JIT;
        Ls[i * LDA + j] = v;
    }
    __syncthreads();

    chol128(Ls, dinv, t);
    trtri128_blocked(Ls, dinv, t);   // Ls = W11 dense (upper zeros)

    // persist W11 + Wt TL
    for (int e = t; e < Mm * Mm; e += 256) {
        int i = e >> 7, k = e & 127;
        g_W11[p][i][k] = Ls[i * LDA + k];
        g_Wt[p][k][i]  = Ls[i * LDA + k];
    }

    // X1 = W11 @ kuf (GEMM)
    {
        float acc[8][8];
#pragma unroll
        for (int m = 0; m < 8; m++)
#pragma unroll
            for (int n = 0; n < 8; n++) acc[m][n] = 0.0f;
        for (int kc = 0; kc < Mm; kc += 16) {
            for (int e = t; e < 2048; e += 256) {
                int kk = e >> 7, c = e & 127;
                stg[kk * 128 + c] = g_kuu2[p][kc + kk][Mm + c];
            }
            __syncthreads();
#pragma unroll
            for (int kk = 0; kk < 16; kk++) {
                float a[8], b[8];
#pragma unroll
                for (int m = 0; m < 8; m++) a[m] = Ls[(ty + 16 * m) * LDA + kc + kk];
#pragma unroll
                for (int n = 0; n < 8; n++) b[n] = stg[kk * 128 + tx + 16 * n];
#pragma unroll
                for (int m = 0; m < 8; m++)
#pragma unroll
                    for (int n = 0; n < 8; n++) acc[m][n] += a[m] * b[n];
            }
            __syncthreads();
        }
#pragma unroll
        for (int m = 0; m < 8; m++)
#pragma unroll
            for (int n = 0; n < 8; n++) {
                X1[(ty + 16 * m) * LDA + tx + 16 * n] = acc[m][n];
                g_X1[p][ty + 16 * m][tx + 16 * n] = acc[m][n];
            }
    }
    // X2 = W11 @ L_old (GEMM)
    {
        float acc[8][8];
#pragma unroll
        for (int m = 0; m < 8; m++)
#pragma unroll
            for (int n = 0; n < 8; n++) acc[m][n] = 0.0f;
        for (int kc = 0; kc < Mm; kc += 16) {
            for (int e = t; e < 2048; e += 256) {
                int kk = e >> 7, c = e & 127;
                stg[kk * 128 + c] = L_old[(o * Mm + kc + kk) * Mm + c];
            }
            __syncthreads();
#pragma unroll
            for (int kk = 0; kk < 16; kk++) {
                float a[8], b[8];
#pragma unroll
                for (int m = 0; m < 8; m++) a[m] = Ls[(ty + 16 * m) * LDA + kc + kk];
#pragma unroll
                for (int n = 0; n < 8; n++) b[n] = stg[kk * 128 + tx + 16 * n];
#pragma unroll
                for (int m = 0; m < 8; m++)
#pragma unroll
                    for (int n = 0; n < 8; n++) acc[m][n] += a[m] * b[n];
            }
            __syncthreads();
        }
#pragma unroll
        for (int m = 0; m < 8; m++)
#pragma unroll
            for (int n = 0; n < 8; n++) X2[(ty + 16 * m) * LDA + tx + 16 * n] = acc[m][n];
    }
    __syncthreads();

    // yv = W11 @ m_old (parallel rows)
    if (t < 128) mbuf[t] = m_old[o * Mm + t];
    __syncthreads();
    if (t < 128) {
        float s = 0.0f;
        for (int k = 0; k <= t; k++) s += Ls[t * LDA + k] * mbuf[k];
        yv[t] = s;
        g_vm[p][t] = s;
    }
    __syncthreads();

    // m_joint
    if (t < 128) {
        float s = 0.0f;
        for (int i = 0; i < Mm; i++) s += X1[i * LDA + t] * yv[i];
        g_mj[p][t] = mbuf[t];
        g_mj[p][Mm + t] = s + u_mean[o * Mm + t];
    }
    __syncthreads();

    // AtX[j][k] = sum_i X2[i][j]*X1[i][k] -> overwrite Ls
    {
        float c[8][8];
#pragma unroll
        for (int m = 0; m < 8; m++)
#pragma unroll
            for (int n = 0; n < 8; n++) c[m][n] = 0.0f;
        for (int i = 0; i < Mm; i++) {
            float a[8], b[8];
#pragma unroll
            for (int m = 0; m < 8; m++) a[m] = X2[i * LDA + ty + 16 * m];
#pragma unroll
            for (int n = 0; n < 8; n++) b[n] = X1[i * LDA + tx + 16 * n];
#pragma unroll
            for (int m = 0; m < 8; m++)
#pragma unroll
                for (int n = 0; n < 8; n++) c[m][n] += a[m] * b[n];
        }
        __syncthreads();
#pragma unroll
        for (int m = 0; m < 8; m++)
#pragma unroll
            for (int n = 0; n < 8; n++) Ls[(ty + 16 * m) * LDA + tx + 16 * n] = c[m][n];
    }

    // schur = kuu_new + jit I - X1^T X1
    {
        float c[8][8];
#pragma unroll
        for (int m = 0; m < 8; m++)
#pragma unroll
            for (int n = 0; n < 8; n++) c[m][n] = 0.0f;
        for (int k = 0; k < Mm; k++) {
            float a[8], b[8];
#pragma unroll
            for (int m = 0; m < 8; m++) a[m] = X1[k * LDA + ty + 16 * m];
#pragma unroll
            for (int n = 0; n < 8; n++) b[n] = X1[k * LDA + tx + 16 * n];
#pragma unroll
            for (int m = 0; m < 8; m++)
#pragma unroll
                for (int n = 0; n < 8; n++) c[m][n] += a[m] * b[n];
        }
#pragma unroll
        for (int m = 0; m < 8; m++)
#pragma unroll
            for (int n = 0; n < 8; n++) {
                int i = ty + 16 * m, j = tx + 16 * n;
                float v = g_kuu2[p][Mm + i][Mm + j] - c[m][n];
                if (i == j) v += JIT;
                g_schur[p][i][j] = v;
            }
    }
    __syncthreads();

    // reload: X1 <- L_old, X2 <- dense(u_tril)
    for (int e = t; e < Mm * Mm; e += 256) {
        int i = e >> 7, j = e & 127;
        X1[i * LDA + j] = L_old[(o * Mm + i) * Mm + j];
        X2[i * LDA + j] = (j <= i) ? u_tril_vec[o * 8256 + (i * (i + 1)) / 2 + j] : 0.0f;
    }
    __syncthreads();

    // cov TL
    {
        float c[8][8];
#pragma unroll
        for (int m = 0; m < 8; m++)
#pragma unroll
            for (int n = 0; n < 8; n++) c[m][n] = 0.0f;
        for (int k = 0; k < Mm; k++) {
            float a[8], b[8];
#pragma unroll
            for (int m = 0; m < 8; m++) a[m] = X1[(ty + 16 * m) * LDA + k];
#pragma unroll
            for (int n = 0; n < 8; n++) b[n] = X1[(tx + 16 * n) * LDA + k];
#pragma unroll
            for (int m = 0; m < 8; m++)
#pragma unroll
                for (int n = 0; n < 8; n++) c[m][n] += a[m] * b[n];
        }
#pragma unroll
        for (int m = 0; m < 8; m++)
#pragma unroll
            for (int n = 0; n < 8; n++) g_cov[p][ty + 16 * m][tx + 16 * n] = c[m][n];
    }
    // cov BL[Mm+j][i] = sum_k L_old[i][k] AtX[k][j]
    {
        float c[8][8];
#pragma unroll
        for (int m = 0; m < 8; m++)
#pragma unroll
            for (int n = 0; n < 8; n++) c[m][n] = 0.0f;
        for (int k = 0; k < Mm; k++) {
            float a[8], b[8];
#pragma unroll
            for (int m = 0; m < 8; m++) a[m] = Ls[k * LDA + ty + 16 * m];
#pragma unroll
            for (int n = 0; n < 8; n++) b[n] = X1[(tx + 16 * n) * LDA + k];
#pragma unroll
            for (int m = 0; m < 8; m++)
#pragma unroll
                for (int n = 0; n < 8; n++) c[m][n] += a[m] * b[n];
        }
#pragma unroll
        for (int m = 0; m < 8; m++)
#pragma unroll
            for (int n = 0; n < 8; n++) g_cov[p][Mm + ty + 16 * m][tx + 16 * n] = c[m][n];
    }
    // cov BR
    {
        float c[8][8];
#pragma unroll
        for (int m = 0; m < 8; m++)
#pragma unroll
            for (int n = 0; n < 8; n++) c[m][n] = 0.0f;
        for (int k = 0; k < Mm; k++) {
            float a[8], b[8];
#pragma unroll
            for (int m = 0; m < 8; m++) a[m] = X2[(ty + 16 * m) * LDA + k];
#pragma unroll
            for (int n = 0; n < 8; n++) b[n] = X2[(tx + 16 * n) * LDA + k];
#pragma unroll
            for (int m = 0; m < 8; m++)
#pragma unroll
                for (int n = 0; n < 8; n++) c[m][n] += a[m] * b[n];
        }
        for (int k = 0; k < Mm; k++) {
            float a[8], b[8];
#pragma unroll
            for (int m = 0; m < 8; m++) a[m] = Ls[k * LDA + ty + 16 * m];
#pragma unroll
            for (int n = 0; n < 8; n++) b[n] = Ls[k * LDA + tx + 16 * n];
#pragma unroll
            for (int m = 0; m < 8; m++)
#pragma unroll
                for (int n = 0; n < 8; n++) c[m][n] += a[m] * b[n];
        }
#pragma unroll
        for (int m = 0; m < 8; m++)
#pragma unroll
            for (int n = 0; n < 8; n++) g_cov[p][Mm + ty + 16 * m][Mm + tx + 16 * n] = c[m][n];
    }
}

// ---------------- B1f: chol(schur)+trtri -> W22; W21; Wt TR/BR; vm2 (fused) ----------------
// dyn smem: S 16512 | T1 16512 | stgA 2048 | stgB 2048 | dinv 128 | mjs 256 = 37504 fl = 150016 B
__global__ __launch_bounds__(256, 1) void k_stageB1f() {
    extern __shared__ float sm[];
    float* S    = sm;
    float* T1   = sm + 16512;
    float* stgA = sm + 33024;
    float* stgB = sm + 35072;
    float* dinv = sm + 37120;
    float* mjs  = sm + 37248;
    int p = blockIdx.x, t = threadIdx.x;
    int tx = t & 15, ty = t >> 4;

    for (int e = t; e < Mm * Mm; e += 256) {
        int i = e >> 7, j = e & 127;
        S[i * LDA + j] = g_schur[p][i][j];
    }
    if (t < 256) { mjs[t] = g_mj[p][t]; }
    __syncthreads();
    chol128(S, dinv, t);
    trtri128_blocked(S, dinv, t);   // S = W22 dense (upper zeros)

    // persist Wt BR
    for (int e = t; e < Mm * Mm; e += 256) {
        int k = e >> 7, i = e & 127;
        g_Wt[p][Mm + k][Mm + i] = S[i * LDA + k];
    }

    // phase1: T1[c][j] = sum_i X1[i][c] * W11[i][j]
    {
        float acc[8][8];
#pragma unroll
        for (int m = 0; m < 8; m++)
#pragma unroll
            for (int n = 0; n < 8; n++) acc[m][n] = 0.0f;
        for (int kc = 0; kc < Mm; kc += 16) {
            for (int e = t; e < 2048; e += 256) {
                int kk = e >> 7, q = e & 127;
                stgA[kk * 128 + q] = g_X1[p][kc + kk][q];
                stgB[kk * 128 + q] = g_W11[p][kc + kk][q];
            }
            __syncthreads();
#pragma unroll
            for (int kk = 0; kk < 16; kk++) {
                float a[8], b[8];
#pragma unroll
                for (int m = 0; m < 8; m++) a[m] = stgA[kk * 128 + ty + 16 * m];
#pragma unroll
                for (int n = 0; n < 8; n++) b[n] = stgB[kk * 128 + tx + 16 * n];
#pragma unroll
                for (int m = 0; m < 8; m++)
#pragma unroll
                    for (int n = 0; n < 8; n++) acc[m][n] += a[m] * b[n];
            }
            __syncthreads();
        }
#pragma unroll
        for (int m = 0; m < 8; m++)
#pragma unroll
            for (int n = 0; n < 8; n++) T1[(ty + 16 * m) * LDA + tx + 16 * n] = acc[m][n];
    }
    __syncthreads();

    // phase2: W21[r][j] = -sum_c W22[r][c] * T1[c][j]
    {
        float acc[8][8];
#pragma unroll
        for (int m = 0; m < 8; m++)
#pragma unroll
            for (int n = 0; n < 8; n++) acc[m][n] = 0.0f;
        for (int c = 0; c < Mm; c++) {
            float a[8], b[8];
#pragma unroll
            for (int m = 0; m < 8; m++) a[m] = S[(ty + 16 * m) * LDA + c];
#pragma unroll
            for (int n = 0; n < 8; n++) b[n] = T1[c * LDA + tx + 16 * n];
#pragma unroll
            for (int m = 0; m < 8; m++)
#pragma unroll
                for (int n = 0; n < 8; n++) acc[m][n] -= a[m] * b[n];
        }
        __syncthreads();
        // write W21: Wt TR (transposed) + T1 (row-major, for vm2)
#pragma unroll
        for (int m = 0; m < 8; m++)
#pragma unroll
            for (int n = 0; n < 8; n++) {
                int r = ty + 16 * m, j = tx + 16 * n;
                g_Wt[p][j][Mm + r] = acc[m][n];
                T1[r * LDA + j] = acc[m][n];
            }
    }
    __syncthreads();

    // vm2[r] = W21[r]·mj[0:128] + W22[r]·mj[128:256]
    if (t < 128) {
        float s = 0.0f;
        for (int j = 0; j < Mm; j++) s += T1[t * LDA + j] * mjs[j];
        for (int j = 0; j < Mm; j++) s += S[t * LDA + j] * mjs[Mm + j];
        g_vm[p][Mm + t] = s;
    }
}

// ---------------- B2n: block chol of cov+jit -> L11p, L21p, L22p ----------------
__global__ __launch_bounds__(256, 1) void k_stageB2n() {
    extern __shared__ float sm[];
    float* C = sm;
    float* X = sm + 16512;
    float* dinv = sm + 33024;
    int p = blockIdx.x, t = threadIdx.x;
    int tx = t & 15, ty = t >> 4;

    for (int e = t; e < Mm * Mm; e += 256) {
        int i = e >> 7, j = e & 127;
        float v = g_cov[p][i][j];
        if (i == j) v += JIT;
        C[i * LDA + j] = v;
    }
    __syncthreads();
    chol128(C, dinv, t);
    for (int e = t; e < Mm * Mm; e += 256) {
        int i = e >> 7, k = e & 127;
        g_L11p[p][i][k] = (k <= i) ? C[i * LDA + k] : 0.0f;
    }
    for (int e = t; e < Mm * Mm; e += 256) {
        int r = e >> 7, j = e & 127;
        X[r * LDA + j] = g_cov[p][Mm + r][j];
    }
    __syncthreads();
    if (t < 128) {
        int r = t;
        for (int j = 0; j < Mm; j++) {
            float s0 = 0, s1 = 0, s2 = 0, s3 = 0;
            int k = 0;
            for (; k + 3 < j; k += 4) {
                s0 += X[r * LDA + k]     * C[j * LDA + k];
                s1 += X[r * LDA + k + 1] * C[j * LDA + k + 1];
                s2 += X[r * LDA + k + 2] * C[j * LDA + k + 2];
                s3 += X[r * LDA + k + 3] * C[j * LDA + k + 3];
            }
            for (; k < j; k++) s0 += X[r * LDA + k] * C[j * LDA + k];
            X[r * LDA + j] = (X[r * LDA + j] - ((s0 + s1) + (s2 + s3))) * dinv[j];
        }
    }
    __syncthreads();
    for (int e = t; e < Mm * Mm; e += 256) {
        int r = e >> 7, j = e & 127;
        g_L21p[p][r][j] = X[r * LDA + j];
    }
    {
        float c[8][8];
#pragma unroll
        for (int m = 0; m < 8; m++)
#pragma unroll
            for (int n = 0; n < 8; n++) c[m][n] = 0.0f;
        for (int k = 0; k < Mm; k++) {
            float a[8], b[8];
#pragma unroll
            for (int m = 0; m < 8; m++) a[m] = X[(ty + 16 * m) * LDA + k];
#pragma unroll
            for (int n = 0; n < 8; n++) b[n] = X[(tx + 16 * n) * LDA + k];
#pragma unroll
            for (int m = 0; m < 8; m++)
#pragma unroll
                for (int n = 0; n < 8; n++) c[m][n] += a[m] * b[n];
        }
        __syncthreads();
#pragma unroll
        for (int m = 0; m < 8; m++)
#pragma unroll
            for (int n = 0; n < 8; n++) {
                int i = ty + 16 * m, j = tx + 16 * n;
                float v = g_cov[p][Mm + i][Mm + j] - c[m][n];
                if (i == j) v += JIT;
                C[i * LDA + j] = v;
            }
    }
    __syncthreads();
    chol128(C, dinv, t);
    for (int e = t; e < Mm * Mm; e += 256) {
        int i = e >> 7, k = e & 127;
        g_L22p[p][i][k] = (k <= i) ? C[i * LDA + k] : 0.0f;
    }
}

// ---------------- k_R: R blocks. grid (3, HO) ----------------
__global__ __launch_bounds__(256) void k_R() {
    __shared__ float As[16][128];
    __shared__ float Bs[16][128];
    int v = blockIdx.x, p = blockIdx.y;
    int t = threadIdx.x, tx = t & 15, ty = t >> 4;
    float acc[8][8];
#pragma unroll
    for (int m = 0; m < 8; m++)
#pragma unroll
        for (int n = 0; n < 8; n++) acc[m][n] = 0.0f;

    int kTot = (v == 1) ? M2 : Mm;
    for (int kc = 0; kc < kTot; kc += 16) {
        for (int e = t; e < 2048; e += 256) {
            int kk = e >> 7, q = e & 127;
            int kg = kc + kk;
            float av, bv;
            if (v == 0) { av = g_Wt[p][kg][q];            bv = g_L11p[p][kg][q]; }
            else if (v == 1) {
                av = g_Wt[p][kg][Mm + q];
                bv = (kg < Mm) ? g_L11p[p][kg][q] : g_L21p[p][kg - Mm][q];
            }
            else { av = g_Wt[p][Mm + kg][Mm + q];         bv = g_L22p[p][kg][q]; }
            As[kk][q] = av;
            Bs[kk][q] = bv;
        }
        __syncthreads();
#pragma unroll
        for (int kk = 0; kk < 16; kk++) {
            float4 a0 = *(const float4*)&As[kk][ty * 8];
            float4 a1 = *(const float4*)&As[kk][ty * 8 + 4];
            float4 b0 = *(const float4*)&Bs[kk][tx * 8];
            float4 b1 = *(const float4*)&Bs[kk][tx * 8 + 4];
            float am[8] = { a0.x, a0.y, a0.z, a0.w, a1.x, a1.y, a1.z, a1.w };
            float bn[8] = { b0.x, b0.y, b0.z, b0.w, b1.x, b1.y, b1.z, b1.w };
#pragma unroll
            for (int m = 0; m < 8; m++)
#pragma unroll
                for (int n = 0; n < 8; n++) acc[m][n] += am[m] * bn[n];
        }
        __syncthreads();
    }
    int r0 = (v == 0) ? 0 : Mm;
    int c0 = (v == 2) ? Mm : 0;
#pragma unroll
    for (int m = 0; m < 8; m++) {
        *(float4*)&g_R[p][r0 + ty * 8 + m][c0 + tx * 8]     = make_float4(acc[m][0], acc[m][1], acc[m][2], acc[m][3]);
        *(float4*)&g_R[p][r0 + ty * 8 + m][c0 + tx * 8 + 4] = make_float4(acc[m][4], acc[m][5], acc[m][6], acc[m][7]);
    }
}

// ---------------- gemmA: a = Linv @ kx (FFMA2) + d1/mu partials ----------------
__global__ __launch_bounds__(256) void k_gemmA() {
    __shared__ float As[16][128];
    __shared__ float Bs[16][128];
    __shared__ float vs[128];
    __shared__ float red[16][128];
    int p = blockIdx.z;
    int i0 = blockIdx.y * 128, b0 = blockIdx.x * 128;
    int t = threadIdx.x, tx = t % 16, ty = t / 16;
    if (t < 128) vs[t] = g_vm[p][i0 + t];
    unsigned long long acc[8][4];
#pragma unroll
    for (int m = 0; m < 8; m++)
#pragma unroll
        for (int n = 0; n < 4; n++) acc[m][n] = 0ULL;

    int kmax = i0 + 128;
    for (int kc = 0; kc < kmax; kc += 16) {
#pragma unroll
        for (int e = 0; e < 2; e++) {
            int q = t + e * 256;
            int kk = q >> 5, c4 = q & 31;
            *(float4*)&As[kk][c4 * 4] = *(const float4*)&g_Wt[p][kc + kk][i0 + c4 * 4];
            *(float4*)&Bs[kk][c4 * 4] = *(const float4*)&g_kx[p][kc + kk][b0 + c4 * 4];
        }
        __syncthreads();
#pragma unroll
        for (int kk = 0; kk < 16; kk++) {
            float4 a0 = *(const float4*)&As[kk][ty * 8];
            float4 a1 = *(const float4*)&As[kk][ty * 8 + 4];
            float4 q0 = *(const float4*)&Bs[kk][tx * 8];
            float4 q1 = *(const float4*)&Bs[kk][tx * 8 + 4];
            unsigned long long bp[4] = { pk2(q0.x, q0.y), pk2(q0.z, q0.w), pk2(q1.x, q1.y), pk2(q1.z, q1.w) };
            float am[8] = { a0.x, a0.y, a0.z, a0.w, a1.x, a1.y, a1.z, a1.w };
#pragma unroll
            for (int m = 0; m < 8; m++) {
                unsigned long long ad = pk2(am[m], am[m]);
#pragma unroll
                for (int n = 0; n < 4; n++) acc[m][n] = ffma2(ad, bp[n], acc[m][n]);
            }
        }
        __syncthreads();
    }
    float av[8][8];
#pragma unroll
    for (int m = 0; m < 8; m++) {
#pragma unroll
        for (int n = 0; n < 4; n++) {
            float2 v = upk2(acc[m][n]);
            av[m][n * 2] = v.x; av[m][n * 2 + 1] = v.y;
        }
        *(float4*)&g_a[p][i0 + ty * 8 + m][b0 + tx * 8]     = make_float4(av[m][0], av[m][1], av[m][2], av[m][3]);
        *(float4*)&g_a[p][i0 + ty * 8 + m][b0 + tx * 8 + 4] = make_float4(av[m][4], av[m][5], av[m][6], av[m][7]);
    }
#pragma unroll
    for (int n = 0; n < 8; n++) {
        float s = 0.0f;
#pragma unroll
        for (int m = 0; m < 8; m++) s += av[m][n] * av[m][n];
        red[ty][tx * 8 + n] = s;
    }
    __syncthreads();
    if (t < 128) {
        float s = 0.0f;
#pragma unroll
        for (int y = 0; y < 16; y++) s += red[y][t];
        g_d1p[blockIdx.y][p][b0 + t] = s;
    }
    __syncthreads();
#pragma unroll
    for (int n = 0; n < 8; n++) {
        float s = 0.0f;
#pragma unroll
        for (int m = 0; m < 8; m++) s += vs[ty * 8 + m] * av[m][n];
        red[ty][tx * 8 + n] = s;
    }
    __syncthreads();
    if (t < 128) {
        float s = 0.0f;
#pragma unroll
        for (int y = 0; y < 16; y++) s += red[y][t];
        g_mup[blockIdx.y][p][b0 + t] = s;
    }
}

// ---------------- gemmH: h = R^T @ a, d2 partials (FFMA2) ----------------
__global__ __launch_bounds__(256) void k_gemmH() {
    __shared__ float As[16][128];
    __shared__ float Bs[16][128];
    __shared__ float red[16][128];
    int p = blockIdx.z;
    int j0 = blockIdx.y * 128, b0 = blockIdx.x * 128;
    int t = threadIdx.x, tx = t % 16, ty = t / 16;
    unsigned long long acc[8][4];
#pragma unroll
    for (int m = 0; m < 8; m++)
#pragma unroll
        for (int n = 0; n < 4; n++) acc[m][n] = 0ULL;

    for (int kc = j0; kc < M2; kc += 16) {
#pragma unroll
        for (int e = 0; e < 2; e++) {
            int q = t + e * 256;
            int kk = q >> 5, c4 = q & 31;
            *(float4*)&As[kk][c4 * 4] = *(const float4*)&g_R[p][kc + kk][j0 + c4 * 4];
            *(float4*)&Bs[kk][c4 * 4] = *(const float4*)&g_a[p][kc + kk][b0 + c4 * 4];
        }
        __syncthreads();
#pragma unroll
        for (int kk = 0; kk < 16; kk++) {
            float4 a0 = *(const float4*)&As[kk][ty * 8];
            float4 a1 = *(const float4*)&As[kk][ty * 8 + 4];
            float4 q0 = *(const float4*)&Bs[kk][tx * 8];
            float4 q1 = *(const float4*)&Bs[kk][tx * 8 + 4];
            unsigned long long bp[4] = { pk2(q0.x, q0.y), pk2(q0.z, q0.w), pk2(q1.x, q1.y), pk2(q1.z, q1.w) };
            float am[8] = { a0.x, a0.y, a0.z, a0.w, a1.x, a1.y, a1.z, a1.w };
#pragma unroll
            for (int m = 0; m < 8; m++) {
                unsigned long long ad = pk2(am[m], am[m]);
#pragma unroll
                for (int n = 0; n < 4; n++) acc[m][n] = ffma2(ad, bp[n], acc[m][n]);
            }
        }
        __syncthreads();
    }
#pragma unroll
    for (int n = 0; n < 8; n++) {
        float s = 0.0f;
#pragma unroll
        for (int m = 0; m < 8; m++) {
            float2 v = upk2(acc[m][n / 2]);
            float h = (n & 1) ? v.y : v.x;
            s += h * h;
        }
        red[ty][tx * 8 + n] = s;
    }
    __syncthreads();
    if (t < 128) {
        float s = 0.0f;
#pragma unroll
        for (int y = 0; y < 16; y++) s += red[y][t];
        g_d2p[blockIdx.y][p][b0 + t] = s;
    }
}

// ---------------- final ----------------
__global__ void k_final(float* __restrict__ out) {
    int idx = blockIdx.x * 256 + threadIdx.x;
    if (idx >= HOB) return;
    int p = idx / Bb, b = idx % Bb;
    out[idx] = g_mup[0][p][b] + g_mup[1][p][b];
    out[HOB + idx] = g_sf2[p / Oo] - (g_d1p[0][p][b] + g_d1p[1][p][b]) + (g_d2p[0][p][b] + g_d2p[1][p][b]);
}

extern "C" void kernel_launch(void* const* d_in, const int* in_sizes, int n_in,
                              void* d_out, int out_size) {
    const float* x          = (const float*)d_in[0];
    const float* z          = (const float*)d_in[1];
    const float* u_mean     = (const float*)d_in[2];
    const float* u_tril_vec = (const float*)d_in[3];
    const float* m_old      = (const float*)d_in[4];
    const float* L_old      = (const float*)d_in[5];
    const float* z_old      = (const float*)d_in[6];
    const float* theta      = (const float*)d_in[7];
    float* out = (float*)d_out;

    cudaFuncSetAttribute(k_stageA,   cudaFuncAttributeMaxDynamicSharedMemorySize, 207872);
    cudaFuncSetAttribute(k_stageB1f, cudaFuncAttributeMaxDynamicSharedMemorySize, 150016);
    cudaFuncSetAttribute(k_stageB2n, cudaFuncAttributeMaxDynamicSharedMemorySize, 132608);

    k_prep_theta<<<1, 128>>>(theta);                                   // 0
    k_prep_z<<<HO, 256>>>(z, z_old);                                   // 1
    k_kuu2<<<dim3(16, HO), 256>>>();                                   // 2
    k_stageA<<<HO, 256, 207872>>>(m_old, L_old, u_mean, u_tril_vec);   // 3 (profiled)
    k_stageB1f<<<HO, 256, 150016>>>();                                 // 4
    k_stageB2n<<<HO, 256, 132608>>>();                                 // 5
    k_R<<<dim3(3, HO), 256>>>();                                       // 6
    k_prep_x<<<16, 256>>>(x);                                          // 7
    k_kx<<<dim3(8, HO), 256>>>();                                      // 8
    k_gemmA<<<dim3(8, 2, HO), 256>>>();                                // 9
    k_gemmH<<<dim3(8, 2, HO), 256>>>();                                // 10
    k_final<<<512, 256>>>(out);                                        // 11
}

// round 8
// speedup vs baseline: 2.1601x; 1.0280x over previous
#include <cuda_runtime.h>

#define Hh 4
#define Oo 32
#define Mm 128
#define M2 256
#define Dd 16
#define Bb 1024
#define HO 128
#define HOB (HO*Bb)
#define JIT 1e-4f
#define LDA 129

// ---------------- f32x2 helpers ----------------
__device__ __forceinline__ unsigned long long pk2(float lo, float hi) {
    unsigned long long r;
    asm("mov.b64 %0, {%1, %2};" : "=l"(r) : "f"(lo), "f"(hi));
    return r;
}
__device__ __forceinline__ float2 upk2(unsigned long long v) {
    float2 r;
    asm("mov.b64 {%0, %1}, %2;" : "=f"(r.x), "=f"(r.y) : "l"(v));
    return r;
}
__device__ __forceinline__ unsigned long long ffma2(unsigned long long a, unsigned long long b, unsigned long long c) {
    unsigned long long d;
    asm("fma.rn.f32x2 %0, %1, %2, %3;" : "=l"(d) : "l"(a), "l"(b), "l"(c));
    return d;
}

// ---------------- device scratch ----------------
__device__ float g_sf2[Hh];
__device__ float g_invls[Hh][Dd];
__device__ float g_Xs[Hh][Bb][Dd];
__device__ float g_xn[Hh][Bb];
__device__ float g_Zs[HO][M2][Dd];
__device__ float g_zn[HO][M2];
__device__ float g_kuu2[HO][M2][M2];
__device__ float g_cov[HO][M2][M2];
__device__ float g_Wt[HO][M2][M2];     // Wt[k][i] = Linv256[i][k]
__device__ float g_R[HO][M2][M2];
__device__ float g_vm[HO][M2];
__device__ float g_mj[HO][M2];
__device__ float g_kx[HO][M2][Bb];
__device__ float g_a[HO][M2][Bb];
__device__ float g_X1[HO][Mm][Mm];
__device__ float g_W11[HO][Mm][Mm];
__device__ float g_schur[HO][Mm][Mm];
__device__ float g_L11p[HO][Mm][Mm];
__device__ float g_L21p[HO][Mm][Mm];
__device__ float g_L22p[HO][Mm][Mm];
__device__ float g_d1p[2][HO][Bb];
__device__ float g_d2p[2][HO][Bb];
__device__ float g_mup[2][HO][Bb];

// ---------------- serial building blocks (dense 128, LD=129, blockDim-agnostic) ----------------
__device__ void chol128(float* Ls, float* dinv, int t) {
    for (int j = 0; j < Mm; j++) {
        if (t < 32) {
            float s = 0.0f;
            for (int k = t; k < j; k += 32) { float v = Ls[j * LDA + k]; s += v * v; }
            for (int w = 16; w; w >>= 1) s += __shfl_down_sync(0xffffffffu, s, w);
            if (t == 0) {
                float d = sqrtf(Ls[j * LDA + j] - s);
                Ls[j * LDA + j] = d;
                dinv[j] = 1.0f / d;
            }
        }
        __syncthreads();
        int i = j + 1 + t;
        if (i < Mm) {
            float s0 = 0, s1 = 0, s2 = 0, s3 = 0;
            int k = 0;
            for (; k + 3 < j; k += 4) {
                s0 += Ls[i * LDA + k]     * Ls[j * LDA + k];
                s1 += Ls[i * LDA + k + 1] * Ls[j * LDA + k + 1];
                s2 += Ls[i * LDA + k + 2] * Ls[j * LDA + k + 2];
                s3 += Ls[i * LDA + k + 3] * Ls[j * LDA + k + 3];
            }
            for (; k < j; k++) s0 += Ls[i * LDA + k] * Ls[j * LDA + k];
            Ls[i * LDA + j] = (Ls[i * LDA + j] - ((s0 + s1) + (s2 + s3))) * dinv[j];
        }
        __syncthreads();
    }
}

// blocked in-place trtri of 128 lower-tri. On exit lower = Linv, upper = 0.
__device__ void trtri128_blocked(float* Ls, float* dinv, int t) {
    if (t == 0) Ls[0] = dinv[0];
    if (t == 1) Ls[64 * LDA + 64] = dinv[64];
    __syncthreads();
    for (int i = 1; i < 64; i++) {
        float v = 0.0f;
        bool actA = (t < i);
        int u = t - 128;
        bool actB = (u >= 0 && u < i);
        if (actA) {
            float s0 = 0, s1 = 0, s2 = 0, s3 = 0;
            int k = t;
            for (; k + 3 < i; k += 4) {
                s0 += Ls[i * LDA + k]     * Ls[(k)     * LDA + t];
                s1 += Ls[i * LDA + k + 1] * Ls[(k + 1) * LDA + t];
                s2 += Ls[i * LDA + k + 2] * Ls[(k + 2) * LDA + t];
                s3 += Ls[i * LDA + k + 3] * Ls[(k + 3) * LDA + t];
            }
            for (; k < i; k++) s0 += Ls[i * LDA + k] * Ls[k * LDA + t];
            v = -dinv[i] * ((s0 + s1) + (s2 + s3));
        } else if (actB) {
            const int O = 64 * LDA + 64;
            float s0 = 0, s1 = 0, s2 = 0, s3 = 0;
            int k = u;
            for (; k + 3 < i; k += 4) {
                s0 += Ls[O + i * LDA + k]     * Ls[O + (k)     * LDA + u];
                s1 += Ls[O + i * LDA + k + 1] * Ls[O + (k + 1) * LDA + u];
                s2 += Ls[O + i * LDA + k + 2] * Ls[O + (k + 2) * LDA + u];
                s3 += Ls[O + i * LDA + k + 3] * Ls[O + (k + 3) * LDA + u];
            }
            for (; k < i; k++) s0 += Ls[O + i * LDA + k] * Ls[O + k * LDA + u];
            v = -dinv[64 + i] * ((s0 + s1) + (s2 + s3));
        }
        __syncthreads();
        if (actA) Ls[i * LDA + t] = v;
        if (actB) Ls[(64 + i) * LDA + 64 + u] = v;
        if (t == 0) Ls[i * LDA + i] = dinv[i];
        if (t == 1) Ls[(64 + i) * LDA + 64 + i] = dinv[64 + i];
        __syncthreads();
    }
    for (int e = t; e < 64 * 64; e += blockDim.x) {
        int r = e >> 6, c = e & 63;
        if (c > r) { Ls[r * LDA + c] = 0.0f; Ls[(64 + r) * LDA + 64 + c] = 0.0f; }
        Ls[r * LDA + 64 + c] = 0.0f;
    }
    __syncthreads();
    // corner: B <- -Cinv @ (Borig @ Ainv)  (first 256 threads)
    int tx = t & 15, ty = (t >> 4) & 15;
    bool act = (t < 256);
    float T[4][4];
#pragma unroll
    for (int m = 0; m < 4; m++)
#pragma unroll
        for (int n = 0; n < 4; n++) T[m][n] = 0.0f;
    if (act) {
        for (int k = 0; k < 64; k++) {
            float a[4], b[4];
#pragma unroll
            for (int m = 0; m < 4; m++) a[m] = Ls[(64 + ty + 16 * m) * LDA + k];
#pragma unroll
            for (int n = 0; n < 4; n++) b[n] = Ls[k * LDA + tx + 16 * n];
#pragma unroll
            for (int m = 0; m < 4; m++)
#pragma unroll
                for (int n = 0; n < 4; n++) T[m][n] += a[m] * b[n];
        }
    }
    __syncthreads();
    if (act) {
#pragma unroll
        for (int m = 0; m < 4; m++)
#pragma unroll
            for (int n = 0; n < 4; n++) Ls[(64 + ty + 16 * m) * LDA + tx + 16 * n] = T[m][n];
    }
    __syncthreads();
#pragma unroll
    for (int m = 0; m < 4; m++)
#pragma unroll
        for (int n = 0; n < 4; n++) T[m][n] = 0.0f;
    if (act) {
        for (int k = 0; k < 64; k++) {
            float a[4], b[4];
#pragma unroll
            for (int m = 0; m < 4; m++) a[m] = Ls[(64 + ty + 16 * m) * LDA + 64 + k];
#pragma unroll
            for (int n = 0; n < 4; n++) b[n] = Ls[(64 + k) * LDA + tx + 16 * n];
#pragma unroll
            for (int m = 0; m < 4; m++)
#pragma unroll
                for (int n = 0; n < 4; n++) T[m][n] -= a[m] * b[n];
        }
    }
    __syncthreads();
    if (act) {
#pragma unroll
        for (int m = 0; m < 4; m++)
#pragma unroll
            for (int n = 0; n < 4; n++) Ls[(64 + ty + 16 * m) * LDA + tx + 16 * n] = T[m][n];
    }
    __syncthreads();
}

// ---------------- prep ----------------
__global__ void k_prep_theta(const float* __restrict__ theta) {
    int t = threadIdx.x;
    if (t < Hh * (Dd + 1)) {
        int h = t / (Dd + 1), c = t % (Dd + 1);
        float v = theta[t];
        if (c == 0) g_sf2[h] = expf(v);
        else        g_invls[h][c - 1] = expf(-v);
    }
}

__global__ void k_prep_x(const float* __restrict__ x) {
    int g = blockIdx.x * blockDim.x + threadIdx.x;
    if (g >= Hh * Bb) return;
    int h = g / Bb, b = g % Bb;
    float s = 0.0f;
#pragma unroll
    for (int d = 0; d < Dd; d++) {
        float v = x[b * Dd + d] * g_invls[h][d];
        g_Xs[h][b][d] = v;
        s += v * v;
    }
    g_xn[h][b] = s;
}

__global__ void k_prep_z(const float* __restrict__ z, const float* __restrict__ z_old) {
    int p = blockIdx.x;
    int h = p / Oo, o = p % Oo;
    int i = threadIdx.x;
    const float* src = (i < Mm) ? &z_old[(o * Mm + i) * Dd] : &z[(o * Mm + (i - Mm)) * Dd];
    float s = 0.0f;
#pragma unroll
    for (int d = 0; d < Dd; d++) {
        float v = src[d] * g_invls[h][d];
        g_Zs[p][i][d] = v;
        s += v * v;
    }
    g_zn[p][i] = s;
}

__global__ void k_kuu2() {
    __shared__ float zn[M2];
    int p = blockIdx.y, rc = blockIdx.x, t = threadIdx.x;
    float myz[Dd];
#pragma unroll
    for (int d = 0; d < Dd; d++) myz[d] = g_Zs[p][t][d];
    zn[t] = g_zn[p][t];
    __syncthreads();
    float sf2 = g_sf2[p / Oo];
#pragma unroll 2
    for (int e = 0; e < 16; e++) {
        int row = rc * 16 + e;
        float dot = 0.0f;
#pragma unroll
        for (int d = 0; d < Dd; d++) dot += g_Zs[p][row][d] * myz[d];
        float d2 = fmaxf(zn[row] + zn[t] - 2.0f * dot, 0.0f);
        g_kuu2[p][row][t] = sf2 * __expf(-0.5f * d2);
    }
}

__global__ void k_kx() {
    __shared__ float zs[M2][Dd + 1];
    __shared__ float zn[M2];
    int p = blockIdx.y, b0 = blockIdx.x * 128, t = threadIdx.x;
    int h = p / Oo;
    for (int e = t; e < M2 * Dd; e += 256) {
        int i = e >> 4, d = e & 15;
        zs[i][d] = g_Zs[p][i][d];
    }
    zn[t] = g_zn[p][t];
    __syncthreads();
    int bl = t & 127, half = t >> 7;
    float xr[Dd];
#pragma unroll
    for (int d = 0; d < Dd; d++) xr[d] = g_Xs[h][b0 + bl][d];
    float xnn = g_xn[h][b0 + bl];
    float sf2 = g_sf2[h];
    for (int ii = 0; ii < 128; ii++) {
        int i = half * 128 + ii;
        float dot = 0.0f;
#pragma unroll
        for (int d = 0; d < Dd; d++) dot += zs[i][d] * xr[d];
        float d2 = fmaxf(zn[i] + xnn - 2.0f * dot, 0.0f);
        g_kx[p][i][b0 + bl] = sf2 * __expf(-0.5f * d2);
    }
}

// ---------------- stage A (512 threads) ----------------
// dyn smem: Ls 16512 | X1 16512 | X2 16512 | stg 2048 | dinv 128 | yv 128 | mbuf 128 = 51968 fl = 207872 B
__global__ __launch_bounds__(512, 1) void k_stageA(
        const float* __restrict__ m_old, const float* __restrict__ L_old,
        const float* __restrict__ u_mean, const float* __restrict__ u_tril_vec) {
    extern __shared__ float sm[];
    float* Ls   = sm;
    float* X1   = sm + 16512;
    float* X2   = sm + 33024;
    float* stg  = sm + 49536;
    float* dinv = sm + 51584;
    float* yv   = sm + 51712;
    float* mbuf = sm + 51840;
    int p = blockIdx.x, o = p % Oo, t = threadIdx.x;
    int tx = t & 15, ty = t >> 4;   // ty 0..31; microtile rows = ty + 32*m (m<4), cols = tx + 16*n (n<8)

    for (int e = t; e < Mm * Mm; e += 512) {
        int i = e >> 7, j = e & 127;
        float v = g_kuu2[p][i][j];
        if (i == j) v += JIT;
        Ls[i * LDA + j] = v;
    }
    __syncthreads();

    chol128(Ls, dinv, t);
    trtri128_blocked(Ls, dinv, t);   // Ls = W11 dense (upper zeros)

    for (int e = t; e < Mm * Mm; e += 512) {
        int i = e >> 7, k = e & 127;
        g_W11[p][i][k] = Ls[i * LDA + k];
        g_Wt[p][k][i]  = Ls[i * LDA + k];
    }

    // X1 = W11 @ kuf
    {
        float acc[4][8];
#pragma unroll
        for (int m = 0; m < 4; m++)
#pragma unroll
            for (int n = 0; n < 8; n++) acc[m][n] = 0.0f;
        for (int kc = 0; kc < Mm; kc += 16) {
            for (int e = t; e < 2048; e += 512) {
                int kk = e >> 7, c = e & 127;
                stg[kk * 128 + c] = g_kuu2[p][kc + kk][Mm + c];
            }
            __syncthreads();
#pragma unroll
            for (int kk = 0; kk < 16; kk++) {
                float a[4], b[8];
#pragma unroll
                for (int m = 0; m < 4; m++) a[m] = Ls[(ty + 32 * m) * LDA + kc + kk];
#pragma unroll
                for (int n = 0; n < 8; n++) b[n] = stg[kk * 128 + tx + 16 * n];
#pragma unroll
                for (int m = 0; m < 4; m++)
#pragma unroll
                    for (int n = 0; n < 8; n++) acc[m][n] += a[m] * b[n];
            }
            __syncthreads();
        }
#pragma unroll
        for (int m = 0; m < 4; m++)
#pragma unroll
            for (int n = 0; n < 8; n++) {
                X1[(ty + 32 * m) * LDA + tx + 16 * n] = acc[m][n];
                g_X1[p][ty + 32 * m][tx + 16 * n] = acc[m][n];
            }
    }
    // X2 = W11 @ L_old
    {
        float acc[4][8];
#pragma unroll
        for (int m = 0; m < 4; m++)
#pragma unroll
            for (int n = 0; n < 8; n++) acc[m][n] = 0.0f;
        for (int kc = 0; kc < Mm; kc += 16) {
            for (int e = t; e < 2048; e += 512) {
                int kk = e >> 7, c = e & 127;
                stg[kk * 128 + c] = L_old[(o * Mm + kc + kk) * Mm + c];
            }
            __syncthreads();
#pragma unroll
            for (int kk = 0; kk < 16; kk++) {
                float a[4], b[8];
#pragma unroll
                for (int m = 0; m < 4; m++) a[m] = Ls[(ty + 32 * m) * LDA + kc + kk];
#pragma unroll
                for (int n = 0; n < 8; n++) b[n] = stg[kk * 128 + tx + 16 * n];
#pragma unroll
                for (int m = 0; m < 4; m++)
#pragma unroll
                    for (int n = 0; n < 8; n++) acc[m][n] += a[m] * b[n];
            }
            __syncthreads();
        }
#pragma unroll
        for (int m = 0; m < 4; m++)
#pragma unroll
            for (int n = 0; n < 8; n++) X2[(ty + 32 * m) * LDA + tx + 16 * n] = acc[m][n];
    }
    __syncthreads();

    // yv = W11 @ m_old
    if (t < 128) mbuf[t] = m_old[o * Mm + t];
    __syncthreads();
    if (t < 128) {
        float s = 0.0f;
        for (int k = 0; k <= t; k++) s += Ls[t * LDA + k] * mbuf[k];
        yv[t] = s;
        g_vm[p][t] = s;
    }
    __syncthreads();

    // m_joint
    if (t < 128) {
        float s = 0.0f;
        for (int i = 0; i < Mm; i++) s += X1[i * LDA + t] * yv[i];
        g_mj[p][t] = mbuf[t];
        g_mj[p][Mm + t] = s + u_mean[o * Mm + t];
    }
    __syncthreads();

    // AtX[j][k] = sum_i X2[i][j]*X1[i][k] -> overwrite Ls
    {
        float c[4][8];
#pragma unroll
        for (int m = 0; m < 4; m++)
#pragma unroll
            for (int n = 0; n < 8; n++) c[m][n] = 0.0f;
        for (int i = 0; i < Mm; i++) {
            float a[4], b[8];
#pragma unroll
            for (int m = 0; m < 4; m++) a[m] = X2[i * LDA + ty + 32 * m];
#pragma unroll
            for (int n = 0; n < 8; n++) b[n] = X1[i * LDA + tx + 16 * n];
#pragma unroll
            for (int m = 0; m < 4; m++)
#pragma unroll
                for (int n = 0; n < 8; n++) c[m][n] += a[m] * b[n];
        }
        __syncthreads();
#pragma unroll
        for (int m = 0; m < 4; m++)
#pragma unroll
            for (int n = 0; n < 8; n++) Ls[(ty + 32 * m) * LDA + tx + 16 * n] = c[m][n];
    }

    // schur = kuu_new + jit I - X1^T X1
    {
        float c[4][8];
#pragma unroll
        for (int m = 0; m < 4; m++)
#pragma unroll
            for (int n = 0; n < 8; n++) c[m][n] = 0.0f;
        for (int k = 0; k < Mm; k++) {
            float a[4], b[8];
#pragma unroll
            for (int m = 0; m < 4; m++) a[m] = X1[k * LDA + ty + 32 * m];
#pragma unroll
            for (int n = 0; n < 8; n++) b[n] = X1[k * LDA + tx + 16 * n];
#pragma unroll
            for (int m = 0; m < 4; m++)
#pragma unroll
                for (int n = 0; n < 8; n++) c[m][n] += a[m] * b[n];
        }
#pragma unroll
        for (int m = 0; m < 4; m++)
#pragma unroll
            for (int n = 0; n < 8; n++) {
                int i = ty + 32 * m, j = tx + 16 * n;
                float v = g_kuu2[p][Mm + i][Mm + j] - c[m][n];
                if (i == j) v += JIT;
                g_schur[p][i][j] = v;
            }
    }
    __syncthreads();

    // reload: X1 <- L_old, X2 <- dense(u_tril)
    for (int e = t; e < Mm * Mm; e += 512) {
        int i = e >> 7, j = e & 127;
        X1[i * LDA + j] = L_old[(o * Mm + i) * Mm + j];
        X2[i * LDA + j] = (j <= i) ? u_tril_vec[o * 8256 + (i * (i + 1)) / 2 + j] : 0.0f;
    }
    __syncthreads();

    // cov TL
    {
        float c[4][8];
#pragma unroll
        for (int m = 0; m < 4; m++)
#pragma unroll
            for (int n = 0; n < 8; n++) c[m][n] = 0.0f;
        for (int k = 0; k < Mm; k++) {
            float a[4], b[8];
#pragma unroll
            for (int m = 0; m < 4; m++) a[m] = X1[(ty + 32 * m) * LDA + k];
#pragma unroll
            for (int n = 0; n < 8; n++) b[n] = X1[(tx + 16 * n) * LDA + k];
#pragma unroll
            for (int m = 0; m < 4; m++)
#pragma unroll
                for (int n = 0; n < 8; n++) c[m][n] += a[m] * b[n];
        }
#pragma unroll
        for (int m = 0; m < 4; m++)
#pragma unroll
            for (int n = 0; n < 8; n++) g_cov[p][ty + 32 * m][tx + 16 * n] = c[m][n];
    }
    // cov BL[Mm+j][i] = sum_k L_old[i][k] AtX[k][j]
    {
        float c[4][8];
#pragma unroll
        for (int m = 0; m < 4; m++)
#pragma unroll
            for (int n = 0; n < 8; n++) c[m][n] = 0.0f;
        for (int k = 0; k < Mm; k++) {
            float a[4], b[8];
#pragma unroll
            for (int m = 0; m < 4; m++) a[m] = Ls[k * LDA + ty + 32 * m];
#pragma unroll
            for (int n = 0; n < 8; n++) b[n] = X1[(tx + 16 * n) * LDA + k];
#pragma unroll
            for (int m = 0; m < 4; m++)
#pragma unroll
                for (int n = 0; n < 8; n++) c[m][n] += a[m] * b[n];
        }
#pragma unroll
        for (int m = 0; m < 4; m++)
#pragma unroll
            for (int n = 0; n < 8; n++) g_cov[p][Mm + ty + 32 * m][tx + 16 * n] = c[m][n];
    }
    // cov BR
    {
        float c[4][8];
#pragma unroll
        for (int m = 0; m < 4; m++)
#pragma unroll
            for (int n = 0; n < 8; n++) c[m][n] = 0.0f;
        for (int k = 0; k < Mm; k++) {
            float a[4], b[8];
#pragma unroll
            for (int m = 0; m < 4; m++) a[m] = X2[(ty + 32 * m) * LDA + k];
#pragma unroll
            for (int n = 0; n < 8; n++) b[n] = X2[(tx + 16 * n) * LDA + k];
#pragma unroll
            for (int m = 0; m < 4; m++)
#pragma unroll
                for (int n = 0; n < 8; n++) c[m][n] += a[m] * b[n];
        }
        for (int k = 0; k < Mm; k++) {
            float a[4], b[8];
#pragma unroll
            for (int m = 0; m < 4; m++) a[m] = Ls[k * LDA + ty + 32 * m];
#pragma unroll
            for (int n = 0; n < 8; n++) b[n] = Ls[k * LDA + tx + 16 * n];
#pragma unroll
            for (int m = 0; m < 4; m++)
#pragma unroll
                for (int n = 0; n < 8; n++) c[m][n] += a[m] * b[n];
        }
#pragma unroll
        for (int m = 0; m < 4; m++)
#pragma unroll
            for (int n = 0; n < 8; n++) g_cov[p][Mm + ty + 32 * m][Mm + tx + 16 * n] = c[m][n];
    }
}

// ---------------- B1f: chol(schur)+trtri -> W22; W21; Wt TR/BR; vm2 (fused) ----------------
// dyn smem: S 16512 | T1 16512 | stgA 2048 | stgB 2048 | dinv 128 | mjs 256 = 37504 fl = 150016 B
__global__ __launch_bounds__(256, 1) void k_stageB1f() {
    extern __shared__ float sm[];
    float* S    = sm;
    float* T1   = sm + 16512;
    float* stgA = sm + 33024;
    float* stgB = sm + 35072;
    float* dinv = sm + 37120;
    float* mjs  = sm + 37248;
    int p = blockIdx.x, t = threadIdx.x;
    int tx = t & 15, ty = t >> 4;

    for (int e = t; e < Mm * Mm; e += 256) {
        int i = e >> 7, j = e & 127;
        S[i * LDA + j] = g_schur[p][i][j];
    }
    mjs[t] = g_mj[p][t];
    __syncthreads();
    chol128(S, dinv, t);
    trtri128_blocked(S, dinv, t);   // S = W22 dense

    for (int e = t; e < Mm * Mm; e += 256) {
        int k = e >> 7, i = e & 127;
        g_Wt[p][Mm + k][Mm + i] = S[i * LDA + k];
    }

    // phase1: T1[c][j] = sum_i X1[i][c] * W11[i][j]
    {
        float acc[8][8];
#pragma unroll
        for (int m = 0; m < 8; m++)
#pragma unroll
            for (int n = 0; n < 8; n++) acc[m][n] = 0.0f;
        for (int kc = 0; kc < Mm; kc += 16) {
            for (int e = t; e < 2048; e += 256) {
                int kk = e >> 7, q = e & 127;
                stgA[kk * 128 + q] = g_X1[p][kc + kk][q];
                stgB[kk * 128 + q] = g_W11[p][kc + kk][q];
            }
            __syncthreads();
#pragma unroll
            for (int kk = 0; kk < 16; kk++) {
                float a[8], b[8];
#pragma unroll
                for (int m = 0; m < 8; m++) a[m] = stgA[kk * 128 + ty + 16 * m];
#pragma unroll
                for (int n = 0; n < 8; n++) b[n] = stgB[kk * 128 + tx + 16 * n];
#pragma unroll
                for (int m = 0; m < 8; m++)
#pragma unroll
                    for (int n = 0; n < 8; n++) acc[m][n] += a[m] * b[n];
            }
            __syncthreads();
        }
#pragma unroll
        for (int m = 0; m < 8; m++)
#pragma unroll
            for (int n = 0; n < 8; n++) T1[(ty + 16 * m) * LDA + tx + 16 * n] = acc[m][n];
    }
    __syncthreads();

    // phase2: W21[r][j] = -sum_c W22[r][c] * T1[c][j]
    {
        float acc[8][8];
#pragma unroll
        for (int m = 0; m < 8; m++)
#pragma unroll
            for (int n = 0; n < 8; n++) acc[m][n] = 0.0f;
        for (int c = 0; c < Mm; c++) {
            float a[8], b[8];
#pragma unroll
            for (int m = 0; m < 8; m++) a[m] = S[(ty + 16 * m) * LDA + c];
#pragma unroll
            for (int n = 0; n < 8; n++) b[n] = T1[c * LDA + tx + 16 * n];
#pragma unroll
            for (int m = 0; m < 8; m++)
#pragma unroll
                for (int n = 0; n < 8; n++) acc[m][n] -= a[m] * b[n];
        }
        __syncthreads();
#pragma unroll
        for (int m = 0; m < 8; m++)
#pragma unroll
            for (int n = 0; n < 8; n++) {
                int r = ty + 16 * m, j = tx + 16 * n;
                g_Wt[p][j][Mm + r] = acc[m][n];
                T1[r * LDA + j] = acc[m][n];
            }
    }
    __syncthreads();

    if (t < 128) {
        float s = 0.0f;
        for (int j = 0; j < Mm; j++) s += T1[t * LDA + j] * mjs[j];
        for (int j = 0; j < Mm; j++) s += S[t * LDA + j] * mjs[Mm + j];
        g_vm[p][Mm + t] = s;
    }
}

// ---------------- B2n: block chol of cov+jit -> L11p, L21p, L22p ----------------
__global__ __launch_bounds__(256, 1) void k_stageB2n() {
    extern __shared__ float sm[];
    float* C = sm;
    float* X = sm + 16512;
    float* dinv = sm + 33024;
    int p = blockIdx.x, t = threadIdx.x;
    int tx = t & 15, ty = t >> 4;

    for (int e = t; e < Mm * Mm; e += 256) {
        int i = e >> 7, j = e & 127;
        float v = g_cov[p][i][j];
        if (i == j) v += JIT;
        C[i * LDA + j] = v;
    }
    __syncthreads();
    chol128(C, dinv, t);
    for (int e = t; e < Mm * Mm; e += 256) {
        int i = e >> 7, k = e & 127;
        g_L11p[p][i][k] = (k <= i) ? C[i * LDA + k] : 0.0f;
    }
    for (int e = t; e < Mm * Mm; e += 256) {
        int r = e >> 7, j = e & 127;
        X[r * LDA + j] = g_cov[p][Mm + r][j];
    }
    __syncthreads();
    if (t < 128) {
        int r = t;
        for (int j = 0; j < Mm; j++) {
            float s0 = 0, s1 = 0, s2 = 0, s3 = 0;
            int k = 0;
            for (; k + 3 < j; k += 4) {
                s0 += X[r * LDA + k]     * C[j * LDA + k];
                s1 += X[r * LDA + k + 1] * C[j * LDA + k + 1];
                s2 += X[r * LDA + k + 2] * C[j * LDA + k + 2];
                s3 += X[r * LDA + k + 3] * C[j * LDA + k + 3];
            }
            for (; k < j; k++) s0 += X[r * LDA + k] * C[j * LDA + k];
            X[r * LDA + j] = (X[r * LDA + j] - ((s0 + s1) + (s2 + s3))) * dinv[j];
        }
    }
    __syncthreads();
    for (int e = t; e < Mm * Mm; e += 256) {
        int r = e >> 7, j = e & 127;
        g_L21p[p][r][j] = X[r * LDA + j];
    }
    {
        float c[8][8];
#pragma unroll
        for (int m = 0; m < 8; m++)
#pragma unroll
            for (int n = 0; n < 8; n++) c[m][n] = 0.0f;
        for (int k = 0; k < Mm; k++) {
            float a[8], b[8];
#pragma unroll
            for (int m = 0; m < 8; m++) a[m] = X[(ty + 16 * m) * LDA + k];
#pragma unroll
            for (int n = 0; n < 8; n++) b[n] = X[(tx + 16 * n) * LDA + k];
#pragma unroll
            for (int m = 0; m < 8; m++)
#pragma unroll
                for (int n = 0; n < 8; n++) c[m][n] += a[m] * b[n];
        }
        __syncthreads();
#pragma unroll
        for (int m = 0; m < 8; m++)
#pragma unroll
            for (int n = 0; n < 8; n++) {
                int i = ty + 16 * m, j = tx + 16 * n;
                float v = g_cov[p][Mm + i][Mm + j] - c[m][n];
                if (i == j) v += JIT;
                C[i * LDA + j] = v;
            }
    }
    __syncthreads();
    chol128(C, dinv, t);
    for (int e = t; e < Mm * Mm; e += 256) {
        int i = e >> 7, k = e & 127;
        g_L22p[p][i][k] = (k <= i) ? C[i * LDA + k] : 0.0f;
    }
}

// ---------------- k_R: R blocks. grid (3, HO) ----------------
__global__ __launch_bounds__(256) void k_R() {
    __shared__ float As[16][128];
    __shared__ float Bs[16][128];
    int v = blockIdx.x, p = blockIdx.y;
    int t = threadIdx.x, tx = t & 15, ty = t >> 4;
    float acc[8][8];
#pragma unroll
    for (int m = 0; m < 8; m++)
#pragma unroll
        for (int n = 0; n < 8; n++) acc[m][n] = 0.0f;

    int kTot = (v == 1) ? M2 : Mm;
    for (int kc = 0; kc < kTot; kc += 16) {
        for (int e = t; e < 2048; e += 256) {
            int kk = e >> 7, q = e & 127;
            int kg = kc + kk;
            float av, bv;
            if (v == 0) { av = g_Wt[p][kg][q];            bv = g_L11p[p][kg][q]; }
            else if (v == 1) {
                av = g_Wt[p][kg][Mm + q];
                bv = (kg < Mm) ? g_L11p[p][kg][q] : g_L21p[p][kg - Mm][q];
            }
            else { av = g_Wt[p][Mm + kg][Mm + q];         bv = g_L22p[p][kg][q]; }
            As[kk][q] = av;
            Bs[kk][q] = bv;
        }
        __syncthreads();
#pragma unroll
        for (int kk = 0; kk < 16; kk++) {
            float4 a0 = *(const float4*)&As[kk][ty * 8];
            float4 a1 = *(const float4*)&As[kk][ty * 8 + 4];
            float4 b0 = *(const float4*)&Bs[kk][tx * 8];
            float4 b1 = *(const float4*)&Bs[kk][tx * 8 + 4];
            float am[8] = { a0.x, a0.y, a0.z, a0.w, a1.x, a1.y, a1.z, a1.w };
            float bn[8] = { b0.x, b0.y, b0.z, b0.w, b1.x, b1.y, b1.z, b1.w };
#pragma unroll
            for (int m = 0; m < 8; m++)
#pragma unroll
                for (int n = 0; n < 8; n++) acc[m][n] += am[m] * bn[n];
        }
        __syncthreads();
    }
    int r0 = (v == 0) ? 0 : Mm;
    int c0 = (v == 2) ? Mm : 0;
#pragma unroll
    for (int m = 0; m < 8; m++) {
        *(float4*)&g_R[p][r0 + ty * 8 + m][c0 + tx * 8]     = make_float4(acc[m][0], acc[m][1], acc[m][2], acc[m][3]);
        *(float4*)&g_R[p][r0 + ty * 8 + m][c0 + tx * 8 + 4] = make_float4(acc[m][4], acc[m][5], acc[m][6], acc[m][7]);
    }
}

// ---------------- gemmA: a = Linv @ kx (FFMA2) + d1/mu partials ----------------
__global__ __launch_bounds__(256) void k_gemmA() {
    __shared__ float As[16][128];
    __shared__ float Bs[16][128];
    __shared__ float vs[128];
    __shared__ float red[16][128];
    int p = blockIdx.z;
    int i0 = blockIdx.y * 128, b0 = blockIdx.x * 128;
    int t = threadIdx.x, tx = t % 16, ty = t / 16;
    if (t < 128) vs[t] = g_vm[p][i0 + t];
    unsigned long long acc[8][4];
#pragma unroll
    for (int m = 0; m < 8; m++)
#pragma unroll
        for (int n = 0; n < 4; n++) acc[m][n] = 0ULL;

    int kmax = i0 + 128;
    for (int kc = 0; kc < kmax; kc += 16) {
#pragma unroll
        for (int e = 0; e < 2; e++) {
            int q = t + e * 256;
            int kk = q >> 5, c4 = q & 31;
            *(float4*)&As[kk][c4 * 4] = *(const float4*)&g_Wt[p][kc + kk][i0 + c4 * 4];
            *(float4*)&Bs[kk][c4 * 4] = *(const float4*)&g_kx[p][kc + kk][b0 + c4 * 4];
        }
        __syncthreads();
#pragma unroll
        for (int kk = 0; kk < 16; kk++) {
            float4 a0 = *(const float4*)&As[kk][ty * 8];
            float4 a1 = *(const float4*)&As[kk][ty * 8 + 4];
            float4 q0 = *(const float4*)&Bs[kk][tx * 8];
            float4 q1 = *(const float4*)&Bs[kk][tx * 8 + 4];
            unsigned long long bp[4] = { pk2(q0.x, q0.y), pk2(q0.z, q0.w), pk2(q1.x, q1.y), pk2(q1.z, q1.w) };
            float am[8] = { a0.x, a0.y, a0.z, a0.w, a1.x, a1.y, a1.z, a1.w };
#pragma unroll
            for (int m = 0; m < 8; m++) {
                unsigned long long ad = pk2(am[m], am[m]);
#pragma unroll
                for (int n = 0; n < 4; n++) acc[m][n] = ffma2(ad, bp[n], acc[m][n]);
            }
        }
        __syncthreads();
    }
    float av[8][8];
#pragma unroll
    for (int m = 0; m < 8; m++) {
#pragma unroll
        for (int n = 0; n < 4; n++) {
            float2 v = upk2(acc[m][n]);
            av[m][n * 2] = v.x; av[m][n * 2 + 1] = v.y;
        }
        *(float4*)&g_a[p][i0 + ty * 8 + m][b0 + tx * 8]     = make_float4(av[m][0], av[m][1], av[m][2], av[m][3]);
        *(float4*)&g_a[p][i0 + ty * 8 + m][b0 + tx * 8 + 4] = make_float4(av[m][4], av[m][5], av[m][6], av[m][7]);
    }
#pragma unroll
    for (int n = 0; n < 8; n++) {
        float s = 0.0f;
#pragma unroll
        for (int m = 0; m < 8; m++) s += av[m][n] * av[m][n];
        red[ty][tx * 8 + n] = s;
    }
    __syncthreads();
    if (t < 128) {
        float s = 0.0f;
#pragma unroll
        for (int y = 0; y < 16; y++) s += red[y][t];
        g_d1p[blockIdx.y][p][b0 + t] = s;
    }
    __syncthreads();
#pragma unroll
    for (int n = 0; n < 8; n++) {
        float s = 0.0f;
#pragma unroll
        for (int m = 0; m < 8; m++) s += vs[ty * 8 + m] * av[m][n];
        red[ty][tx * 8 + n] = s;
    }
    __syncthreads();
    if (t < 128) {
        float s = 0.0f;
#pragma unroll
        for (int y = 0; y < 16; y++) s += red[y][t];
        g_mup[blockIdx.y][p][b0 + t] = s;
    }
}

// ---------------- gemmH: h = R^T @ a, d2 partials (FFMA2) ----------------
__global__ __launch_bounds__(256) void k_gemmH() {
    __shared__ float As[16][128];
    __shared__ float Bs[16][128];
    __shared__ float red[16][128];
    int p = blockIdx.z;
    int j0 = blockIdx.y * 128, b0 = blockIdx.x * 128;
    int t = threadIdx.x, tx = t % 16, ty = t / 16;
    unsigned long long acc[8][4];
#pragma unroll
    for (int m = 0; m < 8; m++)
#pragma unroll
        for (int n = 0; n < 4; n++) acc[m][n] = 0ULL;

    for (int kc = j0; kc < M2; kc += 16) {
#pragma unroll
        for (int e = 0; e < 2; e++) {
            int q = t + e * 256;
            int kk = q >> 5, c4 = q & 31;
            *(float4*)&As[kk][c4 * 4] = *(const float4*)&g_R[p][kc + kk][j0 + c4 * 4];
            *(float4*)&Bs[kk][c4 * 4] = *(const float4*)&g_a[p][kc + kk][b0 + c4 * 4];
        }
        __syncthreads();
#pragma unroll
        for (int kk = 0; kk < 16; kk++) {
            float4 a0 = *(const float4*)&As[kk][ty * 8];
            float4 a1 = *(const float4*)&As[kk][ty * 8 + 4];
            float4 q0 = *(const float4*)&Bs[kk][tx * 8];
            float4 q1 = *(const float4*)&Bs[kk][tx * 8 + 4];
            unsigned long long bp[4] = { pk2(q0.x, q0.y), pk2(q0.z, q0.w), pk2(q1.x, q1.y), pk2(q1.z, q1.w) };
            float am[8] = { a0.x, a0.y, a0.z, a0.w, a1.x, a1.y, a1.z, a1.w };
#pragma unroll
            for (int m = 0; m < 8; m++) {
                unsigned long long ad = pk2(am[m], am[m]);
#pragma unroll
                for (int n = 0; n < 4; n++) acc[m][n] = ffma2(ad, bp[n], acc[m][n]);
            }
        }
        __syncthreads();
    }
#pragma unroll
    for (int n = 0; n < 8; n++) {
        float s = 0.0f;
#pragma unroll
        for (int m = 0; m < 8; m++) {
            float2 v = upk2(acc[m][n / 2]);
            float h = (n & 1) ? v.y : v.x;
            s += h * h;
        }
        red[ty][tx * 8 + n] = s;
    }
    __syncthreads();
    if (t < 128) {
        float s = 0.0f;
#pragma unroll
        for (int y = 0; y < 16; y++) s += red[y][t];
        g_d2p[blockIdx.y][p][b0 + t] = s;
    }
}

// ---------------- final ----------------
__global__ void k_final(float* __restrict__ out) {
    int idx = blockIdx.x * 256 + threadIdx.x;
    if (idx >= HOB) return;
    int p = idx / Bb, b = idx % Bb;
    out[idx] = g_mup[0][p][b] + g_mup[1][p][b];
    out[HOB + idx] = g_sf2[p / Oo] - (g_d1p[0][p][b] + g_d1p[1][p][b]) + (g_d2p[0][p][b] + g_d2p[1][p][b]);
}

extern "C" void kernel_launch(void* const* d_in, const int* in_sizes, int n_in,
                              void* d_out, int out_size) {
    const float* x          = (const float*)d_in[0];
    const float* z          = (const float*)d_in[1];
    const float* u_mean     = (const float*)d_in[2];
    const float* u_tril_vec = (const float*)d_in[3];
    const float* m_old      = (const float*)d_in[4];
    const float* L_old      = (const float*)d_in[5];
    const float* z_old      = (const float*)d_in[6];
    const float* theta      = (const float*)d_in[7];
    float* out = (float*)d_out;

    static cudaStream_t s1 = 0;
    static cudaEvent_t evFork = 0, evKx = 0, evA = 0, evB1 = 0, evR = 0;
    if (!s1) {
        cudaStreamCreateWithFlags(&s1, cudaStreamNonBlocking);
        cudaEventCreateWithFlags(&evFork, cudaEventDisableTiming);
        cudaEventCreateWithFlags(&evKx,   cudaEventDisableTiming);
        cudaEventCreateWithFlags(&evA,    cudaEventDisableTiming);
        cudaEventCreateWithFlags(&evB1,   cudaEventDisableTiming);
        cudaEventCreateWithFlags(&evR,    cudaEventDisableTiming);
        cudaFuncSetAttribute(k_stageA,   cudaFuncAttributeMaxDynamicSharedMemorySize, 207872);
        cudaFuncSetAttribute(k_stageB1f, cudaFuncAttributeMaxDynamicSharedMemorySize, 150016);
        cudaFuncSetAttribute(k_stageB2n, cudaFuncAttributeMaxDynamicSharedMemorySize, 132608);
    }

    // s0 chain (launches 0..3 keep stageA at profile slot 3)
    k_prep_theta<<<1, 128>>>(theta);
    k_prep_z<<<HO, 256>>>(z, z_old);
    cudaEventRecord(evFork, 0);
    k_kuu2<<<dim3(16, HO), 256>>>();
    k_stageA<<<HO, 512, 207872>>>(m_old, L_old, u_mean, u_tril_vec);
    cudaEventRecord(evA, 0);

    // s1: prep_x + kx overlap stageA; then B2n overlaps B1f
    cudaStreamWaitEvent(s1, evFork, 0);
    k_prep_x<<<16, 256, 0, s1>>>(x);
    k_kx<<<dim3(8, HO), 256, 0, s1>>>();
    cudaEventRecord(evKx, s1);
    cudaStreamWaitEvent(s1, evA, 0);
    k_stageB2n<<<HO, 256, 132608, s1>>>();

    // s0: B1f
    k_stageB1f<<<HO, 256, 150016>>>();
    cudaEventRecord(evB1, 0);

    // s1: k_R (needs B2n + B1f), overlaps gemmA
    cudaStreamWaitEvent(s1, evB1, 0);
    k_R<<<dim3(3, HO), 256, 0, s1>>>();
    cudaEventRecord(evR, s1);

    // s0: gemmA (needs B1f + kx), then gemmH (needs R + a), then final
    cudaStreamWaitEvent(0, evKx, 0);
    k_gemmA<<<dim3(8, 2, HO), 256>>>();
    cudaStreamWaitEvent(0, evR, 0);
    k_gemmH<<<dim3(8, 2, HO), 256>>>();
    k_final<<<512, 256>>>(out);
}